// round 6
// baseline (speedup 1.0000x reference)
#include <cuda_runtime.h>
#include <math.h>
#include <stdint.h>

typedef unsigned long long u64;

#define BB 16
#define DD 512
#define HW 484
#define LE 1452
#define LDQ 484
#define NSCALE 0.011048543456039806f
#define DHWF 247808.0f
#define IEPS 1e-5f
#define GRP 247808
#define QF4 15488   // GRP/4/4 : float4s per quarter

// ---- scratch layout (floats) ----
#define SZ_PE     ((size_t)HW*DD)
#define SZ_LABEL  ((size_t)BB*LE)
#define SZ_XE     ((size_t)BB*LE*DD)
#define SZ_PQ     ((size_t)BB*LE*128)
#define SZ_DX     ((size_t)96*LDQ*DD)
#define SZ_DPQ    ((size_t)96*LDQ*128)
#define SZ_DMASK  ((size_t)96*LDQ)
#define SZ_PROBS  ((size_t)96*LDQ*1456)
#define SZ_MEMLAB ((size_t)BB*LE*DD)
#define SZ_RSUM   ((size_t)96*LDQ)

#define OFF_PE    ((size_t)0)
#define OFF_LABEL (OFF_PE + SZ_PE)
#define OFF_XE    (OFF_LABEL + SZ_LABEL)
#define OFF_X1E   (OFF_XE + SZ_XE)
#define OFF_MEM   (OFF_X1E + SZ_XE)
#define OFF_PQ    (OFF_MEM + SZ_XE)
#define OFF_PKC   (OFF_PQ + SZ_PQ)
#define OFF_DX0   (OFF_PKC + SZ_PQ)
#define OFF_DX1   (OFF_DX0 + SZ_DX)
#define OFF_DX    (OFF_DX1 + SZ_DX)
#define OFF_DXPT3 (OFF_DX + SZ_DX)
#define OFF_DPQ   (OFF_DXPT3 + SZ_DX)
#define OFF_DMASK (OFF_DPQ + SZ_DPQ)
#define OFF_DSC   (OFF_DMASK + SZ_DMASK)
#define OFF_IPART (OFF_DSC + 96*4)
#define OFF_DPART (OFF_IPART + 96*4)
#define OFF_MEMLAB (OFF_DPART + 96*4*3)
#define OFF_RSUM  (OFF_MEMLAB + SZ_MEMLAB)
#define OFF_PROBS (OFF_RSUM + SZ_RSUM)
#define SCRATCH_TOTAL (OFF_PROBS + SZ_PROBS)

__device__ __align__(16) float g_scratch[SCRATCH_TOTAL];

// ---- f32x2 helpers ----
__device__ __forceinline__ u64 ffma2(u64 a, u64 b, u64 c) {
    u64 d;
    asm("fma.rn.f32x2 %0, %1, %2, %3;" : "=l"(d) : "l"(a), "l"(b), "l"(c));
    return d;
}
__device__ __forceinline__ u64 pack2(float lo, float hi) {
    u64 r;
    asm("mov.b64 %0, {%1, %2};" : "=l"(r) : "f"(lo), "f"(hi));
    return r;
}
__device__ __forceinline__ void unpack2(u64 v, float& lo, float& hi) {
    asm("mov.b64 {%0, %1}, %2;" : "=f"(lo), "=f"(hi) : "l"(v));
}

__device__ __forceinline__ void ld8(const float* p, bool valid, float* r) {
    if (valid) {
        float4 v0 = *(const float4*)p;
        float4 v1 = *(const float4*)(p + 4);
        r[0] = v0.x; r[1] = v0.y; r[2] = v0.z; r[3] = v0.w;
        r[4] = v1.x; r[5] = v1.y; r[6] = v1.z; r[7] = v1.w;
    } else {
#pragma unroll
        for (int j = 0; j < 8; j++) r[j] = 0.0f;
    }
}
__device__ __forceinline__ void ld4(const float* p, bool valid, float* r) {
    if (valid) {
        float4 v0 = *(const float4*)p;
        r[0] = v0.x; r[1] = v0.y; r[2] = v0.z; r[3] = v0.w;
    } else {
#pragma unroll
        for (int j = 0; j < 4; j++) r[j] = 0.0f;
    }
}

// ================= generic batched GEMM, 64x128 tile, 3 CTAs/SM ==========
// C[g] = f( A[g] @ op(B[gk]) );  op = B^T if TRANSB (B is [N][K]).
// EPI 0: alpha*acc (+Cin)
// EPI 1: bias(AUX) + row L2-normalize  (proj; N==128, G==1)
// EPI 2: exp(alpha*acc) for n<NVALID else 0  (logits; ldC = padded width)
// EPI 3: AUX[g*M+m]*acc + Cin          (value with row 1/sum scale)
template<int TRANSB, int EPI>
__global__ void __launch_bounds__(256, 3)
gemm_kernel(const float* __restrict__ A, const float* __restrict__ B,
            const float* __restrict__ Cin, float* __restrict__ C,
            const float* __restrict__ AUX,
            int M, int N, int Kloop, int KB,
            int ldA, int ldB, int ldC,
            size_t sA, size_t sB, size_t sC,
            int gkMod, float alpha, int addC, int NVALID) {
    __shared__ float As[2][16][68];
    __shared__ float Bs[2][16][132];
    int g = blockIdx.z;
    int gk = gkMod ? (g & 15) : g;
    const float* Ag = A + (size_t)g * sA;
    const float* Bg = B + (size_t)gk * sB;
    int mBase = blockIdx.y * 64, nBase = blockIdx.x * 128;
    int t = threadIdx.x;

    int am = t >> 2, ak = (t & 3) * 4;      // A: 64 rows x 16 k, ld4 each
    bool avalid = (mBase + am) < M;
    const float* aPtr = Ag + (size_t)(mBase + am) * ldA + ak;

    int bn = t >> 1, bk = (t & 1) * 8;       // TRANSB path
    int bk2 = t >> 4, bnq = (t & 15) * 8;    // NN path
    bool bnvalid = (nBase + bn) < N;
    const float* bPtrT = Bg + (size_t)(nBase + bn) * ldB + bk;
    const float* bPtrN = Bg + (size_t)bk2 * ldB + nBase + bnq;

    float ra[4], rb[8];
    ld4(aPtr, avalid, ra);
    if (TRANSB) ld8(bPtrT, bnvalid, rb);
    else        ld8(bPtrN, bk2 < KB, rb);

#pragma unroll
    for (int j = 0; j < 4; j++) As[0][ak + j][am] = ra[j];
    if (TRANSB) {
#pragma unroll
        for (int j = 0; j < 8; j++) Bs[0][bk + j][bn] = rb[j];
    } else {
        *(float4*)&Bs[0][bk2][bnq]     = make_float4(rb[0], rb[1], rb[2], rb[3]);
        *(float4*)&Bs[0][bk2][bnq + 4] = make_float4(rb[4], rb[5], rb[6], rb[7]);
    }
    __syncthreads();

    u64 acc[4][4];
#pragma unroll
    for (int i = 0; i < 4; i++)
#pragma unroll
        for (int j = 0; j < 4; j++) acc[i][j] = 0ull;

    int m0 = (t >> 4) * 4, n0 = (t & 15) * 8;
    int buf = 0;

    for (int k0 = 0; k0 < Kloop; k0 += 16) {
        int kn = k0 + 16;
        bool more = kn < Kloop;
        if (more) {
            ld4(aPtr + kn, avalid, ra);
            if (TRANSB) ld8(bPtrT + kn, bnvalid, rb);
            else        ld8(bPtrN + (size_t)kn * ldB, (kn + bk2) < KB, rb);
        }
#pragma unroll
        for (int kk = 0; kk < 16; kk++) {
            ulonglong2 bA  = *(const ulonglong2*)&Bs[buf][kk][n0];
            ulonglong2 bBv = *(const ulonglong2*)&Bs[buf][kk][n0 + 4];
            float4 a = *(const float4*)&As[buf][kk][m0];
            u64 a0 = pack2(a.x, a.x), a1 = pack2(a.y, a.y);
            u64 a2 = pack2(a.z, a.z), a3 = pack2(a.w, a.w);
            acc[0][0] = ffma2(a0, bA.x, acc[0][0]);
            acc[0][1] = ffma2(a0, bA.y, acc[0][1]);
            acc[0][2] = ffma2(a0, bBv.x, acc[0][2]);
            acc[0][3] = ffma2(a0, bBv.y, acc[0][3]);
            acc[1][0] = ffma2(a1, bA.x, acc[1][0]);
            acc[1][1] = ffma2(a1, bA.y, acc[1][1]);
            acc[1][2] = ffma2(a1, bBv.x, acc[1][2]);
            acc[1][3] = ffma2(a1, bBv.y, acc[1][3]);
            acc[2][0] = ffma2(a2, bA.x, acc[2][0]);
            acc[2][1] = ffma2(a2, bA.y, acc[2][1]);
            acc[2][2] = ffma2(a2, bBv.x, acc[2][2]);
            acc[2][3] = ffma2(a2, bBv.y, acc[2][3]);
            acc[3][0] = ffma2(a3, bA.x, acc[3][0]);
            acc[3][1] = ffma2(a3, bA.y, acc[3][1]);
            acc[3][2] = ffma2(a3, bBv.x, acc[3][2]);
            acc[3][3] = ffma2(a3, bBv.y, acc[3][3]);
        }
        if (more) {
            int nb = buf ^ 1;
#pragma unroll
            for (int j = 0; j < 4; j++) As[nb][ak + j][am] = ra[j];
            if (TRANSB) {
#pragma unroll
                for (int j = 0; j < 8; j++) Bs[nb][bk + j][bn] = rb[j];
            } else {
                *(float4*)&Bs[nb][bk2][bnq]     = make_float4(rb[0], rb[1], rb[2], rb[3]);
                *(float4*)&Bs[nb][bk2][bnq + 4] = make_float4(rb[4], rb[5], rb[6], rb[7]);
            }
            __syncthreads();
            buf = nb;
        }
    }

    if (EPI == 1) {
        // fused bias + row L2-normalize; row owned by 16 consecutive lanes
        float bkv[8];
#pragma unroll
        for (int j = 0; j < 8; j++) bkv[j] = AUX[n0 + j];
#pragma unroll
        for (int i = 0; i < 4; i++) {
            int m = mBase + m0 + i;
            float o[8];
#pragma unroll
            for (int j = 0; j < 4; j++) unpack2(acc[i][j], o[2 * j], o[2 * j + 1]);
            float ss = 0.0f;
#pragma unroll
            for (int j = 0; j < 8; j++) {
                o[j] += bkv[j];
                ss += o[j] * o[j];
            }
#pragma unroll
            for (int d = 8; d; d >>= 1) ss += __shfl_xor_sync(0xffffffffu, ss, d, 16);
            float rn = 1.0f / fmaxf(sqrtf(ss), 1e-12f);
            if (m < M) {
                size_t off = (size_t)m * 128 + n0;
                *(float4*)(C + off)     = make_float4(o[0] * rn, o[1] * rn, o[2] * rn, o[3] * rn);
                *(float4*)(C + off + 4) = make_float4(o[4] * rn, o[5] * rn, o[6] * rn, o[7] * rn);
            }
        }
        return;
    }

    if (EPI == 2) {
        bool interior = (nBase + 128) <= NVALID;
#pragma unroll
        for (int i = 0; i < 4; i++) {
            int m = mBase + m0 + i;
            if (m >= M) continue;
            float o[8];
#pragma unroll
            for (int j = 0; j < 4; j++) unpack2(acc[i][j], o[2 * j], o[2 * j + 1]);
            size_t off = (size_t)g * sC + (size_t)m * ldC + nBase + n0;
            if (interior) {
                *(float4*)(C + off) = make_float4(
                    __expf(alpha * o[0]), __expf(alpha * o[1]),
                    __expf(alpha * o[2]), __expf(alpha * o[3]));
                *(float4*)(C + off + 4) = make_float4(
                    __expf(alpha * o[4]), __expf(alpha * o[5]),
                    __expf(alpha * o[6]), __expf(alpha * o[7]));
            } else {
#pragma unroll
                for (int j = 0; j < 8; j++) {
                    int n = nBase + n0 + j;
                    if (n < ldC) C[off + j] = (n < NVALID) ? __expf(alpha * o[j]) : 0.0f;
                }
            }
        }
        return;
    }

    if (EPI == 3) {
#pragma unroll
        for (int i = 0; i < 4; i++) {
            int m = mBase + m0 + i;
            if (m >= M) continue;
            float rs = AUX[(size_t)g * M + m];
            float o[8];
#pragma unroll
            for (int j = 0; j < 4; j++) unpack2(acc[i][j], o[2 * j], o[2 * j + 1]);
            size_t off = (size_t)g * sC + (size_t)m * ldC + nBase + n0;
            float4 c0 = *(const float4*)(Cin + off);
            float4 c1 = *(const float4*)(Cin + off + 4);
            *(float4*)(C + off) = make_float4(rs * o[0] + c0.x, rs * o[1] + c0.y,
                                              rs * o[2] + c0.z, rs * o[3] + c0.w);
            *(float4*)(C + off + 4) = make_float4(rs * o[4] + c1.x, rs * o[5] + c1.y,
                                                  rs * o[6] + c1.z, rs * o[7] + c1.w);
        }
        return;
    }

    // EPI 0
    bool fullN = (nBase + 128) <= N;
#pragma unroll
    for (int i = 0; i < 4; i++) {
        int m = mBase + m0 + i;
        if (m >= M) continue;
        float o[8];
#pragma unroll
        for (int j = 0; j < 4; j++) unpack2(acc[i][j], o[2 * j], o[2 * j + 1]);
#pragma unroll
        for (int j = 0; j < 8; j++) o[j] *= alpha;
        size_t off = (size_t)g * sC + (size_t)m * ldC + nBase + n0;
        if (fullN) {
            if (addC) {
                float4 c0 = *(const float4*)(Cin + off);
                float4 c1 = *(const float4*)(Cin + off + 4);
                o[0] += c0.x; o[1] += c0.y; o[2] += c0.z; o[3] += c0.w;
                o[4] += c1.x; o[5] += c1.y; o[6] += c1.z; o[7] += c1.w;
            }
            *(float4*)(C + off)     = make_float4(o[0], o[1], o[2], o[3]);
            *(float4*)(C + off + 4) = make_float4(o[4], o[5], o[6], o[7]);
        } else {
#pragma unroll
            for (int j = 0; j < 8; j++) {
                int n = nBase + n0 + j;
                if (n < N) {
                    float v = o[j];
                    if (addC) v += Cin[off + j];
                    C[off + j] = v;
                }
            }
        }
    }
}

// ================= small kernels =================
__global__ void pe_kernel(float* __restrict__ pe) {
    int idx = blockIdx.x * 256 + threadIdx.x;
    if (idx >= HW * DD) return;
    int p = idx >> 9, c = idx & 511;
    float pos = (float)(p + 1);
    int j = c & 255;
    float f = powf(10000.0f, -(float)j * (1.0f / 256.0f));
    float a = pos * f;
    pe[idx] = (c < 256) ? sinf(a) : cosf(a);
}

__global__ void label_kernel(const float* __restrict__ lab, float* __restrict__ out) {
    int idx = blockIdx.x * 256 + threadIdx.x;
    if (idx >= 3 * BB * HW) return;
    int p = idx % HW;
    int t = idx / HW;
    int b = t % BB;
    int ni = t / BB;
    out[(size_t)b * LE + ni * HW + p] = lab[idx];
}

__global__ void build_kernel(const float* __restrict__ fa, const float* __restrict__ fb,
                             int split, const float* __restrict__ pe,
                             float* __restrict__ xout, int mode) {
    int g = blockIdx.x;
    int img = g >> 4, b = g & 15;
    const float* f = (img < split) ? (fa + (size_t)img * BB * DD * HW)
                                   : (fb + (size_t)(img - split) * BB * DD * HW);
    int p0 = blockIdx.y * 32, c0 = blockIdx.z * 32;
    __shared__ float tl[32][33];
    int tx = threadIdx.x, ty = threadIdx.y;
#pragma unroll
    for (int r = 0; r < 4; r++) {
        int c = c0 + ty + r * 8, p = p0 + tx;
        if (p < HW) tl[ty + r * 8][tx] = f[((size_t)b * DD + c) * HW + p];
    }
    __syncthreads();
#pragma unroll
    for (int r = 0; r < 4; r++) {
        int p = p0 + ty + r * 8, c = c0 + tx;
        if (p < HW) {
            size_t row = (mode == 0) ? ((size_t)b * LE + (size_t)img * HW + p)
                                     : ((size_t)g * LDQ + p);
            xout[row * DD + c] = tl[tx][ty + r * 8] + pe[(size_t)p * DD + c] * 1e-3f;
        }
    }
}

// row sums of exp'd probs -> 1/sum (and mask = sum(p*label)/sum when LABEL)
__global__ void rowsum_kernel(const float* __restrict__ P, const float* __restrict__ LABEL,
                              float* __restrict__ RS, float* __restrict__ MASKOUT,
                              int Mrows, int Lk, int ld, int gkMod) {
    int q = blockIdx.x, g = blockIdx.y, t = threadIdx.x;   // 128 threads
    int gk = gkMod ? (g & 15) : g;
    const float4* p4 = (const float4*)(P + ((size_t)g * Mrows + q) * ld);
    int n4 = Lk >> 2;
    float s = 0.0f, ms = 0.0f;
    if (LABEL) {
        const float4* l4 = (const float4*)(LABEL + (size_t)gk * Lk);
        for (int i = t; i < n4; i += 128) {
            float4 v = p4[i];
            float4 lv = l4[i];
            s += v.x + v.y + v.z + v.w;
            ms += v.x * lv.x + v.y * lv.y + v.z * lv.z + v.w * lv.w;
        }
    } else {
        for (int i = t; i < n4; i += 128) {
            float4 v = p4[i];
            s += v.x + v.y + v.z + v.w;
        }
    }
    __shared__ float rs_[4], rm_[4];
#pragma unroll
    for (int m = 16; m; m >>= 1) {
        s += __shfl_xor_sync(0xffffffffu, s, m);
        ms += __shfl_xor_sync(0xffffffffu, ms, m);
    }
    if ((t & 31) == 0) { rs_[t >> 5] = s; rm_[t >> 5] = ms; }
    __syncthreads();
    if (t == 0) {
        float st = rs_[0] + rs_[1] + rs_[2] + rs_[3];
        float inv = 1.0f / st;
        RS[(size_t)g * Mrows + q] = inv;
        if (MASKOUT) {
            float mt = rm_[0] + rm_[1] + rm_[2] + rm_[3];
            MASKOUT[(size_t)g * Mrows + q] = mt * inv;
        }
    }
}

// memlab[b][k][d] = mem[b][k][d] * label[b][k]
__global__ void memlab_kernel(const float* __restrict__ mem, const float* __restrict__ label,
                              float* __restrict__ ml) {
    int i = blockIdx.x * 256 + threadIdx.x;   // float4 index
    if (i >= (int)(SZ_MEMLAB / 4)) return;
    float lb = label[i >> 7];
    float4 v = ((const float4*)mem)[i];
    v.x *= lb; v.y *= lb; v.z *= lb; v.w *= lb;
    ((float4*)ml)[i] = v;
}

// InstanceL2Norm: partial sums then apply (deterministic 2-stage)
__global__ void inorm_part(const float* __restrict__ in, float* __restrict__ part) {
    int g = blockIdx.x, q = blockIdx.y, t = threadIdx.x;
    const float4* ip = (const float4*)(in + (size_t)g * GRP) + (size_t)q * QF4;
    float ss = 0.0f;
    for (int i = t; i < QF4; i += 256) {
        float4 v = ip[i];
        ss += v.x * v.x + v.y * v.y + v.z * v.z + v.w * v.w;
    }
    __shared__ float red[8];
#pragma unroll
    for (int m = 16; m; m >>= 1) ss += __shfl_xor_sync(0xffffffffu, ss, m);
    if ((t & 31) == 0) red[t >> 5] = ss;
    __syncthreads();
    if (t == 0) {
        float s = 0.0f;
#pragma unroll
        for (int i = 0; i < 8; i++) s += red[i];
        part[g * 4 + q] = s;
    }
}

__global__ void inorm_apply(const float* __restrict__ in, float* __restrict__ out,
                            const float* __restrict__ part) {
    int g = blockIdx.x, q = blockIdx.y, t = threadIdx.x;
    float ss = part[g * 4 + 0] + part[g * 4 + 1] + part[g * 4 + 2] + part[g * 4 + 3];
    float sc = NSCALE * sqrtf(DHWF / (ss + IEPS));
    const float4* ip = (const float4*)(in + (size_t)g * GRP) + (size_t)q * QF4;
    float4* op = (float4*)(out + (size_t)g * GRP) + (size_t)q * QF4;
    for (int i = t; i < QF4; i += 256) {
        float4 v = ip[i];
        v.x *= sc; v.y *= sc; v.z *= sc; v.w *= sc;
        op[i] = v;
    }
}

// decoder 3-sum partials: u = x*mask, v = x + t3
__global__ void dec_part_kernel(const float* __restrict__ X, const float* __restrict__ XP,
                                const float* __restrict__ MASK, float* __restrict__ part) {
    int g = blockIdx.x, q = blockIdx.y, t = threadIdx.x;
    const float4* x4 = (const float4*)(X + (size_t)g * GRP);
    const float4* p4 = (const float4*)(XP + (size_t)g * GRP);
    const float* mk = MASK + (size_t)g * LDQ;
    float s2 = 0.0f, s4 = 0.0f, cr = 0.0f;
    for (int i = t; i < QF4; i += 256) {
        int gi = q * QF4 + i;
        float m = mk[gi >> 7];
        float4 x = x4[gi];
        float4 v = p4[gi];
        float ux = x.x * m, uy = x.y * m, uz = x.z * m, uw = x.w * m;
        s2 += ux * ux + uy * uy + uz * uz + uw * uw;
        s4 += v.x * v.x + v.y * v.y + v.z * v.z + v.w * v.w;
        cr += ux * v.x + uy * v.y + uz * v.z + uw * v.w;
    }
    __shared__ float r2[8], r4[8], rc[8];
#pragma unroll
    for (int m = 16; m; m >>= 1) {
        s2 += __shfl_xor_sync(0xffffffffu, s2, m);
        s4 += __shfl_xor_sync(0xffffffffu, s4, m);
        cr += __shfl_xor_sync(0xffffffffu, cr, m);
    }
    if ((t & 31) == 0) { r2[t >> 5] = s2; r4[t >> 5] = s4; rc[t >> 5] = cr; }
    __syncthreads();
    if (t == 0) {
        float a = 0, b = 0, c = 0;
#pragma unroll
        for (int i = 0; i < 8; i++) { a += r2[i]; b += r4[i]; c += rc[i]; }
        part[(g * 4 + q) * 3 + 0] = a;
        part[(g * 4 + q) * 3 + 1] = b;
        part[(g * 4 + q) * 3 + 2] = c;
    }
}

__global__ void dec_scale_kernel(const float* __restrict__ part, float* __restrict__ SC) {
    int g = threadIdx.x;
    if (g >= 96) return;
    float a = 0, b = 0, c = 0;
#pragma unroll
    for (int q = 0; q < 4; q++) {
        a += part[(g * 4 + q) * 3 + 0];
        b += part[(g * 4 + q) * 3 + 1];
        c += part[(g * 4 + q) * 3 + 2];
    }
    float S2 = NSCALE * sqrtf(DHWF / (a + IEPS));
    float S4 = NSCALE * sqrtf(DHWF / (b + IEPS));
    float sso = S2 * S2 * a + 2.0f * S2 * S4 * c + S4 * S4 * b;
    float SO = NSCALE * sqrtf(DHWF / (sso + IEPS));
    SC[g * 4 + 0] = S2;
    SC[g * 4 + 1] = S4;
    SC[g * 4 + 2] = SO;
}

__global__ void final_kernel(const float* __restrict__ X, const float* __restrict__ XP,
                             const float* __restrict__ MASK, const float* __restrict__ SC,
                             float* __restrict__ out) {
    int g = blockIdx.x;
    float S2 = SC[g * 4 + 0], S4 = SC[g * 4 + 1], SO = SC[g * 4 + 2];
    int p0 = blockIdx.y * 32, c0 = blockIdx.z * 32;
    __shared__ float tile[32][33];
    int tx = threadIdx.x, ty = threadIdx.y;
    size_t base = (size_t)g * GRP;
#pragma unroll
    for (int r = 0; r < 4; r++) {
        int p = p0 + ty + r * 8, c = c0 + tx;
        if (p < LDQ) {
            size_t idx = base + (size_t)p * 512 + c;
            float u = X[idx] * MASK[(size_t)g * LDQ + p];
            tile[ty + r * 8][tx] = SO * (S2 * u + S4 * XP[idx]);
        }
    }
    __syncthreads();
#pragma unroll
    for (int r = 0; r < 4; r++) {
        int p = p0 + tx, c = c0 + ty + r * 8;
        if (p < LDQ) out[((size_t)g * 512 + c) * LDQ + p] = tile[tx][ty + r * 8];
    }
}

// ================= launcher =================
extern "C" void kernel_launch(void* const* d_in, const int* in_sizes, int n_in,
                              void* d_out, int out_size) {
    const float* train_feat  = (const float*)d_in[0];
    const float* test_feat   = (const float*)d_in[1];
    const float* train_label = (const float*)d_in[2];
    const float* wk_self     = (const float*)d_in[3];
    const float* bk_self     = (const float*)d_in[4];
    const float* wk_cross    = (const float*)d_in[5];
    const float* bk_cross    = (const float*)d_in[6];
    float* out = (float*)d_out;

    float* base = nullptr;
    cudaGetSymbolAddress((void**)&base, g_scratch);
    float* pe     = base + OFF_PE;
    float* label  = base + OFF_LABEL;
    float* xe     = base + OFF_XE;
    float* x1e    = base + OFF_X1E;
    float* mem    = base + OFF_MEM;
    float* pq     = base + OFF_PQ;
    float* pkc    = base + OFF_PKC;
    float* dx0    = base + OFF_DX0;
    float* dx1    = base + OFF_DX1;
    float* dx     = base + OFF_DX;
    float* dxpt3  = base + OFF_DXPT3;
    float* dpq    = base + OFF_DPQ;
    float* dmask  = base + OFF_DMASK;
    float* dsc    = base + OFF_DSC;
    float* ipart  = base + OFF_IPART;
    float* dpart  = base + OFF_DPART;
    float* memlab = base + OFF_MEMLAB;
    float* rsum   = base + OFF_RSUM;
    float* probs  = base + OFF_PROBS;

    dim3 tb(32, 8);

    pe_kernel<<<(HW * DD + 255) / 256, 256>>>(pe);
    label_kernel<<<(3 * BB * HW + 255) / 256, 256>>>(train_label, label);

    // ---- encoder ----
    build_kernel<<<dim3(48, 16, 16), tb>>>(train_feat, train_feat, 3, pe, xe, 0);
    // proj self (fused bias+norm)
    gemm_kernel<1, 1><<<dim3(1, (16 * LE + 63) / 64, 1), 256>>>(
        xe, wk_self, nullptr, pq, bk_self, 16 * LE, 128, 512, 512,
        512, 512, 128, 0, 0, 0, 0, 1.0f, 0, 128);
    // logits with exp epilogue
    gemm_kernel<1, 2><<<dim3(12, (LE + 63) / 64, 16), 256>>>(
        pq, pq, nullptr, probs, nullptr, LE, LE, 128, 128,
        128, 128, 1456, (size_t)LE * 128, (size_t)LE * 128, (size_t)LE * 1456,
        0, 30.0f, 0, LE);
    rowsum_kernel<<<dim3(LE, 16), 128>>>(probs, nullptr, rsum, nullptr, LE, 1456, 1456, 0);
    // value + residual, row-scaled
    gemm_kernel<0, 3><<<dim3(4, (LE + 63) / 64, 16), 256>>>(
        probs, xe, xe, x1e, rsum, LE, 512, 1456, LE,
        1456, 512, 512, (size_t)LE * 1456, (size_t)LE * 512, (size_t)LE * 512,
        0, 1.0f, 1, 512);
    inorm_part<<<dim3(48, 4), 256>>>(x1e, ipart);
    inorm_apply<<<dim3(48, 4), 256>>>(x1e, mem, ipart);
    // cross keys + memlab
    gemm_kernel<1, 1><<<dim3(1, (16 * LE + 63) / 64, 1), 256>>>(
        mem, wk_cross, nullptr, pkc, bk_cross, 16 * LE, 128, 512, 512,
        512, 512, 128, 0, 0, 0, 0, 1.0f, 0, 128);
    memlab_kernel<<<((int)(SZ_MEMLAB / 4) + 255) / 256, 256>>>(mem, label, memlab);

    // ---- decoder (96 batched) ----
    build_kernel<<<dim3(96, 16, 16), tb>>>(train_feat, test_feat, 3, pe, dx0, 1);
    gemm_kernel<1, 1><<<dim3(1, (96 * LDQ + 63) / 64, 1), 256>>>(
        dx0, wk_self, nullptr, dpq, bk_self, 96 * LDQ, 128, 512, 512,
        512, 512, 128, 0, 0, 0, 0, 1.0f, 0, 128);
    gemm_kernel<1, 2><<<dim3(4, (LDQ + 63) / 64, 96), 256>>>(
        dpq, dpq, nullptr, probs, nullptr, LDQ, LDQ, 128, 128,
        128, 128, 496, (size_t)LDQ * 128, (size_t)LDQ * 128, (size_t)LDQ * 496,
        0, 30.0f, 0, LDQ);
    rowsum_kernel<<<dim3(LDQ, 96), 128>>>(probs, nullptr, rsum, nullptr, LDQ, 496, 496, 0);
    gemm_kernel<0, 3><<<dim3(4, (LDQ + 63) / 64, 96), 256>>>(
        probs, dx0, dx0, dx1, rsum, LDQ, 512, 496, LDQ,
        496, 512, 512, (size_t)LDQ * 496, (size_t)LDQ * 512, (size_t)LDQ * 512,
        0, 1.0f, 1, 512);
    inorm_part<<<dim3(96, 4), 256>>>(dx1, ipart);
    inorm_apply<<<dim3(96, 4), 256>>>(dx1, dx, ipart);
    gemm_kernel<1, 1><<<dim3(1, (96 * LDQ + 63) / 64, 1), 256>>>(
        dx, wk_cross, nullptr, dpq, bk_cross, 96 * LDQ, 128, 512, 512,
        512, 512, 128, 0, 0, 0, 0, 1.0f, 0, 128);
    // cross logits (keys shared per batch: gk = g & 15) with exp epilogue
    gemm_kernel<1, 2><<<dim3(12, (LDQ + 63) / 64, 96), 256>>>(
        dpq, pkc, nullptr, probs, nullptr, LDQ, LE, 128, 128,
        128, 128, 1456, (size_t)LDQ * 128, (size_t)LE * 128, (size_t)LDQ * 1456,
        1, 30.0f, 0, LE);
    rowsum_kernel<<<dim3(LDQ, 96), 128>>>(probs, label, rsum, dmask, LDQ, LE, 1456, 1);
    // t3 value: P~ @ (mem*label), row-scaled, + dx residual
    gemm_kernel<0, 3><<<dim3(4, (LDQ + 63) / 64, 96), 256>>>(
        probs, memlab, dx, dxpt3, rsum, LDQ, 512, 1456, LE,
        1456, 512, 512, (size_t)LDQ * 1456, (size_t)LE * 512, (size_t)LDQ * 512,
        1, 1.0f, 1, 512);
    dec_part_kernel<<<dim3(96, 4), 256>>>(dx, dxpt3, dmask, dpart);
    dec_scale_kernel<<<1, 96>>>(dpart, dsc);
    final_kernel<<<dim3(96, 16, 16), tb>>>(dx, dxpt3, dmask, dsc, out);
}

// round 7
// speedup vs baseline: 1.4401x; 1.4401x over previous
#include <cuda_runtime.h>
#include <math.h>
#include <stdint.h>

typedef unsigned long long u64;

#define BB 16
#define DD 512
#define HW 484
#define LE 1452
#define LDQ 484
#define NSCALE 0.011048543456039806f
#define DHWF 247808.0f
#define IEPS 1e-5f
#define GRP 247808
#define QF4 15488   // GRP/4/4 : float4s per quarter

// ---- scratch layout (floats) ----
#define SZ_PE     ((size_t)HW*DD)
#define SZ_LABEL  ((size_t)BB*LE)
#define SZ_XE     ((size_t)BB*LE*DD)
#define SZ_PQ     ((size_t)BB*LE*128)
#define SZ_DX     ((size_t)96*LDQ*DD)
#define SZ_DPQ    ((size_t)96*LDQ*128)
#define SZ_DMASK  ((size_t)96*LDQ)
#define SZ_PROBS  ((size_t)96*LDQ*1456)
#define SZ_MEMLAB ((size_t)BB*LE*DD)
#define SZ_RSUM   ((size_t)96*LDQ)

#define OFF_PE    ((size_t)0)
#define OFF_LABEL (OFF_PE + SZ_PE)
#define OFF_XE    (OFF_LABEL + SZ_LABEL)
#define OFF_X1E   (OFF_XE + SZ_XE)
#define OFF_MEM   (OFF_X1E + SZ_XE)
#define OFF_PQ    (OFF_MEM + SZ_XE)
#define OFF_PKC   (OFF_PQ + SZ_PQ)
#define OFF_DX0   (OFF_PKC + SZ_PQ)
#define OFF_DX1   (OFF_DX0 + SZ_DX)
#define OFF_DX    (OFF_DX1 + SZ_DX)
#define OFF_DXPT3 (OFF_DX + SZ_DX)
#define OFF_DPQ   (OFF_DXPT3 + SZ_DX)
#define OFF_DMASK (OFF_DPQ + SZ_DPQ)
#define OFF_DSC   (OFF_DMASK + SZ_DMASK)
#define OFF_IPART (OFF_DSC + 96*4)
#define OFF_DPART (OFF_IPART + 96*4)
#define OFF_MEMLAB (OFF_DPART + 96*4*3)
#define OFF_RSUM  (OFF_MEMLAB + SZ_MEMLAB)
#define OFF_PROBS (OFF_RSUM + SZ_RSUM)
#define SCRATCH_TOTAL (OFF_PROBS + SZ_PROBS)

__device__ __align__(16) float g_scratch[SCRATCH_TOTAL];

// ---- f32x2 helpers ----
__device__ __forceinline__ u64 ffma2(u64 a, u64 b, u64 c) {
    u64 d;
    asm("fma.rn.f32x2 %0, %1, %2, %3;" : "=l"(d) : "l"(a), "l"(b), "l"(c));
    return d;
}
__device__ __forceinline__ u64 pack2(float lo, float hi) {
    u64 r;
    asm("mov.b64 %0, {%1, %2};" : "=l"(r) : "f"(lo), "f"(hi));
    return r;
}
__device__ __forceinline__ void unpack2(u64 v, float& lo, float& hi) {
    asm("mov.b64 {%0, %1}, %2;" : "=f"(lo), "=f"(hi) : "l"(v));
}

__device__ __forceinline__ void ld8(const float* p, bool valid, float* r) {
    if (valid) {
        float4 v0 = *(const float4*)p;
        float4 v1 = *(const float4*)(p + 4);
        r[0] = v0.x; r[1] = v0.y; r[2] = v0.z; r[3] = v0.w;
        r[4] = v1.x; r[5] = v1.y; r[6] = v1.z; r[7] = v1.w;
    } else {
#pragma unroll
        for (int j = 0; j < 8; j++) r[j] = 0.0f;
    }
}

// ============ generic batched GEMM, 128x128 tile, double-buffered ============
// C[g] = f( A[g] @ op(B[gk]) );  op = B^T if TRANSB (B is [N][K]).
// EPI 0: alpha*acc (+Cin)
// EPI 1: bias(AUX) + row L2-normalize  (proj; N==128, G==1)
// EPI 2: exp(alpha*acc) for n<NVALID else 0  (logits; ldC = padded width)
// EPI 3: AUX[g*M+m]*acc + Cin          (value with row 1/sum scale)
template<int TRANSB, int EPI>
__global__ void __launch_bounds__(256, 2)
gemm_kernel(const float* __restrict__ A, const float* __restrict__ B,
            const float* __restrict__ Cin, float* __restrict__ C,
            const float* __restrict__ AUX,
            int M, int N, int Kloop, int KB,
            int ldA, int ldB, int ldC,
            size_t sA, size_t sB, size_t sC,
            int gkMod, float alpha, int addC, int NVALID) {
    __shared__ float As[2][16][132];
    __shared__ float Bs[2][16][132];
    int g = blockIdx.z;
    int gk = gkMod ? (g & 15) : g;
    const float* Ag = A + (size_t)g * sA;
    const float* Bg = B + (size_t)gk * sB;
    int mBase = blockIdx.y * 128, nBase = blockIdx.x * 128;
    int t = threadIdx.x;

    int am = t >> 1, ak = (t & 1) * 8;
    bool avalid = (mBase + am) < M;
    const float* aPtr = Ag + (size_t)(mBase + am) * ldA + ak;

    int bn = t >> 1, bk = (t & 1) * 8;       // TRANSB path
    int bk2 = t >> 4, bnq = (t & 15) * 8;    // NN path
    bool bnvalid = (nBase + bn) < N;
    const float* bPtrT = Bg + (size_t)(nBase + bn) * ldB + bk;
    const float* bPtrN = Bg + (size_t)bk2 * ldB + nBase + bnq;

    float ra[8], rb[8];
    ld8(aPtr, avalid, ra);
    if (TRANSB) ld8(bPtrT, bnvalid, rb);
    else        ld8(bPtrN, bk2 < KB, rb);

#pragma unroll
    for (int j = 0; j < 8; j++) As[0][ak + j][am] = ra[j];
    if (TRANSB) {
#pragma unroll
        for (int j = 0; j < 8; j++) Bs[0][bk + j][bn] = rb[j];
    } else {
        *(float4*)&Bs[0][bk2][bnq]     = make_float4(rb[0], rb[1], rb[2], rb[3]);
        *(float4*)&Bs[0][bk2][bnq + 4] = make_float4(rb[4], rb[5], rb[6], rb[7]);
    }
    __syncthreads();

    u64 acc[8][4];
#pragma unroll
    for (int i = 0; i < 8; i++)
#pragma unroll
        for (int j = 0; j < 4; j++) acc[i][j] = 0ull;

    int m0 = (t >> 4) * 8, n0 = (t & 15) * 8;
    int buf = 0;

    for (int k0 = 0; k0 < Kloop; k0 += 16) {
        int kn = k0 + 16;
        bool more = kn < Kloop;
        if (more) {
            ld8(aPtr + kn, avalid, ra);
            if (TRANSB) ld8(bPtrT + kn, bnvalid, rb);
            else        ld8(bPtrN + (size_t)kn * ldB, (kn + bk2) < KB, rb);
        }
#pragma unroll
        for (int kk = 0; kk < 16; kk++) {
            ulonglong2 bA  = *(const ulonglong2*)&Bs[buf][kk][n0];
            ulonglong2 bBv = *(const ulonglong2*)&Bs[buf][kk][n0 + 4];
            float4 a0 = *(const float4*)&As[buf][kk][m0];
            float4 a1 = *(const float4*)&As[buf][kk][m0 + 4];
            float av[8] = {a0.x, a0.y, a0.z, a0.w, a1.x, a1.y, a1.z, a1.w};
#pragma unroll
            for (int i = 0; i < 8; i++) {
                u64 ad = pack2(av[i], av[i]);
                acc[i][0] = ffma2(ad, bA.x, acc[i][0]);
                acc[i][1] = ffma2(ad, bA.y, acc[i][1]);
                acc[i][2] = ffma2(ad, bBv.x, acc[i][2]);
                acc[i][3] = ffma2(ad, bBv.y, acc[i][3]);
            }
        }
        if (more) {
            int nb = buf ^ 1;
#pragma unroll
            for (int j = 0; j < 8; j++) As[nb][ak + j][am] = ra[j];
            if (TRANSB) {
#pragma unroll
                for (int j = 0; j < 8; j++) Bs[nb][bk + j][bn] = rb[j];
            } else {
                *(float4*)&Bs[nb][bk2][bnq]     = make_float4(rb[0], rb[1], rb[2], rb[3]);
                *(float4*)&Bs[nb][bk2][bnq + 4] = make_float4(rb[4], rb[5], rb[6], rb[7]);
            }
            __syncthreads();
            buf = nb;
        }
    }

    if (EPI == 1) {
        float bkv[8];
#pragma unroll
        for (int j = 0; j < 8; j++) bkv[j] = AUX[n0 + j];
#pragma unroll
        for (int i = 0; i < 8; i++) {
            int m = mBase + m0 + i;
            float o[8];
#pragma unroll
            for (int j = 0; j < 4; j++) unpack2(acc[i][j], o[2 * j], o[2 * j + 1]);
            float ss = 0.0f;
#pragma unroll
            for (int j = 0; j < 8; j++) {
                o[j] += bkv[j];
                ss += o[j] * o[j];
            }
#pragma unroll
            for (int d = 8; d; d >>= 1) ss += __shfl_xor_sync(0xffffffffu, ss, d, 16);
            float rn = 1.0f / fmaxf(sqrtf(ss), 1e-12f);
            if (m < M) {
                size_t off = (size_t)m * 128 + n0;
                *(float4*)(C + off)     = make_float4(o[0] * rn, o[1] * rn, o[2] * rn, o[3] * rn);
                *(float4*)(C + off + 4) = make_float4(o[4] * rn, o[5] * rn, o[6] * rn, o[7] * rn);
            }
        }
        return;
    }

    if (EPI == 2) {
        bool interior = (nBase + 128) <= NVALID;
#pragma unroll
        for (int i = 0; i < 8; i++) {
            int m = mBase + m0 + i;
            if (m >= M) continue;
            float o[8];
#pragma unroll
            for (int j = 0; j < 4; j++) unpack2(acc[i][j], o[2 * j], o[2 * j + 1]);
            size_t off = (size_t)g * sC + (size_t)m * ldC + nBase + n0;
            if (interior) {
                *(float4*)(C + off) = make_float4(
                    __expf(alpha * o[0]), __expf(alpha * o[1]),
                    __expf(alpha * o[2]), __expf(alpha * o[3]));
                *(float4*)(C + off + 4) = make_float4(
                    __expf(alpha * o[4]), __expf(alpha * o[5]),
                    __expf(alpha * o[6]), __expf(alpha * o[7]));
            } else {
#pragma unroll
                for (int j = 0; j < 8; j++) {
                    int n = nBase + n0 + j;
                    if (n < ldC) C[off + j] = (n < NVALID) ? __expf(alpha * o[j]) : 0.0f;
                }
            }
        }
        return;
    }

    if (EPI == 3) {
#pragma unroll
        for (int i = 0; i < 8; i++) {
            int m = mBase + m0 + i;
            if (m >= M) continue;
            float rs = AUX[(size_t)g * M + m];
            float o[8];
#pragma unroll
            for (int j = 0; j < 4; j++) unpack2(acc[i][j], o[2 * j], o[2 * j + 1]);
            size_t off = (size_t)g * sC + (size_t)m * ldC + nBase + n0;
            float4 c0 = *(const float4*)(Cin + off);
            float4 c1 = *(const float4*)(Cin + off + 4);
            *(float4*)(C + off) = make_float4(rs * o[0] + c0.x, rs * o[1] + c0.y,
                                              rs * o[2] + c0.z, rs * o[3] + c0.w);
            *(float4*)(C + off + 4) = make_float4(rs * o[4] + c1.x, rs * o[5] + c1.y,
                                                  rs * o[6] + c1.z, rs * o[7] + c1.w);
        }
        return;
    }

    // EPI 0
    bool fullN = (nBase + 128) <= N;
#pragma unroll
    for (int i = 0; i < 8; i++) {
        int m = mBase + m0 + i;
        if (m >= M) continue;
        float o[8];
#pragma unroll
        for (int j = 0; j < 4; j++) unpack2(acc[i][j], o[2 * j], o[2 * j + 1]);
#pragma unroll
        for (int j = 0; j < 8; j++) o[j] *= alpha;
        size_t off = (size_t)g * sC + (size_t)m * ldC + nBase + n0;
        if (fullN) {
            if (addC) {
                float4 c0 = *(const float4*)(Cin + off);
                float4 c1 = *(const float4*)(Cin + off + 4);
                o[0] += c0.x; o[1] += c0.y; o[2] += c0.z; o[3] += c0.w;
                o[4] += c1.x; o[5] += c1.y; o[6] += c1.z; o[7] += c1.w;
            }
            *(float4*)(C + off)     = make_float4(o[0], o[1], o[2], o[3]);
            *(float4*)(C + off + 4) = make_float4(o[4], o[5], o[6], o[7]);
        } else {
#pragma unroll
            for (int j = 0; j < 8; j++) {
                int n = nBase + n0 + j;
                if (n < N) {
                    float v = o[j];
                    if (addC) v += Cin[off + j];
                    C[off + j] = v;
                }
            }
        }
    }
}

// ================= small kernels =================
__global__ void pe_kernel(float* __restrict__ pe) {
    int idx = blockIdx.x * 256 + threadIdx.x;
    if (idx >= HW * DD) return;
    int p = idx >> 9, c = idx & 511;
    float pos = (float)(p + 1);
    int j = c & 255;
    float f = powf(10000.0f, -(float)j * (1.0f / 256.0f));
    float a = pos * f;
    pe[idx] = (c < 256) ? sinf(a) : cosf(a);
}

__global__ void label_kernel(const float* __restrict__ lab, float* __restrict__ out) {
    int idx = blockIdx.x * 256 + threadIdx.x;
    if (idx >= 3 * BB * HW) return;
    int p = idx % HW;
    int t = idx / HW;
    int b = t % BB;
    int ni = t / BB;
    out[(size_t)b * LE + ni * HW + p] = lab[idx];
}

__global__ void build_kernel(const float* __restrict__ fa, const float* __restrict__ fb,
                             int split, const float* __restrict__ pe,
                             float* __restrict__ xout, int mode) {
    int g = blockIdx.x;
    int img = g >> 4, b = g & 15;
    const float* f = (img < split) ? (fa + (size_t)img * BB * DD * HW)
                                   : (fb + (size_t)(img - split) * BB * DD * HW);
    int p0 = blockIdx.y * 32, c0 = blockIdx.z * 32;
    __shared__ float tl[32][33];
    int tx = threadIdx.x, ty = threadIdx.y;
#pragma unroll
    for (int r = 0; r < 4; r++) {
        int c = c0 + ty + r * 8, p = p0 + tx;
        if (p < HW) tl[ty + r * 8][tx] = f[((size_t)b * DD + c) * HW + p];
    }
    __syncthreads();
#pragma unroll
    for (int r = 0; r < 4; r++) {
        int p = p0 + ty + r * 8, c = c0 + tx;
        if (p < HW) {
            size_t row = (mode == 0) ? ((size_t)b * LE + (size_t)img * HW + p)
                                     : ((size_t)g * LDQ + p);
            xout[row * DD + c] = tl[tx][ty + r * 8] + pe[(size_t)p * DD + c] * 1e-3f;
        }
    }
}

// row sums of exp'd probs -> 1/sum (and mask = sum(p*label)/sum when LABEL)
__global__ void rowsum_kernel(const float* __restrict__ P, const float* __restrict__ LABEL,
                              float* __restrict__ RS, float* __restrict__ MASKOUT,
                              int Mrows, int Lk, int ld, int gkMod) {
    int q = blockIdx.x, g = blockIdx.y, t = threadIdx.x;   // 128 threads
    int gk = gkMod ? (g & 15) : g;
    const float4* p4 = (const float4*)(P + ((size_t)g * Mrows + q) * ld);
    int n4 = Lk >> 2;
    float s = 0.0f, ms = 0.0f;
    if (LABEL) {
        const float4* l4 = (const float4*)(LABEL + (size_t)gk * Lk);
        for (int i = t; i < n4; i += 128) {
            float4 v = p4[i];
            float4 lv = l4[i];
            s += v.x + v.y + v.z + v.w;
            ms += v.x * lv.x + v.y * lv.y + v.z * lv.z + v.w * lv.w;
        }
    } else {
        for (int i = t; i < n4; i += 128) {
            float4 v = p4[i];
            s += v.x + v.y + v.z + v.w;
        }
    }
    __shared__ float rs_[4], rm_[4];
#pragma unroll
    for (int m = 16; m; m >>= 1) {
        s += __shfl_xor_sync(0xffffffffu, s, m);
        ms += __shfl_xor_sync(0xffffffffu, ms, m);
    }
    if ((t & 31) == 0) { rs_[t >> 5] = s; rm_[t >> 5] = ms; }
    __syncthreads();
    if (t == 0) {
        float st = rs_[0] + rs_[1] + rs_[2] + rs_[3];
        float inv = 1.0f / st;
        RS[(size_t)g * Mrows + q] = inv;
        if (MASKOUT) {
            float mt = rm_[0] + rm_[1] + rm_[2] + rm_[3];
            MASKOUT[(size_t)g * Mrows + q] = mt * inv;
        }
    }
}

// memlab[b][k][d] = mem[b][k][d] * label[b][k]
__global__ void memlab_kernel(const float* __restrict__ mem, const float* __restrict__ label,
                              float* __restrict__ ml) {
    int i = blockIdx.x * 256 + threadIdx.x;   // float4 index
    if (i >= (int)(SZ_MEMLAB / 4)) return;
    float lb = label[i >> 7];
    float4 v = ((const float4*)mem)[i];
    v.x *= lb; v.y *= lb; v.z *= lb; v.w *= lb;
    ((float4*)ml)[i] = v;
}

// InstanceL2Norm: partial sums then apply (deterministic 2-stage)
__global__ void inorm_part(const float* __restrict__ in, float* __restrict__ part) {
    int g = blockIdx.x, q = blockIdx.y, t = threadIdx.x;
    const float4* ip = (const float4*)(in + (size_t)g * GRP) + (size_t)q * QF4;
    float ss = 0.0f;
    for (int i = t; i < QF4; i += 256) {
        float4 v = ip[i];
        ss += v.x * v.x + v.y * v.y + v.z * v.z + v.w * v.w;
    }
    __shared__ float red[8];
#pragma unroll
    for (int m = 16; m; m >>= 1) ss += __shfl_xor_sync(0xffffffffu, ss, m);
    if ((t & 31) == 0) red[t >> 5] = ss;
    __syncthreads();
    if (t == 0) {
        float s = 0.0f;
#pragma unroll
        for (int i = 0; i < 8; i++) s += red[i];
        part[g * 4 + q] = s;
    }
}

__global__ void inorm_apply(const float* __restrict__ in, float* __restrict__ out,
                            const float* __restrict__ part) {
    int g = blockIdx.x, q = blockIdx.y, t = threadIdx.x;
    float ss = part[g * 4 + 0] + part[g * 4 + 1] + part[g * 4 + 2] + part[g * 4 + 3];
    float sc = NSCALE * sqrtf(DHWF / (ss + IEPS));
    const float4* ip = (const float4*)(in + (size_t)g * GRP) + (size_t)q * QF4;
    float4* op = (float4*)(out + (size_t)g * GRP) + (size_t)q * QF4;
    for (int i = t; i < QF4; i += 256) {
        float4 v = ip[i];
        v.x *= sc; v.y *= sc; v.z *= sc; v.w *= sc;
        op[i] = v;
    }
}

// decoder 3-sum partials: u = x*mask, v = x + t3
__global__ void dec_part_kernel(const float* __restrict__ X, const float* __restrict__ XP,
                                const float* __restrict__ MASK, float* __restrict__ part) {
    int g = blockIdx.x, q = blockIdx.y, t = threadIdx.x;
    const float4* x4 = (const float4*)(X + (size_t)g * GRP);
    const float4* p4 = (const float4*)(XP + (size_t)g * GRP);
    const float* mk = MASK + (size_t)g * LDQ;
    float s2 = 0.0f, s4 = 0.0f, cr = 0.0f;
    for (int i = t; i < QF4; i += 256) {
        int gi = q * QF4 + i;
        float m = mk[gi >> 7];
        float4 x = x4[gi];
        float4 v = p4[gi];
        float ux = x.x * m, uy = x.y * m, uz = x.z * m, uw = x.w * m;
        s2 += ux * ux + uy * uy + uz * uz + uw * uw;
        s4 += v.x * v.x + v.y * v.y + v.z * v.z + v.w * v.w;
        cr += ux * v.x + uy * v.y + uz * v.z + uw * v.w;
    }
    __shared__ float r2[8], r4[8], rc[8];
#pragma unroll
    for (int m = 16; m; m >>= 1) {
        s2 += __shfl_xor_sync(0xffffffffu, s2, m);
        s4 += __shfl_xor_sync(0xffffffffu, s4, m);
        cr += __shfl_xor_sync(0xffffffffu, cr, m);
    }
    if ((t & 31) == 0) { r2[t >> 5] = s2; r4[t >> 5] = s4; rc[t >> 5] = cr; }
    __syncthreads();
    if (t == 0) {
        float a = 0, b = 0, c = 0;
#pragma unroll
        for (int i = 0; i < 8; i++) { a += r2[i]; b += r4[i]; c += rc[i]; }
        part[(g * 4 + q) * 3 + 0] = a;
        part[(g * 4 + q) * 3 + 1] = b;
        part[(g * 4 + q) * 3 + 2] = c;
    }
}

__global__ void dec_scale_kernel(const float* __restrict__ part, float* __restrict__ SC) {
    int g = threadIdx.x;
    if (g >= 96) return;
    float a = 0, b = 0, c = 0;
#pragma unroll
    for (int q = 0; q < 4; q++) {
        a += part[(g * 4 + q) * 3 + 0];
        b += part[(g * 4 + q) * 3 + 1];
        c += part[(g * 4 + q) * 3 + 2];
    }
    float S2 = NSCALE * sqrtf(DHWF / (a + IEPS));
    float S4 = NSCALE * sqrtf(DHWF / (b + IEPS));
    float sso = S2 * S2 * a + 2.0f * S2 * S4 * c + S4 * S4 * b;
    float SO = NSCALE * sqrtf(DHWF / (sso + IEPS));
    SC[g * 4 + 0] = S2;
    SC[g * 4 + 1] = S4;
    SC[g * 4 + 2] = SO;
}

__global__ void final_kernel(const float* __restrict__ X, const float* __restrict__ XP,
                             const float* __restrict__ MASK, const float* __restrict__ SC,
                             float* __restrict__ out) {
    int g = blockIdx.x;
    float S2 = SC[g * 4 + 0], S4 = SC[g * 4 + 1], SO = SC[g * 4 + 2];
    int p0 = blockIdx.y * 32, c0 = blockIdx.z * 32;
    __shared__ float tile[32][33];
    int tx = threadIdx.x, ty = threadIdx.y;
    size_t base = (size_t)g * GRP;
#pragma unroll
    for (int r = 0; r < 4; r++) {
        int p = p0 + ty + r * 8, c = c0 + tx;
        if (p < LDQ) {
            size_t idx = base + (size_t)p * 512 + c;
            float u = X[idx] * MASK[(size_t)g * LDQ + p];
            tile[ty + r * 8][tx] = SO * (S2 * u + S4 * XP[idx]);
        }
    }
    __syncthreads();
#pragma unroll
    for (int r = 0; r < 4; r++) {
        int p = p0 + tx, c = c0 + ty + r * 8;
        if (p < LDQ) out[((size_t)g * 512 + c) * LDQ + p] = tile[tx][ty + r * 8];
    }
}

// ================= launcher =================
extern "C" void kernel_launch(void* const* d_in, const int* in_sizes, int n_in,
                              void* d_out, int out_size) {
    const float* train_feat  = (const float*)d_in[0];
    const float* test_feat   = (const float*)d_in[1];
    const float* train_label = (const float*)d_in[2];
    const float* wk_self     = (const float*)d_in[3];
    const float* bk_self     = (const float*)d_in[4];
    const float* wk_cross    = (const float*)d_in[5];
    const float* bk_cross    = (const float*)d_in[6];
    float* out = (float*)d_out;

    float* base = nullptr;
    cudaGetSymbolAddress((void**)&base, g_scratch);
    float* pe     = base + OFF_PE;
    float* label  = base + OFF_LABEL;
    float* xe     = base + OFF_XE;
    float* x1e    = base + OFF_X1E;
    float* mem    = base + OFF_MEM;
    float* pq     = base + OFF_PQ;
    float* pkc    = base + OFF_PKC;
    float* dx0    = base + OFF_DX0;
    float* dx1    = base + OFF_DX1;
    float* dx     = base + OFF_DX;
    float* dxpt3  = base + OFF_DXPT3;
    float* dpq    = base + OFF_DPQ;
    float* dmask  = base + OFF_DMASK;
    float* dsc    = base + OFF_DSC;
    float* ipart  = base + OFF_IPART;
    float* dpart  = base + OFF_DPART;
    float* memlab = base + OFF_MEMLAB;
    float* rsum   = base + OFF_RSUM;
    float* probs  = base + OFF_PROBS;

    dim3 tb(32, 8);

    pe_kernel<<<(HW * DD + 255) / 256, 256>>>(pe);
    label_kernel<<<(3 * BB * HW + 255) / 256, 256>>>(train_label, label);

    // ---- encoder ----
    build_kernel<<<dim3(48, 16, 16), tb>>>(train_feat, train_feat, 3, pe, xe, 0);
    gemm_kernel<1, 1><<<dim3(1, (16 * LE + 127) / 128, 1), 256>>>(
        xe, wk_self, nullptr, pq, bk_self, 16 * LE, 128, 512, 512,
        512, 512, 128, 0, 0, 0, 0, 1.0f, 0, 128);
    gemm_kernel<1, 2><<<dim3(12, (LE + 127) / 128, 16), 256>>>(
        pq, pq, nullptr, probs, nullptr, LE, LE, 128, 128,
        128, 128, 1456, (size_t)LE * 128, (size_t)LE * 128, (size_t)LE * 1456,
        0, 30.0f, 0, LE);
    rowsum_kernel<<<dim3(LE, 16), 128>>>(probs, nullptr, rsum, nullptr, LE, 1456, 1456, 0);
    gemm_kernel<0, 3><<<dim3(4, (LE + 127) / 128, 16), 256>>>(
        probs, xe, xe, x1e, rsum, LE, 512, 1456, LE,
        1456, 512, 512, (size_t)LE * 1456, (size_t)LE * 512, (size_t)LE * 512,
        0, 1.0f, 1, 512);
    inorm_part<<<dim3(48, 4), 256>>>(x1e, ipart);
    inorm_apply<<<dim3(48, 4), 256>>>(x1e, mem, ipart);
    gemm_kernel<1, 1><<<dim3(1, (16 * LE + 127) / 128, 1), 256>>>(
        mem, wk_cross, nullptr, pkc, bk_cross, 16 * LE, 128, 512, 512,
        512, 512, 128, 0, 0, 0, 0, 1.0f, 0, 128);
    memlab_kernel<<<((int)(SZ_MEMLAB / 4) + 255) / 256, 256>>>(mem, label, memlab);

    // ---- decoder (96 batched) ----
    build_kernel<<<dim3(96, 16, 16), tb>>>(train_feat, test_feat, 3, pe, dx0, 1);
    gemm_kernel<1, 1><<<dim3(1, (96 * LDQ + 127) / 128, 1), 256>>>(
        dx0, wk_self, nullptr, dpq, bk_self, 96 * LDQ, 128, 512, 512,
        512, 512, 128, 0, 0, 0, 0, 1.0f, 0, 128);
    gemm_kernel<1, 2><<<dim3(4, (LDQ + 127) / 128, 96), 256>>>(
        dpq, dpq, nullptr, probs, nullptr, LDQ, LDQ, 128, 128,
        128, 128, 496, (size_t)LDQ * 128, (size_t)LDQ * 128, (size_t)LDQ * 496,
        0, 30.0f, 0, LDQ);
    rowsum_kernel<<<dim3(LDQ, 96), 128>>>(probs, nullptr, rsum, nullptr, LDQ, 496, 496, 0);
    gemm_kernel<0, 3><<<dim3(4, (LDQ + 127) / 128, 96), 256>>>(
        probs, dx0, dx0, dx1, rsum, LDQ, 512, 496, LDQ,
        496, 512, 512, (size_t)LDQ * 496, (size_t)LDQ * 512, (size_t)LDQ * 512,
        0, 1.0f, 1, 512);
    inorm_part<<<dim3(96, 4), 256>>>(dx1, ipart);
    inorm_apply<<<dim3(96, 4), 256>>>(dx1, dx, ipart);
    gemm_kernel<1, 1><<<dim3(1, (96 * LDQ + 127) / 128, 1), 256>>>(
        dx, wk_cross, nullptr, dpq, bk_cross, 96 * LDQ, 128, 512, 512,
        512, 512, 128, 0, 0, 0, 0, 1.0f, 0, 128);
    gemm_kernel<1, 2><<<dim3(12, (LDQ + 127) / 128, 96), 256>>>(
        dpq, pkc, nullptr, probs, nullptr, LDQ, LE, 128, 128,
        128, 128, 1456, (size_t)LDQ * 128, (size_t)LE * 128, (size_t)LDQ * 1456,
        1, 30.0f, 0, LE);
    rowsum_kernel<<<dim3(LDQ, 96), 128>>>(probs, label, rsum, dmask, LDQ, LE, 1456, 1);
    gemm_kernel<0, 3><<<dim3(4, (LDQ + 127) / 128, 96), 256>>>(
        probs, memlab, dx, dxpt3, rsum, LDQ, 512, 1456, LE,
        1456, 512, 512, (size_t)LDQ * 1456, (size_t)LE * 512, (size_t)LDQ * 512,
        1, 1.0f, 1, 512);
    dec_part_kernel<<<dim3(96, 4), 256>>>(dx, dxpt3, dmask, dpart);
    dec_scale_kernel<<<1, 96>>>(dpart, dsc);
    final_kernel<<<dim3(96, 16, 16), tb>>>(dx, dxpt3, dmask, dsc, out);
}

// round 8
// speedup vs baseline: 1.6019x; 1.1123x over previous
#include <cuda_runtime.h>
#include <math.h>
#include <stdint.h>

typedef unsigned long long u64;

#define BB 16
#define DD 512
#define HW 484
#define LE 1452
#define LDQ 484
#define NSCALE 0.011048543456039806f
#define DHWF 247808.0f
#define IEPS 1e-5f
#define GRP 247808
#define QF4 15488   // GRP/4/4 : float4s per quarter

// ---- scratch layout (floats) ----
#define SZ_PE     ((size_t)HW*DD)
#define SZ_LABEL  ((size_t)BB*LE)
#define SZ_XE     ((size_t)BB*LE*DD)
#define SZ_PQ     ((size_t)BB*LE*128)
#define SZ_DX     ((size_t)96*LDQ*DD)
#define SZ_DPQ    ((size_t)96*LDQ*128)
#define SZ_DMASK  ((size_t)96*LDQ)
#define SZ_PROBS  ((size_t)96*LDQ*1456)
#define SZ_MEMLAB ((size_t)BB*LE*DD)
#define SZ_RSUM   ((size_t)96*LDQ)

#define OFF_PE    ((size_t)0)
#define OFF_LABEL (OFF_PE + SZ_PE)
#define OFF_XE    (OFF_LABEL + SZ_LABEL)
#define OFF_X1E   (OFF_XE + SZ_XE)
#define OFF_MEM   (OFF_X1E + SZ_XE)
#define OFF_PQ    (OFF_MEM + SZ_XE)
#define OFF_PKC   (OFF_PQ + SZ_PQ)
#define OFF_DX0   (OFF_PKC + SZ_PQ)
#define OFF_DX1   (OFF_DX0 + SZ_DX)
#define OFF_DX    (OFF_DX1 + SZ_DX)
#define OFF_DXPT3 (OFF_DX + SZ_DX)
#define OFF_DPQ   (OFF_DXPT3 + SZ_DX)
#define OFF_DMASK (OFF_DPQ + SZ_DPQ)
#define OFF_DSC   (OFF_DMASK + SZ_DMASK)
#define OFF_IPART (OFF_DSC + 96*4)
#define OFF_DPART (OFF_IPART + 96*4)
#define OFF_MEMLAB (OFF_DPART + 96*4*3)
#define OFF_RSUM  (OFF_MEMLAB + SZ_MEMLAB)
#define OFF_PROBS (OFF_RSUM + SZ_RSUM)
#define SCRATCH_TOTAL (OFF_PROBS + SZ_PROBS)

__device__ __align__(16) float g_scratch[SCRATCH_TOTAL];

// ---- f32x2 helpers ----
__device__ __forceinline__ u64 ffma2(u64 a, u64 b, u64 c) {
    u64 d;
    asm("fma.rn.f32x2 %0, %1, %2, %3;" : "=l"(d) : "l"(a), "l"(b), "l"(c));
    return d;
}
__device__ __forceinline__ u64 pack2(float lo, float hi) {
    u64 r;
    asm("mov.b64 %0, {%1, %2};" : "=l"(r) : "f"(lo), "f"(hi));
    return r;
}
__device__ __forceinline__ void unpack2(u64 v, float& lo, float& hi) {
    asm("mov.b64 {%0, %1}, %2;" : "=f"(lo), "=f"(hi) : "l"(v));
}

__device__ __forceinline__ void ld8(const float* p, bool valid, float* r) {
    if (valid) {
        float4 v0 = *(const float4*)p;
        float4 v1 = *(const float4*)(p + 4);
        r[0] = v0.x; r[1] = v0.y; r[2] = v0.z; r[3] = v0.w;
        r[4] = v1.x; r[5] = v1.y; r[6] = v1.z; r[7] = v1.w;
    } else {
#pragma unroll
        for (int j = 0; j < 8; j++) r[j] = 0.0f;
    }
}

// ============ generic batched GEMM, 128x128 tile, double-buffered ============
// Thread's 8 N-columns are split into two 4-wide segments 64 apart so every
// 8-lane LDS.128 phase covers all 32 banks exactly once (conflict-free).
// C[g] = f( A[g] @ op(B[gk]) );  op = B^T if TRANSB (B is [N][K]).
// EPI 0: alpha*acc (+Cin)
// EPI 1: bias(AUX) + row L2-normalize  (proj; N==128, G==1)
// EPI 2: exp(alpha*acc) for n<NVALID else 0  (logits; ldC = padded width)
// EPI 3: AUX[g*M+m]*acc + Cin          (value with row 1/sum scale)
template<int TRANSB, int EPI>
__global__ void __launch_bounds__(256, 2)
gemm_kernel(const float* __restrict__ A, const float* __restrict__ B,
            const float* __restrict__ Cin, float* __restrict__ C,
            const float* __restrict__ AUX,
            int M, int N, int Kloop, int KB,
            int ldA, int ldB, int ldC,
            size_t sA, size_t sB, size_t sC,
            int gkMod, float alpha, int addC, int NVALID) {
    __shared__ float As[2][16][132];
    __shared__ float Bs[2][16][132];
    int g = blockIdx.z;
    int gk = gkMod ? (g & 15) : g;
    const float* Ag = A + (size_t)g * sA;
    const float* Bg = B + (size_t)gk * sB;
    int mBase = blockIdx.y * 128, nBase = blockIdx.x * 128;
    int t = threadIdx.x;

    int am = t >> 1, ak = (t & 1) * 8;
    bool avalid = (mBase + am) < M;
    const float* aPtr = Ag + (size_t)(mBase + am) * ldA + ak;

    int bn = t >> 1, bk = (t & 1) * 8;       // TRANSB path
    int bk2 = t >> 4, bnq = (t & 15) * 8;    // NN path
    bool bnvalid = (nBase + bn) < N;
    const float* bPtrT = Bg + (size_t)(nBase + bn) * ldB + bk;
    const float* bPtrN = Bg + (size_t)bk2 * ldB + nBase + bnq;

    float ra[8], rb[8];
    ld8(aPtr, avalid, ra);
    if (TRANSB) ld8(bPtrT, bnvalid, rb);
    else        ld8(bPtrN, bk2 < KB, rb);

#pragma unroll
    for (int j = 0; j < 8; j++) As[0][ak + j][am] = ra[j];
    if (TRANSB) {
#pragma unroll
        for (int j = 0; j < 8; j++) Bs[0][bk + j][bn] = rb[j];
    } else {
        *(float4*)&Bs[0][bk2][bnq]     = make_float4(rb[0], rb[1], rb[2], rb[3]);
        *(float4*)&Bs[0][bk2][bnq + 4] = make_float4(rb[4], rb[5], rb[6], rb[7]);
    }
    __syncthreads();

    u64 acc[8][4];   // [mi][2*seg + pair] ; seg 0 -> cols nA..nA+3, seg 1 -> nA+64..
#pragma unroll
    for (int i = 0; i < 8; i++)
#pragma unroll
        for (int j = 0; j < 4; j++) acc[i][j] = 0ull;

    int m0 = (t >> 4) * 8;
    int nA = (t & 15) * 4;       // segment 0 base; segment 1 at nA + 64
    int buf = 0;

    for (int k0 = 0; k0 < Kloop; k0 += 16) {
        int kn = k0 + 16;
        bool more = kn < Kloop;
        if (more) {
            ld8(aPtr + kn, avalid, ra);
            if (TRANSB) ld8(bPtrT + kn, bnvalid, rb);
            else        ld8(bPtrN + (size_t)kn * ldB, (kn + bk2) < KB, rb);
        }
#pragma unroll
        for (int kk = 0; kk < 16; kk++) {
            ulonglong2 bA  = *(const ulonglong2*)&Bs[buf][kk][nA];        // cols nA..nA+3
            ulonglong2 bBv = *(const ulonglong2*)&Bs[buf][kk][nA + 64];   // cols nA+64..+67
            float4 a0 = *(const float4*)&As[buf][kk][m0];
            float4 a1 = *(const float4*)&As[buf][kk][m0 + 4];
            float av[8] = {a0.x, a0.y, a0.z, a0.w, a1.x, a1.y, a1.z, a1.w};
#pragma unroll
            for (int i = 0; i < 8; i++) {
                u64 ad = pack2(av[i], av[i]);
                acc[i][0] = ffma2(ad, bA.x, acc[i][0]);
                acc[i][1] = ffma2(ad, bA.y, acc[i][1]);
                acc[i][2] = ffma2(ad, bBv.x, acc[i][2]);
                acc[i][3] = ffma2(ad, bBv.y, acc[i][3]);
            }
        }
        if (more) {
            int nb = buf ^ 1;
#pragma unroll
            for (int j = 0; j < 8; j++) As[nb][ak + j][am] = ra[j];
            if (TRANSB) {
#pragma unroll
                for (int j = 0; j < 8; j++) Bs[nb][bk + j][bn] = rb[j];
            } else {
                *(float4*)&Bs[nb][bk2][bnq]     = make_float4(rb[0], rb[1], rb[2], rb[3]);
                *(float4*)&Bs[nb][bk2][bnq + 4] = make_float4(rb[4], rb[5], rb[6], rb[7]);
            }
            __syncthreads();
            buf = nb;
        }
    }

    if (EPI == 1) {
        // fused bias + row L2-normalize; lanes 0-15 of each half-warp cover all 128 cols
        float bkv[8];
#pragma unroll
        for (int s = 0; s < 2; s++)
#pragma unroll
            for (int j = 0; j < 4; j++) bkv[s * 4 + j] = AUX[nA + s * 64 + j];
#pragma unroll
        for (int i = 0; i < 8; i++) {
            int m = mBase + m0 + i;
            float o[8];
#pragma unroll
            for (int j = 0; j < 4; j++) unpack2(acc[i][j], o[2 * j], o[2 * j + 1]);
            float ss = 0.0f;
#pragma unroll
            for (int j = 0; j < 8; j++) {
                o[j] += bkv[j];
                ss += o[j] * o[j];
            }
#pragma unroll
            for (int d = 8; d; d >>= 1) ss += __shfl_xor_sync(0xffffffffu, ss, d, 16);
            float rn = 1.0f / fmaxf(sqrtf(ss), 1e-12f);
            if (m < M) {
                size_t off = (size_t)m * 128;
                *(float4*)(C + off + nA)      = make_float4(o[0] * rn, o[1] * rn, o[2] * rn, o[3] * rn);
                *(float4*)(C + off + nA + 64) = make_float4(o[4] * rn, o[5] * rn, o[6] * rn, o[7] * rn);
            }
        }
        return;
    }

    if (EPI == 2) {
        bool interior = (nBase + 128) <= NVALID;
#pragma unroll
        for (int i = 0; i < 8; i++) {
            int m = mBase + m0 + i;
            if (m >= M) continue;
            float o[8];
#pragma unroll
            for (int j = 0; j < 4; j++) unpack2(acc[i][j], o[2 * j], o[2 * j + 1]);
            size_t off = (size_t)g * sC + (size_t)m * ldC + nBase;
            if (interior) {
                *(float4*)(C + off + nA) = make_float4(
                    __expf(alpha * o[0]), __expf(alpha * o[1]),
                    __expf(alpha * o[2]), __expf(alpha * o[3]));
                *(float4*)(C + off + nA + 64) = make_float4(
                    __expf(alpha * o[4]), __expf(alpha * o[5]),
                    __expf(alpha * o[6]), __expf(alpha * o[7]));
            } else {
#pragma unroll
                for (int s = 0; s < 2; s++)
#pragma unroll
                    for (int j = 0; j < 4; j++) {
                        int n = nBase + nA + s * 64 + j;
                        if (n < ldC)
                            C[(size_t)g * sC + (size_t)m * ldC + n] =
                                (n < NVALID) ? __expf(alpha * o[s * 4 + j]) : 0.0f;
                    }
            }
        }
        return;
    }

    if (EPI == 3) {
#pragma unroll
        for (int i = 0; i < 8; i++) {
            int m = mBase + m0 + i;
            if (m >= M) continue;
            float rs = AUX[(size_t)g * M + m];
            float o[8];
#pragma unroll
            for (int j = 0; j < 4; j++) unpack2(acc[i][j], o[2 * j], o[2 * j + 1]);
            size_t off = (size_t)g * sC + (size_t)m * ldC + nBase;
            float4 c0 = *(const float4*)(Cin + off + nA);
            float4 c1 = *(const float4*)(Cin + off + nA + 64);
            *(float4*)(C + off + nA) = make_float4(rs * o[0] + c0.x, rs * o[1] + c0.y,
                                                   rs * o[2] + c0.z, rs * o[3] + c0.w);
            *(float4*)(C + off + nA + 64) = make_float4(rs * o[4] + c1.x, rs * o[5] + c1.y,
                                                        rs * o[6] + c1.z, rs * o[7] + c1.w);
        }
        return;
    }

    // EPI 0
    bool fullN = (nBase + 128) <= N;
#pragma unroll
    for (int i = 0; i < 8; i++) {
        int m = mBase + m0 + i;
        if (m >= M) continue;
        float o[8];
#pragma unroll
        for (int j = 0; j < 4; j++) unpack2(acc[i][j], o[2 * j], o[2 * j + 1]);
#pragma unroll
        for (int j = 0; j < 8; j++) o[j] *= alpha;
        size_t off = (size_t)g * sC + (size_t)m * ldC + nBase;
        if (fullN) {
            if (addC) {
                float4 c0 = *(const float4*)(Cin + off + nA);
                float4 c1 = *(const float4*)(Cin + off + nA + 64);
                o[0] += c0.x; o[1] += c0.y; o[2] += c0.z; o[3] += c0.w;
                o[4] += c1.x; o[5] += c1.y; o[6] += c1.z; o[7] += c1.w;
            }
            *(float4*)(C + off + nA)      = make_float4(o[0], o[1], o[2], o[3]);
            *(float4*)(C + off + nA + 64) = make_float4(o[4], o[5], o[6], o[7]);
        } else {
#pragma unroll
            for (int s = 0; s < 2; s++)
#pragma unroll
                for (int j = 0; j < 4; j++) {
                    int n = nBase + nA + s * 64 + j;
                    if (n < N) {
                        float v = o[s * 4 + j];
                        if (addC) v += Cin[off + nA + s * 64 + j];
                        C[off + nA + s * 64 + j] = v;
                    }
                }
        }
    }
}

// ================= small kernels =================
__global__ void pe_kernel(float* __restrict__ pe) {
    int idx = blockIdx.x * 256 + threadIdx.x;
    if (idx >= HW * DD) return;
    int p = idx >> 9, c = idx & 511;
    float pos = (float)(p + 1);
    int j = c & 255;
    float f = powf(10000.0f, -(float)j * (1.0f / 256.0f));
    float a = pos * f;
    pe[idx] = (c < 256) ? sinf(a) : cosf(a);
}

__global__ void label_kernel(const float* __restrict__ lab, float* __restrict__ out) {
    int idx = blockIdx.x * 256 + threadIdx.x;
    if (idx >= 3 * BB * HW) return;
    int p = idx % HW;
    int t = idx / HW;
    int b = t % BB;
    int ni = t / BB;
    out[(size_t)b * LE + ni * HW + p] = lab[idx];
}

__global__ void build_kernel(const float* __restrict__ fa, const float* __restrict__ fb,
                             int split, const float* __restrict__ pe,
                             float* __restrict__ xout, int mode) {
    int g = blockIdx.x;
    int img = g >> 4, b = g & 15;
    const float* f = (img < split) ? (fa + (size_t)img * BB * DD * HW)
                                   : (fb + (size_t)(img - split) * BB * DD * HW);
    int p0 = blockIdx.y * 32, c0 = blockIdx.z * 32;
    __shared__ float tl[32][33];
    int tx = threadIdx.x, ty = threadIdx.y;
#pragma unroll
    for (int r = 0; r < 4; r++) {
        int c = c0 + ty + r * 8, p = p0 + tx;
        if (p < HW) tl[ty + r * 8][tx] = f[((size_t)b * DD + c) * HW + p];
    }
    __syncthreads();
#pragma unroll
    for (int r = 0; r < 4; r++) {
        int p = p0 + ty + r * 8, c = c0 + tx;
        if (p < HW) {
            size_t row = (mode == 0) ? ((size_t)b * LE + (size_t)img * HW + p)
                                     : ((size_t)g * LDQ + p);
            xout[row * DD + c] = tl[tx][ty + r * 8] + pe[(size_t)p * DD + c] * 1e-3f;
        }
    }
}

// row sums of exp'd probs -> 1/sum (and mask = sum(p*label)/sum when LABEL)
__global__ void rowsum_kernel(const float* __restrict__ P, const float* __restrict__ LABEL,
                              float* __restrict__ RS, float* __restrict__ MASKOUT,
                              int Mrows, int Lk, int ld, int gkMod) {
    int q = blockIdx.x, g = blockIdx.y, t = threadIdx.x;   // 128 threads
    int gk = gkMod ? (g & 15) : g;
    const float4* p4 = (const float4*)(P + ((size_t)g * Mrows + q) * ld);
    int n4 = Lk >> 2;
    float s = 0.0f, ms = 0.0f;
    if (LABEL) {
        const float4* l4 = (const float4*)(LABEL + (size_t)gk * Lk);
        for (int i = t; i < n4; i += 128) {
            float4 v = p4[i];
            float4 lv = l4[i];
            s += v.x + v.y + v.z + v.w;
            ms += v.x * lv.x + v.y * lv.y + v.z * lv.z + v.w * lv.w;
        }
    } else {
        for (int i = t; i < n4; i += 128) {
            float4 v = p4[i];
            s += v.x + v.y + v.z + v.w;
        }
    }
    __shared__ float rs_[4], rm_[4];
#pragma unroll
    for (int m = 16; m; m >>= 1) {
        s += __shfl_xor_sync(0xffffffffu, s, m);
        ms += __shfl_xor_sync(0xffffffffu, ms, m);
    }
    if ((t & 31) == 0) { rs_[t >> 5] = s; rm_[t >> 5] = ms; }
    __syncthreads();
    if (t == 0) {
        float st = rs_[0] + rs_[1] + rs_[2] + rs_[3];
        float inv = 1.0f / st;
        RS[(size_t)g * Mrows + q] = inv;
        if (MASKOUT) {
            float mt = rm_[0] + rm_[1] + rm_[2] + rm_[3];
            MASKOUT[(size_t)g * Mrows + q] = mt * inv;
        }
    }
}

// memlab[b][k][d] = mem[b][k][d] * label[b][k]
__global__ void memlab_kernel(const float* __restrict__ mem, const float* __restrict__ label,
                              float* __restrict__ ml) {
    int i = blockIdx.x * 256 + threadIdx.x;   // float4 index
    if (i >= (int)(SZ_MEMLAB / 4)) return;
    float lb = label[i >> 7];
    float4 v = ((const float4*)mem)[i];
    v.x *= lb; v.y *= lb; v.z *= lb; v.w *= lb;
    ((float4*)ml)[i] = v;
}

// InstanceL2Norm: partial sums then apply (deterministic 2-stage)
__global__ void inorm_part(const float* __restrict__ in, float* __restrict__ part) {
    int g = blockIdx.x, q = blockIdx.y, t = threadIdx.x;
    const float4* ip = (const float4*)(in + (size_t)g * GRP) + (size_t)q * QF4;
    float ss = 0.0f;
    for (int i = t; i < QF4; i += 256) {
        float4 v = ip[i];
        ss += v.x * v.x + v.y * v.y + v.z * v.z + v.w * v.w;
    }
    __shared__ float red[8];
#pragma unroll
    for (int m = 16; m; m >>= 1) ss += __shfl_xor_sync(0xffffffffu, ss, m);
    if ((t & 31) == 0) red[t >> 5] = ss;
    __syncthreads();
    if (t == 0) {
        float s = 0.0f;
#pragma unroll
        for (int i = 0; i < 8; i++) s += red[i];
        part[g * 4 + q] = s;
    }
}

__global__ void inorm_apply(const float* __restrict__ in, float* __restrict__ out,
                            const float* __restrict__ part) {
    int g = blockIdx.x, q = blockIdx.y, t = threadIdx.x;
    float ss = part[g * 4 + 0] + part[g * 4 + 1] + part[g * 4 + 2] + part[g * 4 + 3];
    float sc = NSCALE * sqrtf(DHWF / (ss + IEPS));
    const float4* ip = (const float4*)(in + (size_t)g * GRP) + (size_t)q * QF4;
    float4* op = (float4*)(out + (size_t)g * GRP) + (size_t)q * QF4;
    for (int i = t; i < QF4; i += 256) {
        float4 v = ip[i];
        v.x *= sc; v.y *= sc; v.z *= sc; v.w *= sc;
        op[i] = v;
    }
}

// decoder 3-sum partials: u = x*mask, v = x + t3
__global__ void dec_part_kernel(const float* __restrict__ X, const float* __restrict__ XP,
                                const float* __restrict__ MASK, float* __restrict__ part) {
    int g = blockIdx.x, q = blockIdx.y, t = threadIdx.x;
    const float4* x4 = (const float4*)(X + (size_t)g * GRP);
    const float4* p4 = (const float4*)(XP + (size_t)g * GRP);
    const float* mk = MASK + (size_t)g * LDQ;
    float s2 = 0.0f, s4 = 0.0f, cr = 0.0f;
    for (int i = t; i < QF4; i += 256) {
        int gi = q * QF4 + i;
        float m = mk[gi >> 7];
        float4 x = x4[gi];
        float4 v = p4[gi];
        float ux = x.x * m, uy = x.y * m, uz = x.z * m, uw = x.w * m;
        s2 += ux * ux + uy * uy + uz * uz + uw * uw;
        s4 += v.x * v.x + v.y * v.y + v.z * v.z + v.w * v.w;
        cr += ux * v.x + uy * v.y + uz * v.z + uw * v.w;
    }
    __shared__ float r2[8], r4[8], rc[8];
#pragma unroll
    for (int m = 16; m; m >>= 1) {
        s2 += __shfl_xor_sync(0xffffffffu, s2, m);
        s4 += __shfl_xor_sync(0xffffffffu, s4, m);
        cr += __shfl_xor_sync(0xffffffffu, cr, m);
    }
    if ((t & 31) == 0) { r2[t >> 5] = s2; r4[t >> 5] = s4; rc[t >> 5] = cr; }
    __syncthreads();
    if (t == 0) {
        float a = 0, b = 0, c = 0;
#pragma unroll
        for (int i = 0; i < 8; i++) { a += r2[i]; b += r4[i]; c += rc[i]; }
        part[(g * 4 + q) * 3 + 0] = a;
        part[(g * 4 + q) * 3 + 1] = b;
        part[(g * 4 + q) * 3 + 2] = c;
    }
}

__global__ void dec_scale_kernel(const float* __restrict__ part, float* __restrict__ SC) {
    int g = threadIdx.x;
    if (g >= 96) return;
    float a = 0, b = 0, c = 0;
#pragma unroll
    for (int q = 0; q < 4; q++) {
        a += part[(g * 4 + q) * 3 + 0];
        b += part[(g * 4 + q) * 3 + 1];
        c += part[(g * 4 + q) * 3 + 2];
    }
    float S2 = NSCALE * sqrtf(DHWF / (a + IEPS));
    float S4 = NSCALE * sqrtf(DHWF / (b + IEPS));
    float sso = S2 * S2 * a + 2.0f * S2 * S4 * c + S4 * S4 * b;
    float SO = NSCALE * sqrtf(DHWF / (sso + IEPS));
    SC[g * 4 + 0] = S2;
    SC[g * 4 + 1] = S4;
    SC[g * 4 + 2] = SO;
}

__global__ void final_kernel(const float* __restrict__ X, const float* __restrict__ XP,
                             const float* __restrict__ MASK, const float* __restrict__ SC,
                             float* __restrict__ out) {
    int g = blockIdx.x;
    float S2 = SC[g * 4 + 0], S4 = SC[g * 4 + 1], SO = SC[g * 4 + 2];
    int p0 = blockIdx.y * 32, c0 = blockIdx.z * 32;
    __shared__ float tile[32][33];
    int tx = threadIdx.x, ty = threadIdx.y;
    size_t base = (size_t)g * GRP;
#pragma unroll
    for (int r = 0; r < 4; r++) {
        int p = p0 + ty + r * 8, c = c0 + tx;
        if (p < LDQ) {
            size_t idx = base + (size_t)p * 512 + c;
            float u = X[idx] * MASK[(size_t)g * LDQ + p];
            tile[ty + r * 8][tx] = SO * (S2 * u + S4 * XP[idx]);
        }
    }
    __syncthreads();
#pragma unroll
    for (int r = 0; r < 4; r++) {
        int p = p0 + tx, c = c0 + ty + r * 8;
        if (p < LDQ) out[((size_t)g * 512 + c) * LDQ + p] = tile[tx][ty + r * 8];
    }
}

// ================= launcher =================
extern "C" void kernel_launch(void* const* d_in, const int* in_sizes, int n_in,
                              void* d_out, int out_size) {
    const float* train_feat  = (const float*)d_in[0];
    const float* test_feat   = (const float*)d_in[1];
    const float* train_label = (const float*)d_in[2];
    const float* wk_self     = (const float*)d_in[3];
    const float* bk_self     = (const float*)d_in[4];
    const float* wk_cross    = (const float*)d_in[5];
    const float* bk_cross    = (const float*)d_in[6];
    float* out = (float*)d_out;

    float* base = nullptr;
    cudaGetSymbolAddress((void**)&base, g_scratch);
    float* pe     = base + OFF_PE;
    float* label  = base + OFF_LABEL;
    float* xe     = base + OFF_XE;
    float* x1e    = base + OFF_X1E;
    float* mem    = base + OFF_MEM;
    float* pq     = base + OFF_PQ;
    float* pkc    = base + OFF_PKC;
    float* dx0    = base + OFF_DX0;
    float* dx1    = base + OFF_DX1;
    float* dx     = base + OFF_DX;
    float* dxpt3  = base + OFF_DXPT3;
    float* dpq    = base + OFF_DPQ;
    float* dmask  = base + OFF_DMASK;
    float* dsc    = base + OFF_DSC;
    float* ipart  = base + OFF_IPART;
    float* dpart  = base + OFF_DPART;
    float* memlab = base + OFF_MEMLAB;
    float* rsum   = base + OFF_RSUM;
    float* probs  = base + OFF_PROBS;

    dim3 tb(32, 8);

    pe_kernel<<<(HW * DD + 255) / 256, 256>>>(pe);
    label_kernel<<<(3 * BB * HW + 255) / 256, 256>>>(train_label, label);

    // ---- encoder ----
    build_kernel<<<dim3(48, 16, 16), tb>>>(train_feat, train_feat, 3, pe, xe, 0);
    gemm_kernel<1, 1><<<dim3(1, (16 * LE + 127) / 128, 1), 256>>>(
        xe, wk_self, nullptr, pq, bk_self, 16 * LE, 128, 512, 512,
        512, 512, 128, 0, 0, 0, 0, 1.0f, 0, 128);
    gemm_kernel<1, 2><<<dim3(12, (LE + 127) / 128, 16), 256>>>(
        pq, pq, nullptr, probs, nullptr, LE, LE, 128, 128,
        128, 128, 1456, (size_t)LE * 128, (size_t)LE * 128, (size_t)LE * 1456,
        0, 30.0f, 0, LE);
    rowsum_kernel<<<dim3(LE, 16), 128>>>(probs, nullptr, rsum, nullptr, LE, 1456, 1456, 0);
    gemm_kernel<0, 3><<<dim3(4, (LE + 127) / 128, 16), 256>>>(
        probs, xe, xe, x1e, rsum, LE, 512, 1456, LE,
        1456, 512, 512, (size_t)LE * 1456, (size_t)LE * 512, (size_t)LE * 512,
        0, 1.0f, 1, 512);
    inorm_part<<<dim3(48, 4), 256>>>(x1e, ipart);
    inorm_apply<<<dim3(48, 4), 256>>>(x1e, mem, ipart);
    gemm_kernel<1, 1><<<dim3(1, (16 * LE + 127) / 128, 1), 256>>>(
        mem, wk_cross, nullptr, pkc, bk_cross, 16 * LE, 128, 512, 512,
        512, 512, 128, 0, 0, 0, 0, 1.0f, 0, 128);
    memlab_kernel<<<((int)(SZ_MEMLAB / 4) + 255) / 256, 256>>>(mem, label, memlab);

    // ---- decoder (96 batched) ----
    build_kernel<<<dim3(96, 16, 16), tb>>>(train_feat, test_feat, 3, pe, dx0, 1);
    gemm_kernel<1, 1><<<dim3(1, (96 * LDQ + 127) / 128, 1), 256>>>(
        dx0, wk_self, nullptr, dpq, bk_self, 96 * LDQ, 128, 512, 512,
        512, 512, 128, 0, 0, 0, 0, 1.0f, 0, 128);
    gemm_kernel<1, 2><<<dim3(4, (LDQ + 127) / 128, 96), 256>>>(
        dpq, dpq, nullptr, probs, nullptr, LDQ, LDQ, 128, 128,
        128, 128, 496, (size_t)LDQ * 128, (size_t)LDQ * 128, (size_t)LDQ * 496,
        0, 30.0f, 0, LDQ);
    rowsum_kernel<<<dim3(LDQ, 96), 128>>>(probs, nullptr, rsum, nullptr, LDQ, 496, 496, 0);
    gemm_kernel<0, 3><<<dim3(4, (LDQ + 127) / 128, 96), 256>>>(
        probs, dx0, dx0, dx1, rsum, LDQ, 512, 496, LDQ,
        496, 512, 512, (size_t)LDQ * 496, (size_t)LDQ * 512, (size_t)LDQ * 512,
        0, 1.0f, 1, 512);
    inorm_part<<<dim3(96, 4), 256>>>(dx1, ipart);
    inorm_apply<<<dim3(96, 4), 256>>>(dx1, dx, ipart);
    gemm_kernel<1, 1><<<dim3(1, (96 * LDQ + 127) / 128, 1), 256>>>(
        dx, wk_cross, nullptr, dpq, bk_cross, 96 * LDQ, 128, 512, 512,
        512, 512, 128, 0, 0, 0, 0, 1.0f, 0, 128);
    gemm_kernel<1, 2><<<dim3(12, (LDQ + 127) / 128, 96), 256>>>(
        dpq, pkc, nullptr, probs, nullptr, LDQ, LE, 128, 128,
        128, 128, 1456, (size_t)LDQ * 128, (size_t)LE * 128, (size_t)LDQ * 1456,
        1, 30.0f, 0, LE);
    rowsum_kernel<<<dim3(LDQ, 96), 128>>>(probs, label, rsum, dmask, LDQ, LE, 1456, 1);
    gemm_kernel<0, 3><<<dim3(4, (LDQ + 127) / 128, 96), 256>>>(
        probs, memlab, dx, dxpt3, rsum, LDQ, 512, 1456, LE,
        1456, 512, 512, (size_t)LDQ * 1456, (size_t)LE * 512, (size_t)LDQ * 512,
        1, 1.0f, 1, 512);
    dec_part_kernel<<<dim3(96, 4), 256>>>(dx, dxpt3, dmask, dpart);
    dec_scale_kernel<<<1, 96>>>(dpart, dsc);
    final_kernel<<<dim3(96, 16, 16), tb>>>(dx, dxpt3, dmask, dsc, out);
}

// round 9
// speedup vs baseline: 1.6153x; 1.0084x over previous
#include <cuda_runtime.h>
#include <math.h>
#include <stdint.h>

typedef unsigned long long u64;

#define BB 16
#define DD 512
#define HW 484
#define LE 1452
#define LDQ 484
#define NSCALE 0.011048543456039806f
#define DHWF 247808.0f
#define IEPS 1e-5f
#define GRP 247808
#define QF4 15488   // GRP/4/4 : float4s per quarter

// ---- scratch layout (floats) ----
#define SZ_PE     ((size_t)HW*DD)
#define SZ_LABEL  ((size_t)BB*LE)
#define SZ_XE     ((size_t)BB*LE*DD)
#define SZ_PQ     ((size_t)BB*LE*128)
#define SZ_DX     ((size_t)96*LDQ*DD)
#define SZ_DPQ    ((size_t)96*LDQ*128)
#define SZ_DMASK  ((size_t)96*LDQ)
#define SZ_PROBS  ((size_t)96*LDQ*1456)
#define SZ_MEMLAB ((size_t)BB*LE*DD)
#define SZ_RSUM   ((size_t)96*LDQ)

#define OFF_PE    ((size_t)0)
#define OFF_LABEL (OFF_PE + SZ_PE)
#define OFF_XE    (OFF_LABEL + SZ_LABEL)
#define OFF_X1E   (OFF_XE + SZ_XE)
#define OFF_MEM   (OFF_X1E + SZ_XE)
#define OFF_PQ    (OFF_MEM + SZ_XE)
#define OFF_PKC   (OFF_PQ + SZ_PQ)
#define OFF_DX0   (OFF_PKC + SZ_PQ)
#define OFF_DX1   (OFF_DX0 + SZ_DX)
#define OFF_DX    (OFF_DX1 + SZ_DX)
#define OFF_DXPT3 (OFF_DX + SZ_DX)
#define OFF_DPQ   (OFF_DXPT3 + SZ_DX)
#define OFF_DMASK (OFF_DPQ + SZ_DPQ)
#define OFF_DSC   (OFF_DMASK + SZ_DMASK)
#define OFF_IPART (OFF_DSC + 96*4)
#define OFF_DPART (OFF_IPART + 96*4)
#define OFF_MEMLAB (OFF_DPART + 96*4*3)
#define OFF_RSUM  (OFF_MEMLAB + SZ_MEMLAB)
#define OFF_PROBS (OFF_RSUM + SZ_RSUM)
#define SCRATCH_TOTAL (OFF_PROBS + SZ_PROBS)

__device__ __align__(16) float g_scratch[SCRATCH_TOTAL];

// ---- f32x2 helpers ----
__device__ __forceinline__ u64 ffma2(u64 a, u64 b, u64 c) {
    u64 d;
    asm("fma.rn.f32x2 %0, %1, %2, %3;" : "=l"(d) : "l"(a), "l"(b), "l"(c));
    return d;
}
__device__ __forceinline__ u64 pack2(float lo, float hi) {
    u64 r;
    asm("mov.b64 %0, {%1, %2};" : "=l"(r) : "f"(lo), "f"(hi));
    return r;
}
__device__ __forceinline__ void unpack2(u64 v, float& lo, float& hi) {
    asm("mov.b64 {%0, %1}, %2;" : "=f"(lo), "=f"(hi) : "l"(v));
}

__device__ __forceinline__ void ld8(const float* p, bool valid, float* r) {
    if (valid) {
        float4 v0 = *(const float4*)p;
        float4 v1 = *(const float4*)(p + 4);
        r[0] = v0.x; r[1] = v0.y; r[2] = v0.z; r[3] = v0.w;
        r[4] = v1.x; r[5] = v1.y; r[6] = v1.z; r[7] = v1.w;
    } else {
#pragma unroll
        for (int j = 0; j < 8; j++) r[j] = 0.0f;
    }
}

// ============ generic batched GEMM, 128x128 tile, double-buffered ============
// Thread's 8 N-columns split into two 4-wide segments 64 apart (bank-conflict
// free). Inner kk loop software-pipelines smem operand loads one step ahead.
// C[g] = f( A[g] @ op(B[gk]) );  op = B^T if TRANSB (B is [N][K]).
// EPI 0: alpha*acc (+Cin)
// EPI 1: bias(AUX) + row L2-normalize  (proj; N==128, G==1)
// EPI 2: exp(alpha*acc) for n<NVALID else 0  (logits; ldC = padded width)
// EPI 3: AUX[g*M+m]*acc + Cin          (value with row 1/sum scale)
template<int TRANSB, int EPI>
__global__ void __launch_bounds__(256, 2)
gemm_kernel(const float* __restrict__ A, const float* __restrict__ B,
            const float* __restrict__ Cin, float* __restrict__ C,
            const float* __restrict__ AUX,
            int M, int N, int Kloop, int KB,
            int ldA, int ldB, int ldC,
            size_t sA, size_t sB, size_t sC,
            int gkMod, float alpha, int addC, int NVALID) {
    __shared__ float As[2][16][132];
    __shared__ float Bs[2][16][132];
    int g = blockIdx.z;
    int gk = gkMod ? (g & 15) : g;
    const float* Ag = A + (size_t)g * sA;
    const float* Bg = B + (size_t)gk * sB;
    int mBase = blockIdx.y * 128, nBase = blockIdx.x * 128;
    int t = threadIdx.x;

    int am = t >> 1, ak = (t & 1) * 8;
    bool avalid = (mBase + am) < M;
    const float* aPtr = Ag + (size_t)(mBase + am) * ldA + ak;

    int bn = t >> 1, bk = (t & 1) * 8;       // TRANSB path
    int bk2 = t >> 4, bnq = (t & 15) * 8;    // NN path
    bool bnvalid = (nBase + bn) < N;
    const float* bPtrT = Bg + (size_t)(nBase + bn) * ldB + bk;
    const float* bPtrN = Bg + (size_t)bk2 * ldB + nBase + bnq;

    float ra[8], rb[8];
    ld8(aPtr, avalid, ra);
    if (TRANSB) ld8(bPtrT, bnvalid, rb);
    else        ld8(bPtrN, bk2 < KB, rb);

#pragma unroll
    for (int j = 0; j < 8; j++) As[0][ak + j][am] = ra[j];
    if (TRANSB) {
#pragma unroll
        for (int j = 0; j < 8; j++) Bs[0][bk + j][bn] = rb[j];
    } else {
        *(float4*)&Bs[0][bk2][bnq]     = make_float4(rb[0], rb[1], rb[2], rb[3]);
        *(float4*)&Bs[0][bk2][bnq + 4] = make_float4(rb[4], rb[5], rb[6], rb[7]);
    }
    __syncthreads();

    u64 acc[8][4];   // [mi][2*seg + pair]
#pragma unroll
    for (int i = 0; i < 8; i++)
#pragma unroll
        for (int j = 0; j < 4; j++) acc[i][j] = 0ull;

    int m0 = (t >> 4) * 8;
    int nA = (t & 15) * 4;       // segment 0 base; segment 1 at nA + 64
    int buf = 0;

    for (int k0 = 0; k0 < Kloop; k0 += 16) {
        int kn = k0 + 16;
        bool more = kn < Kloop;
        if (more) {
            ld8(aPtr + kn, avalid, ra);
            if (TRANSB) ld8(bPtrT + kn, bnvalid, rb);
            else        ld8(bPtrN + (size_t)kn * ldB, (kn + bk2) < KB, rb);
        }
        // software-pipelined operand fetch: stage kk+1 loads before kk math
        ulonglong2 pbA[2], pbB[2];
        float4 pa0[2], pa1[2];
        pbA[0] = *(const ulonglong2*)&Bs[buf][0][nA];
        pbB[0] = *(const ulonglong2*)&Bs[buf][0][nA + 64];
        pa0[0] = *(const float4*)&As[buf][0][m0];
        pa1[0] = *(const float4*)&As[buf][0][m0 + 4];
#pragma unroll
        for (int kk = 0; kk < 16; kk++) {
            int cur = kk & 1, nxt = cur ^ 1;
            if (kk < 15) {
                pbA[nxt] = *(const ulonglong2*)&Bs[buf][kk + 1][nA];
                pbB[nxt] = *(const ulonglong2*)&Bs[buf][kk + 1][nA + 64];
                pa0[nxt] = *(const float4*)&As[buf][kk + 1][m0];
                pa1[nxt] = *(const float4*)&As[buf][kk + 1][m0 + 4];
            }
            float av[8] = {pa0[cur].x, pa0[cur].y, pa0[cur].z, pa0[cur].w,
                           pa1[cur].x, pa1[cur].y, pa1[cur].z, pa1[cur].w};
#pragma unroll
            for (int i = 0; i < 8; i++) {
                u64 ad = pack2(av[i], av[i]);
                acc[i][0] = ffma2(ad, pbA[cur].x, acc[i][0]);
                acc[i][1] = ffma2(ad, pbA[cur].y, acc[i][1]);
                acc[i][2] = ffma2(ad, pbB[cur].x, acc[i][2]);
                acc[i][3] = ffma2(ad, pbB[cur].y, acc[i][3]);
            }
        }
        if (more) {
            int nb = buf ^ 1;
#pragma unroll
            for (int j = 0; j < 8; j++) As[nb][ak + j][am] = ra[j];
            if (TRANSB) {
#pragma unroll
                for (int j = 0; j < 8; j++) Bs[nb][bk + j][bn] = rb[j];
            } else {
                *(float4*)&Bs[nb][bk2][bnq]     = make_float4(rb[0], rb[1], rb[2], rb[3]);
                *(float4*)&Bs[nb][bk2][bnq + 4] = make_float4(rb[4], rb[5], rb[6], rb[7]);
            }
            __syncthreads();
            buf = nb;
        }
    }

    if (EPI == 1) {
        float bkv[8];
#pragma unroll
        for (int s = 0; s < 2; s++)
#pragma unroll
            for (int j = 0; j < 4; j++) bkv[s * 4 + j] = AUX[nA + s * 64 + j];
#pragma unroll
        for (int i = 0; i < 8; i++) {
            int m = mBase + m0 + i;
            float o[8];
#pragma unroll
            for (int j = 0; j < 4; j++) unpack2(acc[i][j], o[2 * j], o[2 * j + 1]);
            float ss = 0.0f;
#pragma unroll
            for (int j = 0; j < 8; j++) {
                o[j] += bkv[j];
                ss += o[j] * o[j];
            }
#pragma unroll
            for (int d = 8; d; d >>= 1) ss += __shfl_xor_sync(0xffffffffu, ss, d, 16);
            float rn = 1.0f / fmaxf(sqrtf(ss), 1e-12f);
            if (m < M) {
                size_t off = (size_t)m * 128;
                *(float4*)(C + off + nA)      = make_float4(o[0] * rn, o[1] * rn, o[2] * rn, o[3] * rn);
                *(float4*)(C + off + nA + 64) = make_float4(o[4] * rn, o[5] * rn, o[6] * rn, o[7] * rn);
            }
        }
        return;
    }

    if (EPI == 2) {
        bool interior = (nBase + 128) <= NVALID;
#pragma unroll
        for (int i = 0; i < 8; i++) {
            int m = mBase + m0 + i;
            if (m >= M) continue;
            float o[8];
#pragma unroll
            for (int j = 0; j < 4; j++) unpack2(acc[i][j], o[2 * j], o[2 * j + 1]);
            size_t off = (size_t)g * sC + (size_t)m * ldC + nBase;
            if (interior) {
                *(float4*)(C + off + nA) = make_float4(
                    __expf(alpha * o[0]), __expf(alpha * o[1]),
                    __expf(alpha * o[2]), __expf(alpha * o[3]));
                *(float4*)(C + off + nA + 64) = make_float4(
                    __expf(alpha * o[4]), __expf(alpha * o[5]),
                    __expf(alpha * o[6]), __expf(alpha * o[7]));
            } else {
#pragma unroll
                for (int s = 0; s < 2; s++)
#pragma unroll
                    for (int j = 0; j < 4; j++) {
                        int n = nBase + nA + s * 64 + j;
                        if (n < ldC)
                            C[(size_t)g * sC + (size_t)m * ldC + n] =
                                (n < NVALID) ? __expf(alpha * o[s * 4 + j]) : 0.0f;
                    }
            }
        }
        return;
    }

    if (EPI == 3) {
#pragma unroll
        for (int i = 0; i < 8; i++) {
            int m = mBase + m0 + i;
            if (m >= M) continue;
            float rs = AUX[(size_t)g * M + m];
            float o[8];
#pragma unroll
            for (int j = 0; j < 4; j++) unpack2(acc[i][j], o[2 * j], o[2 * j + 1]);
            size_t off = (size_t)g * sC + (size_t)m * ldC + nBase;
            float4 c0 = *(const float4*)(Cin + off + nA);
            float4 c1 = *(const float4*)(Cin + off + nA + 64);
            *(float4*)(C + off + nA) = make_float4(rs * o[0] + c0.x, rs * o[1] + c0.y,
                                                   rs * o[2] + c0.z, rs * o[3] + c0.w);
            *(float4*)(C + off + nA + 64) = make_float4(rs * o[4] + c1.x, rs * o[5] + c1.y,
                                                        rs * o[6] + c1.z, rs * o[7] + c1.w);
        }
        return;
    }

    // EPI 0
    bool fullN = (nBase + 128) <= N;
#pragma unroll
    for (int i = 0; i < 8; i++) {
        int m = mBase + m0 + i;
        if (m >= M) continue;
        float o[8];
#pragma unroll
        for (int j = 0; j < 4; j++) unpack2(acc[i][j], o[2 * j], o[2 * j + 1]);
#pragma unroll
        for (int j = 0; j < 8; j++) o[j] *= alpha;
        size_t off = (size_t)g * sC + (size_t)m * ldC + nBase;
        if (fullN) {
            if (addC) {
                float4 c0 = *(const float4*)(Cin + off + nA);
                float4 c1 = *(const float4*)(Cin + off + nA + 64);
                o[0] += c0.x; o[1] += c0.y; o[2] += c0.z; o[3] += c0.w;
                o[4] += c1.x; o[5] += c1.y; o[6] += c1.z; o[7] += c1.w;
            }
            *(float4*)(C + off + nA)      = make_float4(o[0], o[1], o[2], o[3]);
            *(float4*)(C + off + nA + 64) = make_float4(o[4], o[5], o[6], o[7]);
        } else {
#pragma unroll
            for (int s = 0; s < 2; s++)
#pragma unroll
                for (int j = 0; j < 4; j++) {
                    int n = nBase + nA + s * 64 + j;
                    if (n < N) {
                        float v = o[s * 4 + j];
                        if (addC) v += Cin[off + nA + s * 64 + j];
                        C[off + nA + s * 64 + j] = v;
                    }
                }
        }
    }
}

// ================= small kernels =================
__global__ void pe_kernel(float* __restrict__ pe) {
    int idx = blockIdx.x * 256 + threadIdx.x;
    if (idx >= HW * DD) return;
    int p = idx >> 9, c = idx & 511;
    float pos = (float)(p + 1);
    int j = c & 255;
    float f = powf(10000.0f, -(float)j * (1.0f / 256.0f));
    float a = pos * f;
    pe[idx] = (c < 256) ? sinf(a) : cosf(a);
}

__global__ void label_kernel(const float* __restrict__ lab, float* __restrict__ out) {
    int idx = blockIdx.x * 256 + threadIdx.x;
    if (idx >= 3 * BB * HW) return;
    int p = idx % HW;
    int t = idx / HW;
    int b = t % BB;
    int ni = t / BB;
    out[(size_t)b * LE + ni * HW + p] = lab[idx];
}

__global__ void build_kernel(const float* __restrict__ fa, const float* __restrict__ fb,
                             int split, const float* __restrict__ pe,
                             float* __restrict__ xout, int mode) {
    int g = blockIdx.x;
    int img = g >> 4, b = g & 15;
    const float* f = (img < split) ? (fa + (size_t)img * BB * DD * HW)
                                   : (fb + (size_t)(img - split) * BB * DD * HW);
    int p0 = blockIdx.y * 32, c0 = blockIdx.z * 32;
    __shared__ float tl[32][33];
    int tx = threadIdx.x, ty = threadIdx.y;
#pragma unroll
    for (int r = 0; r < 4; r++) {
        int c = c0 + ty + r * 8, p = p0 + tx;
        if (p < HW) tl[ty + r * 8][tx] = f[((size_t)b * DD + c) * HW + p];
    }
    __syncthreads();
#pragma unroll
    for (int r = 0; r < 4; r++) {
        int p = p0 + ty + r * 8, c = c0 + tx;
        if (p < HW) {
            size_t row = (mode == 0) ? ((size_t)b * LE + (size_t)img * HW + p)
                                     : ((size_t)g * LDQ + p);
            xout[row * DD + c] = tl[tx][ty + r * 8] + pe[(size_t)p * DD + c] * 1e-3f;
        }
    }
}

// row sums of exp'd probs -> 1/sum (and mask = sum(p*label)/sum when LABEL)
__global__ void rowsum_kernel(const float* __restrict__ P, const float* __restrict__ LABEL,
                              float* __restrict__ RS, float* __restrict__ MASKOUT,
                              int Mrows, int Lk, int ld, int gkMod) {
    int q = blockIdx.x, g = blockIdx.y, t = threadIdx.x;   // 128 threads
    int gk = gkMod ? (g & 15) : g;
    const float4* p4 = (const float4*)(P + ((size_t)g * Mrows + q) * ld);
    int n4 = Lk >> 2;
    float s = 0.0f, ms = 0.0f;
    if (LABEL) {
        const float4* l4 = (const float4*)(LABEL + (size_t)gk * Lk);
        for (int i = t; i < n4; i += 128) {
            float4 v = p4[i];
            float4 lv = l4[i];
            s += v.x + v.y + v.z + v.w;
            ms += v.x * lv.x + v.y * lv.y + v.z * lv.z + v.w * lv.w;
        }
    } else {
        for (int i = t; i < n4; i += 128) {
            float4 v = p4[i];
            s += v.x + v.y + v.z + v.w;
        }
    }
    __shared__ float rs_[4], rm_[4];
#pragma unroll
    for (int m = 16; m; m >>= 1) {
        s += __shfl_xor_sync(0xffffffffu, s, m);
        ms += __shfl_xor_sync(0xffffffffu, ms, m);
    }
    if ((t & 31) == 0) { rs_[t >> 5] = s; rm_[t >> 5] = ms; }
    __syncthreads();
    if (t == 0) {
        float st = rs_[0] + rs_[1] + rs_[2] + rs_[3];
        float inv = 1.0f / st;
        RS[(size_t)g * Mrows + q] = inv;
        if (MASKOUT) {
            float mt = rm_[0] + rm_[1] + rm_[2] + rm_[3];
            MASKOUT[(size_t)g * Mrows + q] = mt * inv;
        }
    }
}

// memlab[b][k][d] = mem[b][k][d] * label[b][k]
__global__ void memlab_kernel(const float* __restrict__ mem, const float* __restrict__ label,
                              float* __restrict__ ml) {
    int i = blockIdx.x * 256 + threadIdx.x;   // float4 index
    if (i >= (int)(SZ_MEMLAB / 4)) return;
    float lb = label[i >> 7];
    float4 v = ((const float4*)mem)[i];
    v.x *= lb; v.y *= lb; v.z *= lb; v.w *= lb;
    ((float4*)ml)[i] = v;
}

// InstanceL2Norm: partial sums then apply (deterministic 2-stage)
__global__ void inorm_part(const float* __restrict__ in, float* __restrict__ part) {
    int g = blockIdx.x, q = blockIdx.y, t = threadIdx.x;
    const float4* ip = (const float4*)(in + (size_t)g * GRP) + (size_t)q * QF4;
    float ss = 0.0f;
    for (int i = t; i < QF4; i += 256) {
        float4 v = ip[i];
        ss += v.x * v.x + v.y * v.y + v.z * v.z + v.w * v.w;
    }
    __shared__ float red[8];
#pragma unroll
    for (int m = 16; m; m >>= 1) ss += __shfl_xor_sync(0xffffffffu, ss, m);
    if ((t & 31) == 0) red[t >> 5] = ss;
    __syncthreads();
    if (t == 0) {
        float s = 0.0f;
#pragma unroll
        for (int i = 0; i < 8; i++) s += red[i];
        part[g * 4 + q] = s;
    }
}

__global__ void inorm_apply(const float* __restrict__ in, float* __restrict__ out,
                            const float* __restrict__ part) {
    int g = blockIdx.x, q = blockIdx.y, t = threadIdx.x;
    float ss = part[g * 4 + 0] + part[g * 4 + 1] + part[g * 4 + 2] + part[g * 4 + 3];
    float sc = NSCALE * sqrtf(DHWF / (ss + IEPS));
    const float4* ip = (const float4*)(in + (size_t)g * GRP) + (size_t)q * QF4;
    float4* op = (float4*)(out + (size_t)g * GRP) + (size_t)q * QF4;
    for (int i = t; i < QF4; i += 256) {
        float4 v = ip[i];
        v.x *= sc; v.y *= sc; v.z *= sc; v.w *= sc;
        op[i] = v;
    }
}

// decoder 3-sum partials: u = x*mask, v = x + t3
__global__ void dec_part_kernel(const float* __restrict__ X, const float* __restrict__ XP,
                                const float* __restrict__ MASK, float* __restrict__ part) {
    int g = blockIdx.x, q = blockIdx.y, t = threadIdx.x;
    const float4* x4 = (const float4*)(X + (size_t)g * GRP);
    const float4* p4 = (const float4*)(XP + (size_t)g * GRP);
    const float* mk = MASK + (size_t)g * LDQ;
    float s2 = 0.0f, s4 = 0.0f, cr = 0.0f;
    for (int i = t; i < QF4; i += 256) {
        int gi = q * QF4 + i;
        float m = mk[gi >> 7];
        float4 x = x4[gi];
        float4 v = p4[gi];
        float ux = x.x * m, uy = x.y * m, uz = x.z * m, uw = x.w * m;
        s2 += ux * ux + uy * uy + uz * uz + uw * uw;
        s4 += v.x * v.x + v.y * v.y + v.z * v.z + v.w * v.w;
        cr += ux * v.x + uy * v.y + uz * v.z + uw * v.w;
    }
    __shared__ float r2[8], r4[8], rc[8];
#pragma unroll
    for (int m = 16; m; m >>= 1) {
        s2 += __shfl_xor_sync(0xffffffffu, s2, m);
        s4 += __shfl_xor_sync(0xffffffffu, s4, m);
        cr += __shfl_xor_sync(0xffffffffu, cr, m);
    }
    if ((t & 31) == 0) { r2[t >> 5] = s2; r4[t >> 5] = s4; rc[t >> 5] = cr; }
    __syncthreads();
    if (t == 0) {
        float a = 0, b = 0, c = 0;
#pragma unroll
        for (int i = 0; i < 8; i++) { a += r2[i]; b += r4[i]; c += rc[i]; }
        part[(g * 4 + q) * 3 + 0] = a;
        part[(g * 4 + q) * 3 + 1] = b;
        part[(g * 4 + q) * 3 + 2] = c;
    }
}

__global__ void dec_scale_kernel(const float* __restrict__ part, float* __restrict__ SC) {
    int g = threadIdx.x;
    if (g >= 96) return;
    float a = 0, b = 0, c = 0;
#pragma unroll
    for (int q = 0; q < 4; q++) {
        a += part[(g * 4 + q) * 3 + 0];
        b += part[(g * 4 + q) * 3 + 1];
        c += part[(g * 4 + q) * 3 + 2];
    }
    float S2 = NSCALE * sqrtf(DHWF / (a + IEPS));
    float S4 = NSCALE * sqrtf(DHWF / (b + IEPS));
    float sso = S2 * S2 * a + 2.0f * S2 * S4 * c + S4 * S4 * b;
    float SO = NSCALE * sqrtf(DHWF / (sso + IEPS));
    SC[g * 4 + 0] = S2;
    SC[g * 4 + 1] = S4;
    SC[g * 4 + 2] = SO;
}

__global__ void final_kernel(const float* __restrict__ X, const float* __restrict__ XP,
                             const float* __restrict__ MASK, const float* __restrict__ SC,
                             float* __restrict__ out) {
    int g = blockIdx.x;
    float S2 = SC[g * 4 + 0], S4 = SC[g * 4 + 1], SO = SC[g * 4 + 2];
    int p0 = blockIdx.y * 32, c0 = blockIdx.z * 32;
    __shared__ float tile[32][33];
    int tx = threadIdx.x, ty = threadIdx.y;
    size_t base = (size_t)g * GRP;
#pragma unroll
    for (int r = 0; r < 4; r++) {
        int p = p0 + ty + r * 8, c = c0 + tx;
        if (p < LDQ) {
            size_t idx = base + (size_t)p * 512 + c;
            float u = X[idx] * MASK[(size_t)g * LDQ + p];
            tile[ty + r * 8][tx] = SO * (S2 * u + S4 * XP[idx]);
        }
    }
    __syncthreads();
#pragma unroll
    for (int r = 0; r < 4; r++) {
        int p = p0 + tx, c = c0 + ty + r * 8;
        if (p < LDQ) out[((size_t)g * 512 + c) * LDQ + p] = tile[tx][ty + r * 8];
    }
}

// ================= launcher =================
extern "C" void kernel_launch(void* const* d_in, const int* in_sizes, int n_in,
                              void* d_out, int out_size) {
    const float* train_feat  = (const float*)d_in[0];
    const float* test_feat   = (const float*)d_in[1];
    const float* train_label = (const float*)d_in[2];
    const float* wk_self     = (const float*)d_in[3];
    const float* bk_self     = (const float*)d_in[4];
    const float* wk_cross    = (const float*)d_in[5];
    const float* bk_cross    = (const float*)d_in[6];
    float* out = (float*)d_out;

    float* base = nullptr;
    cudaGetSymbolAddress((void**)&base, g_scratch);
    float* pe     = base + OFF_PE;
    float* label  = base + OFF_LABEL;
    float* xe     = base + OFF_XE;
    float* x1e    = base + OFF_X1E;
    float* mem    = base + OFF_MEM;
    float* pq     = base + OFF_PQ;
    float* pkc    = base + OFF_PKC;
    float* dx0    = base + OFF_DX0;
    float* dx1    = base + OFF_DX1;
    float* dx     = base + OFF_DX;
    float* dxpt3  = base + OFF_DXPT3;
    float* dpq    = base + OFF_DPQ;
    float* dmask  = base + OFF_DMASK;
    float* dsc    = base + OFF_DSC;
    float* ipart  = base + OFF_IPART;
    float* dpart  = base + OFF_DPART;
    float* memlab = base + OFF_MEMLAB;
    float* rsum   = base + OFF_RSUM;
    float* probs  = base + OFF_PROBS;

    dim3 tb(32, 8);

    pe_kernel<<<(HW * DD + 255) / 256, 256>>>(pe);
    label_kernel<<<(3 * BB * HW + 255) / 256, 256>>>(train_label, label);

    // ---- encoder ----
    build_kernel<<<dim3(48, 16, 16), tb>>>(train_feat, train_feat, 3, pe, xe, 0);
    gemm_kernel<1, 1><<<dim3(1, (16 * LE + 127) / 128, 1), 256>>>(
        xe, wk_self, nullptr, pq, bk_self, 16 * LE, 128, 512, 512,
        512, 512, 128, 0, 0, 0, 0, 1.0f, 0, 128);
    gemm_kernel<1, 2><<<dim3(12, (LE + 127) / 128, 16), 256>>>(
        pq, pq, nullptr, probs, nullptr, LE, LE, 128, 128,
        128, 128, 1456, (size_t)LE * 128, (size_t)LE * 128, (size_t)LE * 1456,
        0, 30.0f, 0, LE);
    rowsum_kernel<<<dim3(LE, 16), 128>>>(probs, nullptr, rsum, nullptr, LE, 1456, 1456, 0);
    gemm_kernel<0, 3><<<dim3(4, (LE + 127) / 128, 16), 256>>>(
        probs, xe, xe, x1e, rsum, LE, 512, 1456, LE,
        1456, 512, 512, (size_t)LE * 1456, (size_t)LE * 512, (size_t)LE * 512,
        0, 1.0f, 1, 512);
    inorm_part<<<dim3(48, 4), 256>>>(x1e, ipart);
    inorm_apply<<<dim3(48, 4), 256>>>(x1e, mem, ipart);
    gemm_kernel<1, 1><<<dim3(1, (16 * LE + 127) / 128, 1), 256>>>(
        mem, wk_cross, nullptr, pkc, bk_cross, 16 * LE, 128, 512, 512,
        512, 512, 128, 0, 0, 0, 0, 1.0f, 0, 128);
    memlab_kernel<<<((int)(SZ_MEMLAB / 4) + 255) / 256, 256>>>(mem, label, memlab);

    // ---- decoder (96 batched) ----
    build_kernel<<<dim3(96, 16, 16), tb>>>(train_feat, test_feat, 3, pe, dx0, 1);
    gemm_kernel<1, 1><<<dim3(1, (96 * LDQ + 127) / 128, 1), 256>>>(
        dx0, wk_self, nullptr, dpq, bk_self, 96 * LDQ, 128, 512, 512,
        512, 512, 128, 0, 0, 0, 0, 1.0f, 0, 128);
    gemm_kernel<1, 2><<<dim3(4, (LDQ + 127) / 128, 96), 256>>>(
        dpq, dpq, nullptr, probs, nullptr, LDQ, LDQ, 128, 128,
        128, 128, 496, (size_t)LDQ * 128, (size_t)LDQ * 128, (size_t)LDQ * 496,
        0, 30.0f, 0, LDQ);
    rowsum_kernel<<<dim3(LDQ, 96), 128>>>(probs, nullptr, rsum, nullptr, LDQ, 496, 496, 0);
    gemm_kernel<0, 3><<<dim3(4, (LDQ + 127) / 128, 96), 256>>>(
        probs, dx0, dx0, dx1, rsum, LDQ, 512, 496, LDQ,
        496, 512, 512, (size_t)LDQ * 496, (size_t)LDQ * 512, (size_t)LDQ * 512,
        0, 1.0f, 1, 512);
    inorm_part<<<dim3(96, 4), 256>>>(dx1, ipart);
    inorm_apply<<<dim3(96, 4), 256>>>(dx1, dx, ipart);
    gemm_kernel<1, 1><<<dim3(1, (96 * LDQ + 127) / 128, 1), 256>>>(
        dx, wk_cross, nullptr, dpq, bk_cross, 96 * LDQ, 128, 512, 512,
        512, 512, 128, 0, 0, 0, 0, 1.0f, 0, 128);
    gemm_kernel<1, 2><<<dim3(12, (LDQ + 127) / 128, 96), 256>>>(
        dpq, pkc, nullptr, probs, nullptr, LDQ, LE, 128, 128,
        128, 128, 1456, (size_t)LDQ * 128, (size_t)LE * 128, (size_t)LDQ * 1456,
        1, 30.0f, 0, LE);
    rowsum_kernel<<<dim3(LDQ, 96), 128>>>(probs, label, rsum, dmask, LDQ, LE, 1456, 1);
    gemm_kernel<0, 3><<<dim3(4, (LDQ + 127) / 128, 96), 256>>>(
        probs, memlab, dx, dxpt3, rsum, LDQ, 512, 1456, LE,
        1456, 512, 512, (size_t)LDQ * 1456, (size_t)LE * 512, (size_t)LDQ * 512,
        1, 1.0f, 1, 512);
    dec_part_kernel<<<dim3(96, 4), 256>>>(dx, dxpt3, dmask, dpart);
    dec_scale_kernel<<<1, 96>>>(dpart, dsc);
    final_kernel<<<dim3(96, 16, 16), tb>>>(dx, dxpt3, dmask, dsc, out);
}

// round 10
// speedup vs baseline: 1.6459x; 1.0190x over previous
#include <cuda_runtime.h>
#include <math.h>
#include <stdint.h>

typedef unsigned long long u64;

#define BB 16
#define DD 512
#define HW 484
#define LE 1452
#define LDQ 484
#define NSCALE 0.011048543456039806f
#define DHWF 247808.0f
#define IEPS 1e-5f
#define GRP 247808
#define QF4 15488   // GRP/4/4 : float4s per quarter

// ---- scratch layout (floats) ----
#define SZ_PE     ((size_t)HW*DD)
#define SZ_LABEL  ((size_t)BB*LE)
#define SZ_XE     ((size_t)BB*LE*DD)
#define SZ_DX0    ((size_t)96*LDQ*DD)
#define SZ_PQ     ((size_t)BB*LE*128)
#define SZ_DPQ    ((size_t)96*LDQ*128)
#define SZ_DX     ((size_t)96*LDQ*DD)
#define SZ_DMASK  ((size_t)96*LDQ)
#define SZ_PROBS  ((size_t)96*LDQ*1456)
#define SZ_RSUM   ((size_t)96*LDQ)

#define OFF_PE    ((size_t)0)
#define OFF_LABEL (OFF_PE + SZ_PE)
#define OFF_XE    (OFF_LABEL + SZ_LABEL)
#define OFF_DX0   (OFF_XE + SZ_XE)          // contiguous with XE for merged proj
#define OFF_X1E   (OFF_DX0 + SZ_DX0)
#define OFF_MEM   (OFF_X1E + SZ_XE)
#define OFF_PQ    (OFF_MEM + SZ_XE)
#define OFF_DPQ   (OFF_PQ + SZ_PQ)          // contiguous with PQ for merged proj
#define OFF_PKC   (OFF_DPQ + SZ_DPQ)
#define OFF_DX1   (OFF_PKC + SZ_PQ)
#define OFF_DX    (OFF_DX1 + SZ_DX)
#define OFF_DXPT3 (OFF_DX + SZ_DX)
#define OFF_DMASK (OFF_DXPT3 + SZ_DX)
#define OFF_DSC   (OFF_DMASK + SZ_DMASK)
#define OFF_IPART (OFF_DSC + 96*4)
#define OFF_DPART (OFF_IPART + 96*4)
#define OFF_RSUM  (OFF_DPART + 96*4*3)
#define OFF_PROBS (OFF_RSUM + SZ_RSUM)
#define SCRATCH_TOTAL (OFF_PROBS + SZ_PROBS)

__device__ __align__(16) float g_scratch[SCRATCH_TOTAL];

// ---- f32x2 helpers ----
__device__ __forceinline__ u64 ffma2(u64 a, u64 b, u64 c) {
    u64 d;
    asm("fma.rn.f32x2 %0, %1, %2, %3;" : "=l"(d) : "l"(a), "l"(b), "l"(c));
    return d;
}
__device__ __forceinline__ u64 pack2(float lo, float hi) {
    u64 r;
    asm("mov.b64 %0, {%1, %2};" : "=l"(r) : "f"(lo), "f"(hi));
    return r;
}
__device__ __forceinline__ void unpack2(u64 v, float& lo, float& hi) {
    asm("mov.b64 {%0, %1}, %2;" : "=f"(lo), "=f"(hi) : "l"(v));
}

__device__ __forceinline__ void ld8(const float* p, bool valid, float* r) {
    if (valid) {
        float4 v0 = *(const float4*)p;
        float4 v1 = *(const float4*)(p + 4);
        r[0] = v0.x; r[1] = v0.y; r[2] = v0.z; r[3] = v0.w;
        r[4] = v1.x; r[5] = v1.y; r[6] = v1.z; r[7] = v1.w;
    } else {
#pragma unroll
        for (int j = 0; j < 8; j++) r[j] = 0.0f;
    }
}

// ============ generic batched GEMM, 128x128 tile, double-buffered ============
// Thread's 8 N-columns split into two 4-wide segments 64 apart (bank-conflict
// free). Inner kk loop software-pipelines smem operand loads one step ahead.
// C[g] = f( A[g] @ op(B[gk]) );  op = B^T if TRANSB (B is [N][K]).
// LABB (NN path only): B row k is scaled by LABB[gk*KB + k] during staging.
// EPI 0: alpha*acc (+Cin)
// EPI 1: bias(AUX) + row L2-normalize  (proj; N==128, G==1)
// EPI 2: exp(alpha*acc) for n<NVALID else 0  (logits; ldC = padded width)
// EPI 3: AUX[g*M+m]*acc + Cin          (value with row 1/sum scale)
template<int TRANSB, int EPI>
__global__ void __launch_bounds__(256, 2)
gemm_kernel(const float* __restrict__ A, const float* __restrict__ B,
            const float* __restrict__ Cin, float* __restrict__ C,
            const float* __restrict__ AUX, const float* __restrict__ LABB,
            int M, int N, int Kloop, int KB,
            int ldA, int ldB, int ldC,
            size_t sA, size_t sB, size_t sC,
            int gkMod, float alpha, int addC, int NVALID) {
    __shared__ float As[2][16][132];
    __shared__ float Bs[2][16][132];
    int g = blockIdx.z;
    int gk = gkMod ? (g & 15) : g;
    const float* Ag = A + (size_t)g * sA;
    const float* Bg = B + (size_t)gk * sB;
    int mBase = blockIdx.y * 128, nBase = blockIdx.x * 128;
    int t = threadIdx.x;

    int am = t >> 1, ak = (t & 1) * 8;
    bool avalid = (mBase + am) < M;
    const float* aPtr = Ag + (size_t)(mBase + am) * ldA + ak;

    int bn = t >> 1, bk = (t & 1) * 8;       // TRANSB path
    int bk2 = t >> 4, bnq = (t & 15) * 8;    // NN path
    bool bnvalid = (nBase + bn) < N;
    const float* bPtrT = Bg + (size_t)(nBase + bn) * ldB + bk;
    const float* bPtrN = Bg + (size_t)bk2 * ldB + nBase + bnq;
    const float* labRow = LABB ? (LABB + (size_t)gk * KB) : nullptr;

    float ra[8], rb[8];
    ld8(aPtr, avalid, ra);
    if (TRANSB) {
        ld8(bPtrT, bnvalid, rb);
    } else {
        ld8(bPtrN, bk2 < KB, rb);
        if (labRow && bk2 < KB) {
            float lb = labRow[bk2];
#pragma unroll
            for (int j = 0; j < 8; j++) rb[j] *= lb;
        }
    }

#pragma unroll
    for (int j = 0; j < 8; j++) As[0][ak + j][am] = ra[j];
    if (TRANSB) {
#pragma unroll
        for (int j = 0; j < 8; j++) Bs[0][bk + j][bn] = rb[j];
    } else {
        *(float4*)&Bs[0][bk2][bnq]     = make_float4(rb[0], rb[1], rb[2], rb[3]);
        *(float4*)&Bs[0][bk2][bnq + 4] = make_float4(rb[4], rb[5], rb[6], rb[7]);
    }
    __syncthreads();

    u64 acc[8][4];   // [mi][2*seg + pair]
#pragma unroll
    for (int i = 0; i < 8; i++)
#pragma unroll
        for (int j = 0; j < 4; j++) acc[i][j] = 0ull;

    int m0 = (t >> 4) * 8;
    int nA = (t & 15) * 4;       // segment 0 base; segment 1 at nA + 64
    int buf = 0;

    for (int k0 = 0; k0 < Kloop; k0 += 16) {
        int kn = k0 + 16;
        bool more = kn < Kloop;
        if (more) {
            ld8(aPtr + kn, avalid, ra);
            if (TRANSB) {
                ld8(bPtrT + kn, bnvalid, rb);
            } else {
                ld8(bPtrN + (size_t)kn * ldB, (kn + bk2) < KB, rb);
                if (labRow && (kn + bk2) < KB) {
                    float lb = labRow[kn + bk2];
#pragma unroll
                    for (int j = 0; j < 8; j++) rb[j] *= lb;
                }
            }
        }
        // software-pipelined operand fetch: stage kk+1 loads before kk math
        ulonglong2 pbA[2], pbB[2];
        float4 pa0[2], pa1[2];
        pbA[0] = *(const ulonglong2*)&Bs[buf][0][nA];
        pbB[0] = *(const ulonglong2*)&Bs[buf][0][nA + 64];
        pa0[0] = *(const float4*)&As[buf][0][m0];
        pa1[0] = *(const float4*)&As[buf][0][m0 + 4];
#pragma unroll
        for (int kk = 0; kk < 16; kk++) {
            int cur = kk & 1, nxt = cur ^ 1;
            if (kk < 15) {
                pbA[nxt] = *(const ulonglong2*)&Bs[buf][kk + 1][nA];
                pbB[nxt] = *(const ulonglong2*)&Bs[buf][kk + 1][nA + 64];
                pa0[nxt] = *(const float4*)&As[buf][kk + 1][m0];
                pa1[nxt] = *(const float4*)&As[buf][kk + 1][m0 + 4];
            }
            float av[8] = {pa0[cur].x, pa0[cur].y, pa0[cur].z, pa0[cur].w,
                           pa1[cur].x, pa1[cur].y, pa1[cur].z, pa1[cur].w};
#pragma unroll
            for (int i = 0; i < 8; i++) {
                u64 ad = pack2(av[i], av[i]);
                acc[i][0] = ffma2(ad, pbA[cur].x, acc[i][0]);
                acc[i][1] = ffma2(ad, pbA[cur].y, acc[i][1]);
                acc[i][2] = ffma2(ad, pbB[cur].x, acc[i][2]);
                acc[i][3] = ffma2(ad, pbB[cur].y, acc[i][3]);
            }
        }
        if (more) {
            int nb = buf ^ 1;
#pragma unroll
            for (int j = 0; j < 8; j++) As[nb][ak + j][am] = ra[j];
            if (TRANSB) {
#pragma unroll
                for (int j = 0; j < 8; j++) Bs[nb][bk + j][bn] = rb[j];
            } else {
                *(float4*)&Bs[nb][bk2][bnq]     = make_float4(rb[0], rb[1], rb[2], rb[3]);
                *(float4*)&Bs[nb][bk2][bnq + 4] = make_float4(rb[4], rb[5], rb[6], rb[7]);
            }
            __syncthreads();
            buf = nb;
        }
    }

    if (EPI == 1) {
        float bkv[8];
#pragma unroll
        for (int s = 0; s < 2; s++)
#pragma unroll
            for (int j = 0; j < 4; j++) bkv[s * 4 + j] = AUX[nA + s * 64 + j];
#pragma unroll
        for (int i = 0; i < 8; i++) {
            int m = mBase + m0 + i;
            float o[8];
#pragma unroll
            for (int j = 0; j < 4; j++) unpack2(acc[i][j], o[2 * j], o[2 * j + 1]);
            float ss = 0.0f;
#pragma unroll
            for (int j = 0; j < 8; j++) {
                o[j] += bkv[j];
                ss += o[j] * o[j];
            }
#pragma unroll
            for (int d = 8; d; d >>= 1) ss += __shfl_xor_sync(0xffffffffu, ss, d, 16);
            float rn = 1.0f / fmaxf(sqrtf(ss), 1e-12f);
            if (m < M) {
                size_t off = (size_t)m * 128;
                *(float4*)(C + off + nA)      = make_float4(o[0] * rn, o[1] * rn, o[2] * rn, o[3] * rn);
                *(float4*)(C + off + nA + 64) = make_float4(o[4] * rn, o[5] * rn, o[6] * rn, o[7] * rn);
            }
        }
        return;
    }

    if (EPI == 2) {
        bool interior = (nBase + 128) <= NVALID;
#pragma unroll
        for (int i = 0; i < 8; i++) {
            int m = mBase + m0 + i;
            if (m >= M) continue;
            float o[8];
#pragma unroll
            for (int j = 0; j < 4; j++) unpack2(acc[i][j], o[2 * j], o[2 * j + 1]);
            size_t off = (size_t)g * sC + (size_t)m * ldC + nBase;
            if (interior) {
                *(float4*)(C + off + nA) = make_float4(
                    __expf(alpha * o[0]), __expf(alpha * o[1]),
                    __expf(alpha * o[2]), __expf(alpha * o[3]));
                *(float4*)(C + off + nA + 64) = make_float4(
                    __expf(alpha * o[4]), __expf(alpha * o[5]),
                    __expf(alpha * o[6]), __expf(alpha * o[7]));
            } else {
#pragma unroll
                for (int s = 0; s < 2; s++)
#pragma unroll
                    for (int j = 0; j < 4; j++) {
                        int n = nBase + nA + s * 64 + j;
                        if (n < ldC)
                            C[(size_t)g * sC + (size_t)m * ldC + n] =
                                (n < NVALID) ? __expf(alpha * o[s * 4 + j]) : 0.0f;
                    }
            }
        }
        return;
    }

    if (EPI == 3) {
#pragma unroll
        for (int i = 0; i < 8; i++) {
            int m = mBase + m0 + i;
            if (m >= M) continue;
            float rs = AUX[(size_t)g * M + m];
            float o[8];
#pragma unroll
            for (int j = 0; j < 4; j++) unpack2(acc[i][j], o[2 * j], o[2 * j + 1]);
            size_t off = (size_t)g * sC + (size_t)m * ldC + nBase;
            float4 c0 = *(const float4*)(Cin + off + nA);
            float4 c1 = *(const float4*)(Cin + off + nA + 64);
            *(float4*)(C + off + nA) = make_float4(rs * o[0] + c0.x, rs * o[1] + c0.y,
                                                   rs * o[2] + c0.z, rs * o[3] + c0.w);
            *(float4*)(C + off + nA + 64) = make_float4(rs * o[4] + c1.x, rs * o[5] + c1.y,
                                                        rs * o[6] + c1.z, rs * o[7] + c1.w);
        }
        return;
    }

    // EPI 0
    bool fullN = (nBase + 128) <= N;
#pragma unroll
    for (int i = 0; i < 8; i++) {
        int m = mBase + m0 + i;
        if (m >= M) continue;
        float o[8];
#pragma unroll
        for (int j = 0; j < 4; j++) unpack2(acc[i][j], o[2 * j], o[2 * j + 1]);
#pragma unroll
        for (int j = 0; j < 8; j++) o[j] *= alpha;
        size_t off = (size_t)g * sC + (size_t)m * ldC + nBase;
        if (fullN) {
            if (addC) {
                float4 c0 = *(const float4*)(Cin + off + nA);
                float4 c1 = *(const float4*)(Cin + off + nA + 64);
                o[0] += c0.x; o[1] += c0.y; o[2] += c0.z; o[3] += c0.w;
                o[4] += c1.x; o[5] += c1.y; o[6] += c1.z; o[7] += c1.w;
            }
            *(float4*)(C + off + nA)      = make_float4(o[0], o[1], o[2], o[3]);
            *(float4*)(C + off + nA + 64) = make_float4(o[4], o[5], o[6], o[7]);
        } else {
#pragma unroll
            for (int s = 0; s < 2; s++)
#pragma unroll
                for (int j = 0; j < 4; j++) {
                    int n = nBase + nA + s * 64 + j;
                    if (n < N) {
                        float v = o[s * 4 + j];
                        if (addC) v += Cin[off + nA + s * 64 + j];
                        C[off + nA + s * 64 + j] = v;
                    }
                }
        }
    }
}

// ================= small kernels =================
__global__ void pe_kernel(float* __restrict__ pe) {
    int idx = blockIdx.x * 256 + threadIdx.x;
    if (idx >= HW * DD) return;
    int p = idx >> 9, c = idx & 511;
    float pos = (float)(p + 1);
    int j = c & 255;
    float f = powf(10000.0f, -(float)j * (1.0f / 256.0f));
    float a = pos * f;
    pe[idx] = (c < 256) ? sinf(a) : cosf(a);
}

__global__ void label_kernel(const float* __restrict__ lab, float* __restrict__ out) {
    int idx = blockIdx.x * 256 + threadIdx.x;
    if (idx >= 3 * BB * HW) return;
    int p = idx % HW;
    int t = idx / HW;
    int b = t % BB;
    int ni = t / BB;
    out[(size_t)b * LE + ni * HW + p] = lab[idx];
}

__global__ void build_kernel(const float* __restrict__ fa, const float* __restrict__ fb,
                             int split, const float* __restrict__ pe,
                             float* __restrict__ xout, int mode) {
    int g = blockIdx.x;
    int img = g >> 4, b = g & 15;
    const float* f = (img < split) ? (fa + (size_t)img * BB * DD * HW)
                                   : (fb + (size_t)(img - split) * BB * DD * HW);
    int p0 = blockIdx.y * 32, c0 = blockIdx.z * 32;
    __shared__ float tl[32][33];
    int tx = threadIdx.x, ty = threadIdx.y;
#pragma unroll
    for (int r = 0; r < 4; r++) {
        int c = c0 + ty + r * 8, p = p0 + tx;
        if (p < HW) tl[ty + r * 8][tx] = f[((size_t)b * DD + c) * HW + p];
    }
    __syncthreads();
#pragma unroll
    for (int r = 0; r < 4; r++) {
        int p = p0 + ty + r * 8, c = c0 + tx;
        if (p < HW) {
            size_t row = (mode == 0) ? ((size_t)b * LE + (size_t)img * HW + p)
                                     : ((size_t)g * LDQ + p);
            xout[row * DD + c] = tl[tx][ty + r * 8] + pe[(size_t)p * DD + c] * 1e-3f;
        }
    }
}

// row sums of exp'd probs -> 1/sum (and mask = sum(p*label)/sum when LABEL)
__global__ void rowsum_kernel(const float* __restrict__ P, const float* __restrict__ LABEL,
                              float* __restrict__ RS, float* __restrict__ MASKOUT,
                              int Mrows, int Lk, int ld, int gkMod) {
    int q = blockIdx.x, g = blockIdx.y, t = threadIdx.x;   // 128 threads
    int gk = gkMod ? (g & 15) : g;
    const float4* p4 = (const float4*)(P + ((size_t)g * Mrows + q) * ld);
    int n4 = Lk >> 2;
    float s = 0.0f, ms = 0.0f;
    if (LABEL) {
        const float4* l4 = (const float4*)(LABEL + (size_t)gk * Lk);
        for (int i = t; i < n4; i += 128) {
            float4 v = p4[i];
            float4 lv = l4[i];
            s += v.x + v.y + v.z + v.w;
            ms += v.x * lv.x + v.y * lv.y + v.z * lv.z + v.w * lv.w;
        }
    } else {
        for (int i = t; i < n4; i += 128) {
            float4 v = p4[i];
            s += v.x + v.y + v.z + v.w;
        }
    }
    __shared__ float rs_[4], rm_[4];
#pragma unroll
    for (int m = 16; m; m >>= 1) {
        s += __shfl_xor_sync(0xffffffffu, s, m);
        ms += __shfl_xor_sync(0xffffffffu, ms, m);
    }
    if ((t & 31) == 0) { rs_[t >> 5] = s; rm_[t >> 5] = ms; }
    __syncthreads();
    if (t == 0) {
        float st = rs_[0] + rs_[1] + rs_[2] + rs_[3];
        float inv = 1.0f / st;
        RS[(size_t)g * Mrows + q] = inv;
        if (MASKOUT) {
            float mt = rm_[0] + rm_[1] + rm_[2] + rm_[3];
            MASKOUT[(size_t)g * Mrows + q] = mt * inv;
        }
    }
}

// InstanceL2Norm: partial sums then apply (deterministic 2-stage)
__global__ void inorm_part(const float* __restrict__ in, float* __restrict__ part) {
    int g = blockIdx.x, q = blockIdx.y, t = threadIdx.x;
    const float4* ip = (const float4*)(in + (size_t)g * GRP) + (size_t)q * QF4;
    float ss = 0.0f;
    for (int i = t; i < QF4; i += 256) {
        float4 v = ip[i];
        ss += v.x * v.x + v.y * v.y + v.z * v.z + v.w * v.w;
    }
    __shared__ float red[8];
#pragma unroll
    for (int m = 16; m; m >>= 1) ss += __shfl_xor_sync(0xffffffffu, ss, m);
    if ((t & 31) == 0) red[t >> 5] = ss;
    __syncthreads();
    if (t == 0) {
        float s = 0.0f;
#pragma unroll
        for (int i = 0; i < 8; i++) s += red[i];
        part[g * 4 + q] = s;
    }
}

__global__ void inorm_apply(const float* __restrict__ in, float* __restrict__ out,
                            const float* __restrict__ part) {
    int g = blockIdx.x, q = blockIdx.y, t = threadIdx.x;
    float ss = part[g * 4 + 0] + part[g * 4 + 1] + part[g * 4 + 2] + part[g * 4 + 3];
    float sc = NSCALE * sqrtf(DHWF / (ss + IEPS));
    const float4* ip = (const float4*)(in + (size_t)g * GRP) + (size_t)q * QF4;
    float4* op = (float4*)(out + (size_t)g * GRP) + (size_t)q * QF4;
    for (int i = t; i < QF4; i += 256) {
        float4 v = ip[i];
        v.x *= sc; v.y *= sc; v.z *= sc; v.w *= sc;
        op[i] = v;
    }
}

// decoder 3-sum partials: u = x*mask, v = x + t3
__global__ void dec_part_kernel(const float* __restrict__ X, const float* __restrict__ XP,
                                const float* __restrict__ MASK, float* __restrict__ part) {
    int g = blockIdx.x, q = blockIdx.y, t = threadIdx.x;
    const float4* x4 = (const float4*)(X + (size_t)g * GRP);
    const float4* p4 = (const float4*)(XP + (size_t)g * GRP);
    const float* mk = MASK + (size_t)g * LDQ;
    float s2 = 0.0f, s4 = 0.0f, cr = 0.0f;
    for (int i = t; i < QF4; i += 256) {
        int gi = q * QF4 + i;
        float m = mk[gi >> 7];
        float4 x = x4[gi];
        float4 v = p4[gi];
        float ux = x.x * m, uy = x.y * m, uz = x.z * m, uw = x.w * m;
        s2 += ux * ux + uy * uy + uz * uz + uw * uw;
        s4 += v.x * v.x + v.y * v.y + v.z * v.z + v.w * v.w;
        cr += ux * v.x + uy * v.y + uz * v.z + uw * v.w;
    }
    __shared__ float r2[8], r4[8], rc[8];
#pragma unroll
    for (int m = 16; m; m >>= 1) {
        s2 += __shfl_xor_sync(0xffffffffu, s2, m);
        s4 += __shfl_xor_sync(0xffffffffu, s4, m);
        cr += __shfl_xor_sync(0xffffffffu, cr, m);
    }
    if ((t & 31) == 0) { r2[t >> 5] = s2; r4[t >> 5] = s4; rc[t >> 5] = cr; }
    __syncthreads();
    if (t == 0) {
        float a = 0, b = 0, c = 0;
#pragma unroll
        for (int i = 0; i < 8; i++) { a += r2[i]; b += r4[i]; c += rc[i]; }
        part[(g * 4 + q) * 3 + 0] = a;
        part[(g * 4 + q) * 3 + 1] = b;
        part[(g * 4 + q) * 3 + 2] = c;
    }
}

__global__ void dec_scale_kernel(const float* __restrict__ part, float* __restrict__ SC) {
    int g = threadIdx.x;
    if (g >= 96) return;
    float a = 0, b = 0, c = 0;
#pragma unroll
    for (int q = 0; q < 4; q++) {
        a += part[(g * 4 + q) * 3 + 0];
        b += part[(g * 4 + q) * 3 + 1];
        c += part[(g * 4 + q) * 3 + 2];
    }
    float S2 = NSCALE * sqrtf(DHWF / (a + IEPS));
    float S4 = NSCALE * sqrtf(DHWF / (b + IEPS));
    float sso = S2 * S2 * a + 2.0f * S2 * S4 * c + S4 * S4 * b;
    float SO = NSCALE * sqrtf(DHWF / (sso + IEPS));
    SC[g * 4 + 0] = S2;
    SC[g * 4 + 1] = S4;
    SC[g * 4 + 2] = SO;
}

__global__ void final_kernel(const float* __restrict__ X, const float* __restrict__ XP,
                             const float* __restrict__ MASK, const float* __restrict__ SC,
                             float* __restrict__ out) {
    int g = blockIdx.x;
    float S2 = SC[g * 4 + 0], S4 = SC[g * 4 + 1], SO = SC[g * 4 + 2];
    int p0 = blockIdx.y * 32, c0 = blockIdx.z * 32;
    __shared__ float tile[32][33];
    int tx = threadIdx.x, ty = threadIdx.y;
    size_t base = (size_t)g * GRP;
#pragma unroll
    for (int r = 0; r < 4; r++) {
        int p = p0 + ty + r * 8, c = c0 + tx;
        if (p < LDQ) {
            size_t idx = base + (size_t)p * 512 + c;
            float u = X[idx] * MASK[(size_t)g * LDQ + p];
            tile[ty + r * 8][tx] = SO * (S2 * u + S4 * XP[idx]);
        }
    }
    __syncthreads();
#pragma unroll
    for (int r = 0; r < 4; r++) {
        int p = p0 + tx, c = c0 + ty + r * 8;
        if (p < LDQ) out[((size_t)g * 512 + c) * LDQ + p] = tile[tx][ty + r * 8];
    }
}

// ================= launcher =================
extern "C" void kernel_launch(void* const* d_in, const int* in_sizes, int n_in,
                              void* d_out, int out_size) {
    const float* train_feat  = (const float*)d_in[0];
    const float* test_feat   = (const float*)d_in[1];
    const float* train_label = (const float*)d_in[2];
    const float* wk_self     = (const float*)d_in[3];
    const float* bk_self     = (const float*)d_in[4];
    const float* wk_cross    = (const float*)d_in[5];
    const float* bk_cross    = (const float*)d_in[6];
    float* out = (float*)d_out;

    float* base = nullptr;
    cudaGetSymbolAddress((void**)&base, g_scratch);
    float* pe     = base + OFF_PE;
    float* label  = base + OFF_LABEL;
    float* xe     = base + OFF_XE;
    float* dx0    = base + OFF_DX0;
    float* x1e    = base + OFF_X1E;
    float* mem    = base + OFF_MEM;
    float* pq     = base + OFF_PQ;
    float* dpq    = base + OFF_DPQ;
    float* pkc    = base + OFF_PKC;
    float* dx1    = base + OFF_DX1;
    float* dx     = base + OFF_DX;
    float* dxpt3  = base + OFF_DXPT3;
    float* dmask  = base + OFF_DMASK;
    float* dsc    = base + OFF_DSC;
    float* ipart  = base + OFF_IPART;
    float* dpart  = base + OFF_DPART;
    float* rsum   = base + OFF_RSUM;
    float* probs  = base + OFF_PROBS;

    dim3 tb(32, 8);

    pe_kernel<<<(HW * DD + 255) / 256, 256>>>(pe);
    label_kernel<<<(3 * BB * HW + 255) / 256, 256>>>(train_label, label);

    // ---- build both token buffers up front ----
    build_kernel<<<dim3(48, 16, 16), tb>>>(train_feat, train_feat, 3, pe, xe, 0);
    build_kernel<<<dim3(96, 16, 16), tb>>>(train_feat, test_feat, 3, pe, dx0, 1);

    // ---- merged self projection over [xe | dx0] -> [pq | dpq] ----
    const int MALL = 16 * LE + 96 * LDQ;   // 69696
    gemm_kernel<1, 1><<<dim3(1, (MALL + 127) / 128, 1), 256>>>(
        xe, wk_self, nullptr, pq, bk_self, nullptr, MALL, 128, 512, 512,
        512, 512, 128, 0, 0, 0, 0, 1.0f, 0, 128);

    // ---- encoder ----
    gemm_kernel<1, 2><<<dim3(12, (LE + 127) / 128, 16), 256>>>(
        pq, pq, nullptr, probs, nullptr, nullptr, LE, LE, 128, 128,
        128, 128, 1456, (size_t)LE * 128, (size_t)LE * 128, (size_t)LE * 1456,
        0, 30.0f, 0, LE);
    rowsum_kernel<<<dim3(LE, 16), 128>>>(probs, nullptr, rsum, nullptr, LE, 1456, 1456, 0);
    gemm_kernel<0, 3><<<dim3(4, (LE + 127) / 128, 16), 256>>>(
        probs, xe, xe, x1e, rsum, nullptr, LE, 512, 1456, LE,
        1456, 512, 512, (size_t)LE * 1456, (size_t)LE * 512, (size_t)LE * 512,
        0, 1.0f, 1, 512);
    inorm_part<<<dim3(48, 4), 256>>>(x1e, ipart);
    inorm_apply<<<dim3(48, 4), 256>>>(x1e, mem, ipart);
    gemm_kernel<1, 1><<<dim3(1, (16 * LE + 127) / 128, 1), 256>>>(
        mem, wk_cross, nullptr, pkc, bk_cross, nullptr, 16 * LE, 128, 512, 512,
        512, 512, 128, 0, 0, 0, 0, 1.0f, 0, 128);

    // ---- decoder (96 batched) ----
    gemm_kernel<1, 2><<<dim3(4, (LDQ + 127) / 128, 96), 256>>>(
        dpq, dpq, nullptr, probs, nullptr, nullptr, LDQ, LDQ, 128, 128,
        128, 128, 496, (size_t)LDQ * 128, (size_t)LDQ * 128, (size_t)LDQ * 496,
        0, 30.0f, 0, LDQ);
    rowsum_kernel<<<dim3(LDQ, 96), 128>>>(probs, nullptr, rsum, nullptr, LDQ, 496, 496, 0);
    gemm_kernel<0, 3><<<dim3(4, (LDQ + 127) / 128, 96), 256>>>(
        probs, dx0, dx0, dx1, rsum, nullptr, LDQ, 512, 496, LDQ,
        496, 512, 512, (size_t)LDQ * 496, (size_t)LDQ * 512, (size_t)LDQ * 512,
        0, 1.0f, 1, 512);
    inorm_part<<<dim3(96, 4), 256>>>(dx1, ipart);
    inorm_apply<<<dim3(96, 4), 256>>>(dx1, dx, ipart);
    gemm_kernel<1, 1><<<dim3(1, (96 * LDQ + 127) / 128, 1), 256>>>(
        dx, wk_cross, nullptr, dpq, bk_cross, nullptr, 96 * LDQ, 128, 512, 512,
        512, 512, 128, 0, 0, 0, 0, 1.0f, 0, 128);
    gemm_kernel<1, 2><<<dim3(12, (LDQ + 127) / 128, 96), 256>>>(
        dpq, pkc, nullptr, probs, nullptr, nullptr, LDQ, LE, 128, 128,
        128, 128, 1456, (size_t)LDQ * 128, (size_t)LE * 128, (size_t)LDQ * 1456,
        1, 30.0f, 0, LE);
    rowsum_kernel<<<dim3(LDQ, 96), 128>>>(probs, label, rsum, dmask, LDQ, LE, 1456, 1);
    // t3 value: P~ @ (mem * label) via fused label-weighted B staging
    gemm_kernel<0, 3><<<dim3(4, (LDQ + 127) / 128, 96), 256>>>(
        probs, mem, dx, dxpt3, rsum, label, LDQ, 512, 1456, LE,
        1456, 512, 512, (size_t)LDQ * 1456, (size_t)LE * 512, (size_t)LDQ * 512,
        1, 1.0f, 1, 512);
    dec_part_kernel<<<dim3(96, 4), 256>>>(dx, dxpt3, dmask, dpart);
    dec_scale_kernel<<<1, 96>>>(dpart, dsc);
    final_kernel<<<dim3(96, 16, 16), tb>>>(dx, dxpt3, dmask, dsc, out);
}

// round 11
// speedup vs baseline: 2.4543x; 1.4911x over previous
#include <cuda_runtime.h>
#include <math.h>
#include <stdint.h>

typedef unsigned long long u64;

#define BB 16
#define DD 512
#define HW 484
#define LE 1452
#define LDQ 484
#define NSCALE 0.011048543456039806f
#define DHWF 247808.0f
#define IEPS 1e-5f
#define GRP 247808
#define QF4 15488   // GRP/4/4 : float4s per quarter

// ---- scratch layout (floats) ----
#define SZ_PE     ((size_t)HW*DD)
#define SZ_LABEL  ((size_t)BB*LE)
#define SZ_XE     ((size_t)BB*LE*DD)
#define SZ_DX0    ((size_t)96*LDQ*DD)
#define SZ_PQ     ((size_t)BB*LE*128)
#define SZ_DPQ    ((size_t)96*LDQ*128)
#define SZ_DX     ((size_t)96*LDQ*DD)
#define SZ_DMASK  ((size_t)96*LDQ)
#define SZ_PROBS  ((size_t)96*LDQ*1456)
#define SZ_RSUM   ((size_t)96*LDQ)

#define OFF_PE    ((size_t)0)
#define OFF_LABEL (OFF_PE + SZ_PE)
#define OFF_XE    (OFF_LABEL + SZ_LABEL)
#define OFF_DX0   (OFF_XE + SZ_XE)          // contiguous with XE for merged proj
#define OFF_X1E   (OFF_DX0 + SZ_DX0)
#define OFF_MEM   (OFF_X1E + SZ_XE)
#define OFF_PQ    (OFF_MEM + SZ_XE)
#define OFF_DPQ   (OFF_PQ + SZ_PQ)          // contiguous with PQ for merged proj
#define OFF_PKC   (OFF_DPQ + SZ_DPQ)
#define OFF_DX1   (OFF_PKC + SZ_PQ)
#define OFF_DX    (OFF_DX1 + SZ_DX)
#define OFF_DXPT3 (OFF_DX + SZ_DX)
#define OFF_DMASK (OFF_DXPT3 + SZ_DX)
#define OFF_DSC   (OFF_DMASK + SZ_DMASK)
#define OFF_IPART (OFF_DSC + 96*4)
#define OFF_DPART (OFF_IPART + 96*4)
#define OFF_RSUM  (OFF_DPART + 96*4*3)
#define OFF_PROBS (OFF_RSUM + SZ_RSUM)
#define SCRATCH_TOTAL (OFF_PROBS + SZ_PROBS)

__device__ __align__(16) float g_scratch[SCRATCH_TOTAL];

// ---- f32x2 helpers ----
__device__ __forceinline__ u64 ffma2(u64 a, u64 b, u64 c) {
    u64 d;
    asm("fma.rn.f32x2 %0, %1, %2, %3;" : "=l"(d) : "l"(a), "l"(b), "l"(c));
    return d;
}
__device__ __forceinline__ u64 pack2(float lo, float hi) {
    u64 r;
    asm("mov.b64 %0, {%1, %2};" : "=l"(r) : "f"(lo), "f"(hi));
    return r;
}
__device__ __forceinline__ void unpack2(u64 v, float& lo, float& hi) {
    asm("mov.b64 {%0, %1}, %2;" : "=f"(lo), "=f"(hi) : "l"(v));
}
__device__ __forceinline__ uint32_t f2tf32(float f) {
    uint32_t u;
    asm("cvt.rna.tf32.f32 %0, %1;" : "=r"(u) : "f"(f));
    return u;
}
__device__ __forceinline__ void mma_tf32(float* c, uint32_t a0, uint32_t a1,
                                         uint32_t a2, uint32_t a3,
                                         uint32_t b0, uint32_t b1) {
    asm volatile("mma.sync.aligned.m16n8k8.row.col.f32.tf32.tf32.f32 "
                 "{%0,%1,%2,%3}, {%4,%5,%6,%7}, {%8,%9}, {%0,%1,%2,%3};"
                 : "+f"(c[0]), "+f"(c[1]), "+f"(c[2]), "+f"(c[3])
                 : "r"(a0), "r"(a1), "r"(a2), "r"(a3), "r"(b0), "r"(b1));
}

__device__ __forceinline__ void ld8(const float* p, bool valid, float* r) {
    if (valid) {
        float4 v0 = *(const float4*)p;
        float4 v1 = *(const float4*)(p + 4);
        r[0] = v0.x; r[1] = v0.y; r[2] = v0.z; r[3] = v0.w;
        r[4] = v1.x; r[5] = v1.y; r[6] = v1.z; r[7] = v1.w;
    } else {
#pragma unroll
        for (int j = 0; j < 8; j++) r[j] = 0.0f;
    }
}

// ============ tf32 tensor-core value GEMM ============
// C[g] = RS[g][m] * (P[g] @ V[gk]) + Cin[g];  P row-major [M][Kpad] (zero-padded
// cols >= KB), V row-major [KB][512] (LABB row-scale optional). N fixed 512.
__global__ void __launch_bounds__(256, 2)
tf32_value_kernel(const float* __restrict__ P, const float* __restrict__ V,
                  const float* __restrict__ Cin, float* __restrict__ C,
                  const float* __restrict__ RS, const float* __restrict__ LABB,
                  int M, int Kpad, int KB, int ldA,
                  size_t sA, size_t sB, size_t sC, int gkMod) {
    __shared__ __align__(16) uint32_t As[2][128][20];
    __shared__ __align__(16) uint32_t Bs[2][16][136];
    int g = blockIdx.z;
    int gk = gkMod ? (g & 15) : g;
    const float* Pg = P + (size_t)g * sA;
    const float* Vg = V + (size_t)gk * sB;
    int mBase = blockIdx.y * 128, nBase = blockIdx.x * 128;
    int t = threadIdx.x, lane = t & 31, warp = t >> 5;
    int mW = (warp >> 2) * 64, nW = (warp & 3) * 32;

    int am = t >> 1, ak = (t & 1) * 8;
    bool avalid = (mBase + am) < M;
    const float* aPtr = Pg + (size_t)(mBase + am) * ldA + ak;
    int bk2 = t >> 4, bnq = (t & 15) * 8;
    const float* bPtr = Vg + (size_t)bk2 * 512 + nBase + bnq;
    const float* labRow = LABB ? (LABB + (size_t)gk * KB) : nullptr;

    float ra[8], rb[8];
    ld8(aPtr, avalid, ra);
    {
        bool bv = bk2 < KB;
        ld8(bPtr, bv, rb);
        if (labRow && bv) {
            float lb = labRow[bk2];
#pragma unroll
            for (int j = 0; j < 8; j++) rb[j] *= lb;
        }
    }
    {
        uint32_t ua[8], ub[8];
#pragma unroll
        for (int j = 0; j < 8; j++) { ua[j] = f2tf32(ra[j]); ub[j] = f2tf32(rb[j]); }
        *(uint4*)&As[0][am][ak]     = make_uint4(ua[0], ua[1], ua[2], ua[3]);
        *(uint4*)&As[0][am][ak + 4] = make_uint4(ua[4], ua[5], ua[6], ua[7]);
        *(uint4*)&Bs[0][bk2][bnq]     = make_uint4(ub[0], ub[1], ub[2], ub[3]);
        *(uint4*)&Bs[0][bk2][bnq + 4] = make_uint4(ub[4], ub[5], ub[6], ub[7]);
    }
    __syncthreads();

    float acc[4][4][4];
#pragma unroll
    for (int i = 0; i < 4; i++)
#pragma unroll
        for (int j = 0; j < 4; j++)
#pragma unroll
            for (int q = 0; q < 4; q++) acc[i][j][q] = 0.0f;

    int buf = 0;
    int lr = lane >> 2, lc = lane & 3;

    for (int k0 = 0; k0 < Kpad; k0 += 16) {
        int kn = k0 + 16;
        bool more = kn < Kpad;
        if (more) {
            ld8(aPtr + kn, avalid, ra);
            bool bv = (kn + bk2) < KB;
            ld8(bPtr + (size_t)kn * 512, bv, rb);
            if (labRow && bv) {
                float lb = labRow[kn + bk2];
#pragma unroll
                for (int j = 0; j < 8; j++) rb[j] *= lb;
            }
        }
#pragma unroll
        for (int ks = 0; ks < 16; ks += 8) {
            uint32_t bf[4][2];
#pragma unroll
            for (int nt = 0; nt < 4; nt++) {
                int cc = nW + nt * 8 + lr;
                bf[nt][0] = Bs[buf][ks + lc][cc];
                bf[nt][1] = Bs[buf][ks + lc + 4][cc];
            }
#pragma unroll
            for (int mt = 0; mt < 4; mt++) {
                int r = mW + mt * 16 + lr;
                uint32_t a0 = As[buf][r][ks + lc];
                uint32_t a1 = As[buf][r + 8][ks + lc];
                uint32_t a2 = As[buf][r][ks + lc + 4];
                uint32_t a3 = As[buf][r + 8][ks + lc + 4];
#pragma unroll
                for (int nt = 0; nt < 4; nt++)
                    mma_tf32(acc[mt][nt], a0, a1, a2, a3, bf[nt][0], bf[nt][1]);
            }
        }
        if (more) {
            int nb = buf ^ 1;
            uint32_t ua[8], ub[8];
#pragma unroll
            for (int j = 0; j < 8; j++) { ua[j] = f2tf32(ra[j]); ub[j] = f2tf32(rb[j]); }
            *(uint4*)&As[nb][am][ak]     = make_uint4(ua[0], ua[1], ua[2], ua[3]);
            *(uint4*)&As[nb][am][ak + 4] = make_uint4(ua[4], ua[5], ua[6], ua[7]);
            *(uint4*)&Bs[nb][bk2][bnq]     = make_uint4(ub[0], ub[1], ub[2], ub[3]);
            *(uint4*)&Bs[nb][bk2][bnq + 4] = make_uint4(ub[4], ub[5], ub[6], ub[7]);
            __syncthreads();
            buf = nb;
        }
    }

    // epilogue: rs * acc + Cin
#pragma unroll
    for (int mt = 0; mt < 4; mt++) {
        int r1 = mBase + mW + mt * 16 + lr;
        int r2 = r1 + 8;
        float rs1 = (r1 < M) ? RS[(size_t)g * M + r1] : 0.0f;
        float rs2 = (r2 < M) ? RS[(size_t)g * M + r2] : 0.0f;
#pragma unroll
        for (int nt = 0; nt < 4; nt++) {
            int cb = nBase + nW + nt * 8 + lc * 2;
            if (r1 < M) {
                size_t off = (size_t)g * sC + (size_t)r1 * 512 + cb;
                float2 ci = *(const float2*)(Cin + off);
                float2 o;
                o.x = rs1 * acc[mt][nt][0] + ci.x;
                o.y = rs1 * acc[mt][nt][1] + ci.y;
                *(float2*)(C + off) = o;
            }
            if (r2 < M) {
                size_t off = (size_t)g * sC + (size_t)r2 * 512 + cb;
                float2 ci = *(const float2*)(Cin + off);
                float2 o;
                o.x = rs2 * acc[mt][nt][2] + ci.x;
                o.y = rs2 * acc[mt][nt][3] + ci.y;
                *(float2*)(C + off) = o;
            }
        }
    }
}

// ============ generic batched GEMM, 128x128 tile, double-buffered ============
// (f32x2; used for projections and exp-logits where precision matters)
template<int TRANSB, int EPI>
__global__ void __launch_bounds__(256, 2)
gemm_kernel(const float* __restrict__ A, const float* __restrict__ B,
            const float* __restrict__ Cin, float* __restrict__ C,
            const float* __restrict__ AUX,
            int M, int N, int Kloop, int KB,
            int ldA, int ldB, int ldC,
            size_t sA, size_t sB, size_t sC,
            int gkMod, float alpha, int addC, int NVALID) {
    __shared__ float As[2][16][132];
    __shared__ float Bs[2][16][132];
    int g = blockIdx.z;
    int gk = gkMod ? (g & 15) : g;
    const float* Ag = A + (size_t)g * sA;
    const float* Bg = B + (size_t)gk * sB;
    int mBase = blockIdx.y * 128, nBase = blockIdx.x * 128;
    int t = threadIdx.x;

    int am = t >> 1, ak = (t & 1) * 8;
    bool avalid = (mBase + am) < M;
    const float* aPtr = Ag + (size_t)(mBase + am) * ldA + ak;

    int bn = t >> 1, bk = (t & 1) * 8;
    bool bnvalid = (nBase + bn) < N;
    const float* bPtrT = Bg + (size_t)(nBase + bn) * ldB + bk;

    float ra[8], rb[8];
    ld8(aPtr, avalid, ra);
    ld8(bPtrT, bnvalid, rb);

#pragma unroll
    for (int j = 0; j < 8; j++) As[0][ak + j][am] = ra[j];
#pragma unroll
    for (int j = 0; j < 8; j++) Bs[0][bk + j][bn] = rb[j];
    __syncthreads();

    u64 acc[8][4];
#pragma unroll
    for (int i = 0; i < 8; i++)
#pragma unroll
        for (int j = 0; j < 4; j++) acc[i][j] = 0ull;

    int m0 = (t >> 4) * 8;
    int nA = (t & 15) * 4;
    int buf = 0;

    for (int k0 = 0; k0 < Kloop; k0 += 16) {
        int kn = k0 + 16;
        bool more = kn < Kloop;
        if (more) {
            ld8(aPtr + kn, avalid, ra);
            ld8(bPtrT + kn, bnvalid, rb);
        }
        ulonglong2 pbA[2], pbB[2];
        float4 pa0[2], pa1[2];
        pbA[0] = *(const ulonglong2*)&Bs[buf][0][nA];
        pbB[0] = *(const ulonglong2*)&Bs[buf][0][nA + 64];
        pa0[0] = *(const float4*)&As[buf][0][m0];
        pa1[0] = *(const float4*)&As[buf][0][m0 + 4];
#pragma unroll
        for (int kk = 0; kk < 16; kk++) {
            int cur = kk & 1, nxt = cur ^ 1;
            if (kk < 15) {
                pbA[nxt] = *(const ulonglong2*)&Bs[buf][kk + 1][nA];
                pbB[nxt] = *(const ulonglong2*)&Bs[buf][kk + 1][nA + 64];
                pa0[nxt] = *(const float4*)&As[buf][kk + 1][m0];
                pa1[nxt] = *(const float4*)&As[buf][kk + 1][m0 + 4];
            }
            float av[8] = {pa0[cur].x, pa0[cur].y, pa0[cur].z, pa0[cur].w,
                           pa1[cur].x, pa1[cur].y, pa1[cur].z, pa1[cur].w};
#pragma unroll
            for (int i = 0; i < 8; i++) {
                u64 ad = pack2(av[i], av[i]);
                acc[i][0] = ffma2(ad, pbA[cur].x, acc[i][0]);
                acc[i][1] = ffma2(ad, pbA[cur].y, acc[i][1]);
                acc[i][2] = ffma2(ad, pbB[cur].x, acc[i][2]);
                acc[i][3] = ffma2(ad, pbB[cur].y, acc[i][3]);
            }
        }
        if (more) {
            int nb = buf ^ 1;
#pragma unroll
            for (int j = 0; j < 8; j++) As[nb][ak + j][am] = ra[j];
#pragma unroll
            for (int j = 0; j < 8; j++) Bs[nb][bk + j][bn] = rb[j];
            __syncthreads();
            buf = nb;
        }
    }

    if (EPI == 1) {
        float bkv[8];
#pragma unroll
        for (int s = 0; s < 2; s++)
#pragma unroll
            for (int j = 0; j < 4; j++) bkv[s * 4 + j] = AUX[nA + s * 64 + j];
#pragma unroll
        for (int i = 0; i < 8; i++) {
            int m = mBase + m0 + i;
            float o[8];
#pragma unroll
            for (int j = 0; j < 4; j++) unpack2(acc[i][j], o[2 * j], o[2 * j + 1]);
            float ss = 0.0f;
#pragma unroll
            for (int j = 0; j < 8; j++) {
                o[j] += bkv[j];
                ss += o[j] * o[j];
            }
#pragma unroll
            for (int d = 8; d; d >>= 1) ss += __shfl_xor_sync(0xffffffffu, ss, d, 16);
            float rn = 1.0f / fmaxf(sqrtf(ss), 1e-12f);
            if (m < M) {
                size_t off = (size_t)m * 128;
                *(float4*)(C + off + nA)      = make_float4(o[0] * rn, o[1] * rn, o[2] * rn, o[3] * rn);
                *(float4*)(C + off + nA + 64) = make_float4(o[4] * rn, o[5] * rn, o[6] * rn, o[7] * rn);
            }
        }
        return;
    }

    if (EPI == 2) {
        bool interior = (nBase + 128) <= NVALID;
#pragma unroll
        for (int i = 0; i < 8; i++) {
            int m = mBase + m0 + i;
            if (m >= M) continue;
            float o[8];
#pragma unroll
            for (int j = 0; j < 4; j++) unpack2(acc[i][j], o[2 * j], o[2 * j + 1]);
            size_t off = (size_t)g * sC + (size_t)m * ldC + nBase;
            if (interior) {
                *(float4*)(C + off + nA) = make_float4(
                    __expf(alpha * o[0]), __expf(alpha * o[1]),
                    __expf(alpha * o[2]), __expf(alpha * o[3]));
                *(float4*)(C + off + nA + 64) = make_float4(
                    __expf(alpha * o[4]), __expf(alpha * o[5]),
                    __expf(alpha * o[6]), __expf(alpha * o[7]));
            } else {
#pragma unroll
                for (int s = 0; s < 2; s++)
#pragma unroll
                    for (int j = 0; j < 4; j++) {
                        int n = nBase + nA + s * 64 + j;
                        if (n < ldC)
                            C[(size_t)g * sC + (size_t)m * ldC + n] =
                                (n < NVALID) ? __expf(alpha * o[s * 4 + j]) : 0.0f;
                    }
            }
        }
        return;
    }

    // EPI 0 (unused currently, kept for completeness)
    bool fullN = (nBase + 128) <= N;
#pragma unroll
    for (int i = 0; i < 8; i++) {
        int m = mBase + m0 + i;
        if (m >= M) continue;
        float o[8];
#pragma unroll
        for (int j = 0; j < 4; j++) unpack2(acc[i][j], o[2 * j], o[2 * j + 1]);
#pragma unroll
        for (int j = 0; j < 8; j++) o[j] *= alpha;
        size_t off = (size_t)g * sC + (size_t)m * ldC + nBase;
        if (fullN) {
            if (addC) {
                float4 c0 = *(const float4*)(Cin + off + nA);
                float4 c1 = *(const float4*)(Cin + off + nA + 64);
                o[0] += c0.x; o[1] += c0.y; o[2] += c0.z; o[3] += c0.w;
                o[4] += c1.x; o[5] += c1.y; o[6] += c1.z; o[7] += c1.w;
            }
            *(float4*)(C + off + nA)      = make_float4(o[0], o[1], o[2], o[3]);
            *(float4*)(C + off + nA + 64) = make_float4(o[4], o[5], o[6], o[7]);
        } else {
#pragma unroll
            for (int s = 0; s < 2; s++)
#pragma unroll
                for (int j = 0; j < 4; j++) {
                    int n = nBase + nA + s * 64 + j;
                    if (n < N) {
                        float v = o[s * 4 + j];
                        if (addC) v += Cin[off + nA + s * 64 + j];
                        C[off + nA + s * 64 + j] = v;
                    }
                }
        }
    }
}

// ================= small kernels =================
__global__ void pe_kernel(float* __restrict__ pe) {
    int idx = blockIdx.x * 256 + threadIdx.x;
    if (idx >= HW * DD) return;
    int p = idx >> 9, c = idx & 511;
    float pos = (float)(p + 1);
    int j = c & 255;
    float f = powf(10000.0f, -(float)j * (1.0f / 256.0f));
    float a = pos * f;
    pe[idx] = (c < 256) ? sinf(a) : cosf(a);
}

__global__ void label_kernel(const float* __restrict__ lab, float* __restrict__ out) {
    int idx = blockIdx.x * 256 + threadIdx.x;
    if (idx >= 3 * BB * HW) return;
    int p = idx % HW;
    int t = idx / HW;
    int b = t % BB;
    int ni = t / BB;
    out[(size_t)b * LE + ni * HW + p] = lab[idx];
}

__global__ void build_kernel(const float* __restrict__ fa, const float* __restrict__ fb,
                             int split, const float* __restrict__ pe,
                             float* __restrict__ xout, int mode) {
    int g = blockIdx.x;
    int img = g >> 4, b = g & 15;
    const float* f = (img < split) ? (fa + (size_t)img * BB * DD * HW)
                                   : (fb + (size_t)(img - split) * BB * DD * HW);
    int p0 = blockIdx.y * 32, c0 = blockIdx.z * 32;
    __shared__ float tl[32][33];
    int tx = threadIdx.x, ty = threadIdx.y;
#pragma unroll
    for (int r = 0; r < 4; r++) {
        int c = c0 + ty + r * 8, p = p0 + tx;
        if (p < HW) tl[ty + r * 8][tx] = f[((size_t)b * DD + c) * HW + p];
    }
    __syncthreads();
#pragma unroll
    for (int r = 0; r < 4; r++) {
        int p = p0 + ty + r * 8, c = c0 + tx;
        if (p < HW) {
            size_t row = (mode == 0) ? ((size_t)b * LE + (size_t)img * HW + p)
                                     : ((size_t)g * LDQ + p);
            xout[row * DD + c] = tl[tx][ty + r * 8] + pe[(size_t)p * DD + c] * 1e-3f;
        }
    }
}

// row sums of exp'd probs -> 1/sum (and mask = sum(p*label)/sum when LABEL)
__global__ void rowsum_kernel(const float* __restrict__ P, const float* __restrict__ LABEL,
                              float* __restrict__ RS, float* __restrict__ MASKOUT,
                              int Mrows, int Lk, int ld, int gkMod) {
    int q = blockIdx.x, g = blockIdx.y, t = threadIdx.x;   // 128 threads
    int gk = gkMod ? (g & 15) : g;
    const float4* p4 = (const float4*)(P + ((size_t)g * Mrows + q) * ld);
    int n4 = Lk >> 2;
    float s = 0.0f, ms = 0.0f;
    if (LABEL) {
        const float4* l4 = (const float4*)(LABEL + (size_t)gk * Lk);
        for (int i = t; i < n4; i += 128) {
            float4 v = p4[i];
            float4 lv = l4[i];
            s += v.x + v.y + v.z + v.w;
            ms += v.x * lv.x + v.y * lv.y + v.z * lv.z + v.w * lv.w;
        }
    } else {
        for (int i = t; i < n4; i += 128) {
            float4 v = p4[i];
            s += v.x + v.y + v.z + v.w;
        }
    }
    __shared__ float rs_[4], rm_[4];
#pragma unroll
    for (int m = 16; m; m >>= 1) {
        s += __shfl_xor_sync(0xffffffffu, s, m);
        ms += __shfl_xor_sync(0xffffffffu, ms, m);
    }
    if ((t & 31) == 0) { rs_[t >> 5] = s; rm_[t >> 5] = ms; }
    __syncthreads();
    if (t == 0) {
        float st = rs_[0] + rs_[1] + rs_[2] + rs_[3];
        float inv = 1.0f / st;
        RS[(size_t)g * Mrows + q] = inv;
        if (MASKOUT) {
            float mt = rm_[0] + rm_[1] + rm_[2] + rm_[3];
            MASKOUT[(size_t)g * Mrows + q] = mt * inv;
        }
    }
}

// InstanceL2Norm: partial sums then apply (deterministic 2-stage)
__global__ void inorm_part(const float* __restrict__ in, float* __restrict__ part) {
    int g = blockIdx.x, q = blockIdx.y, t = threadIdx.x;
    const float4* ip = (const float4*)(in + (size_t)g * GRP) + (size_t)q * QF4;
    float ss = 0.0f;
    for (int i = t; i < QF4; i += 256) {
        float4 v = ip[i];
        ss += v.x * v.x + v.y * v.y + v.z * v.z + v.w * v.w;
    }
    __shared__ float red[8];
#pragma unroll
    for (int m = 16; m; m >>= 1) ss += __shfl_xor_sync(0xffffffffu, ss, m);
    if ((t & 31) == 0) red[t >> 5] = ss;
    __syncthreads();
    if (t == 0) {
        float s = 0.0f;
#pragma unroll
        for (int i = 0; i < 8; i++) s += red[i];
        part[g * 4 + q] = s;
    }
}

__global__ void inorm_apply(const float* __restrict__ in, float* __restrict__ out,
                            const float* __restrict__ part) {
    int g = blockIdx.x, q = blockIdx.y, t = threadIdx.x;
    float ss = part[g * 4 + 0] + part[g * 4 + 1] + part[g * 4 + 2] + part[g * 4 + 3];
    float sc = NSCALE * sqrtf(DHWF / (ss + IEPS));
    const float4* ip = (const float4*)(in + (size_t)g * GRP) + (size_t)q * QF4;
    float4* op = (float4*)(out + (size_t)g * GRP) + (size_t)q * QF4;
    for (int i = t; i < QF4; i += 256) {
        float4 v = ip[i];
        v.x *= sc; v.y *= sc; v.z *= sc; v.w *= sc;
        op[i] = v;
    }
}

// decoder 3-sum partials: u = x*mask, v = x + t3
__global__ void dec_part_kernel(const float* __restrict__ X, const float* __restrict__ XP,
                                const float* __restrict__ MASK, float* __restrict__ part) {
    int g = blockIdx.x, q = blockIdx.y, t = threadIdx.x;
    const float4* x4 = (const float4*)(X + (size_t)g * GRP);
    const float4* p4 = (const float4*)(XP + (size_t)g * GRP);
    const float* mk = MASK + (size_t)g * LDQ;
    float s2 = 0.0f, s4 = 0.0f, cr = 0.0f;
    for (int i = t; i < QF4; i += 256) {
        int gi = q * QF4 + i;
        float m = mk[gi >> 7];
        float4 x = x4[gi];
        float4 v = p4[gi];
        float ux = x.x * m, uy = x.y * m, uz = x.z * m, uw = x.w * m;
        s2 += ux * ux + uy * uy + uz * uz + uw * uw;
        s4 += v.x * v.x + v.y * v.y + v.z * v.z + v.w * v.w;
        cr += ux * v.x + uy * v.y + uz * v.z + uw * v.w;
    }
    __shared__ float r2[8], r4[8], rc[8];
#pragma unroll
    for (int m = 16; m; m >>= 1) {
        s2 += __shfl_xor_sync(0xffffffffu, s2, m);
        s4 += __shfl_xor_sync(0xffffffffu, s4, m);
        cr += __shfl_xor_sync(0xffffffffu, cr, m);
    }
    if ((t & 31) == 0) { r2[t >> 5] = s2; r4[t >> 5] = s4; rc[t >> 5] = cr; }
    __syncthreads();
    if (t == 0) {
        float a = 0, b = 0, c = 0;
#pragma unroll
        for (int i = 0; i < 8; i++) { a += r2[i]; b += r4[i]; c += rc[i]; }
        part[(g * 4 + q) * 3 + 0] = a;
        part[(g * 4 + q) * 3 + 1] = b;
        part[(g * 4 + q) * 3 + 2] = c;
    }
}

__global__ void dec_scale_kernel(const float* __restrict__ part, float* __restrict__ SC) {
    int g = threadIdx.x;
    if (g >= 96) return;
    float a = 0, b = 0, c = 0;
#pragma unroll
    for (int q = 0; q < 4; q++) {
        a += part[(g * 4 + q) * 3 + 0];
        b += part[(g * 4 + q) * 3 + 1];
        c += part[(g * 4 + q) * 3 + 2];
    }
    float S2 = NSCALE * sqrtf(DHWF / (a + IEPS));
    float S4 = NSCALE * sqrtf(DHWF / (b + IEPS));
    float sso = S2 * S2 * a + 2.0f * S2 * S4 * c + S4 * S4 * b;
    float SO = NSCALE * sqrtf(DHWF / (sso + IEPS));
    SC[g * 4 + 0] = S2;
    SC[g * 4 + 1] = S4;
    SC[g * 4 + 2] = SO;
}

__global__ void final_kernel(const float* __restrict__ X, const float* __restrict__ XP,
                             const float* __restrict__ MASK, const float* __restrict__ SC,
                             float* __restrict__ out) {
    int g = blockIdx.x;
    float S2 = SC[g * 4 + 0], S4 = SC[g * 4 + 1], SO = SC[g * 4 + 2];
    int p0 = blockIdx.y * 32, c0 = blockIdx.z * 32;
    __shared__ float tile[32][33];
    int tx = threadIdx.x, ty = threadIdx.y;
    size_t base = (size_t)g * GRP;
#pragma unroll
    for (int r = 0; r < 4; r++) {
        int p = p0 + ty + r * 8, c = c0 + tx;
        if (p < LDQ) {
            size_t idx = base + (size_t)p * 512 + c;
            float u = X[idx] * MASK[(size_t)g * LDQ + p];
            tile[ty + r * 8][tx] = SO * (S2 * u + S4 * XP[idx]);
        }
    }
    __syncthreads();
#pragma unroll
    for (int r = 0; r < 4; r++) {
        int p = p0 + tx, c = c0 + ty + r * 8;
        if (p < LDQ) out[((size_t)g * 512 + c) * LDQ + p] = tile[tx][ty + r * 8];
    }
}

// ================= launcher =================
extern "C" void kernel_launch(void* const* d_in, const int* in_sizes, int n_in,
                              void* d_out, int out_size) {
    const float* train_feat  = (const float*)d_in[0];
    const float* test_feat   = (const float*)d_in[1];
    const float* train_label = (const float*)d_in[2];
    const float* wk_self     = (const float*)d_in[3];
    const float* bk_self     = (const float*)d_in[4];
    const float* wk_cross    = (const float*)d_in[5];
    const float* bk_cross    = (const float*)d_in[6];
    float* out = (float*)d_out;

    float* base = nullptr;
    cudaGetSymbolAddress((void**)&base, g_scratch);
    float* pe     = base + OFF_PE;
    float* label  = base + OFF_LABEL;
    float* xe     = base + OFF_XE;
    float* dx0    = base + OFF_DX0;
    float* x1e    = base + OFF_X1E;
    float* mem    = base + OFF_MEM;
    float* pq     = base + OFF_PQ;
    float* dpq    = base + OFF_DPQ;
    float* pkc    = base + OFF_PKC;
    float* dx1    = base + OFF_DX1;
    float* dx     = base + OFF_DX;
    float* dxpt3  = base + OFF_DXPT3;
    float* dmask  = base + OFF_DMASK;
    float* dsc    = base + OFF_DSC;
    float* ipart  = base + OFF_IPART;
    float* dpart  = base + OFF_DPART;
    float* rsum   = base + OFF_RSUM;
    float* probs  = base + OFF_PROBS;

    dim3 tb(32, 8);

    pe_kernel<<<(HW * DD + 255) / 256, 256>>>(pe);
    label_kernel<<<(3 * BB * HW + 255) / 256, 256>>>(train_label, label);

    // ---- build both token buffers up front ----
    build_kernel<<<dim3(48, 16, 16), tb>>>(train_feat, train_feat, 3, pe, xe, 0);
    build_kernel<<<dim3(96, 16, 16), tb>>>(train_feat, test_feat, 3, pe, dx0, 1);

    // ---- merged self projection over [xe | dx0] -> [pq | dpq] ----
    const int MALL = 16 * LE + 96 * LDQ;   // 69696
    gemm_kernel<1, 1><<<dim3(1, (MALL + 127) / 128, 1), 256>>>(
        xe, wk_self, nullptr, pq, bk_self, MALL, 128, 512, 512,
        512, 512, 128, 0, 0, 0, 0, 1.0f, 0, 128);

    // ---- encoder ----
    gemm_kernel<1, 2><<<dim3(12, (LE + 127) / 128, 16), 256>>>(
        pq, pq, nullptr, probs, nullptr, LE, LE, 128, 128,
        128, 128, 1456, (size_t)LE * 128, (size_t)LE * 128, (size_t)LE * 1456,
        0, 30.0f, 0, LE);
    rowsum_kernel<<<dim3(LE, 16), 128>>>(probs, nullptr, rsum, nullptr, LE, 1456, 1456, 0);
    tf32_value_kernel<<<dim3(4, 12, 16), 256>>>(
        probs, xe, xe, x1e, rsum, nullptr, LE, 1456, LE, 1456,
        (size_t)LE * 1456, (size_t)LE * 512, (size_t)LE * 512, 0);
    inorm_part<<<dim3(48, 4), 256>>>(x1e, ipart);
    inorm_apply<<<dim3(48, 4), 256>>>(x1e, mem, ipart);
    gemm_kernel<1, 1><<<dim3(1, (16 * LE + 127) / 128, 1), 256>>>(
        mem, wk_cross, nullptr, pkc, bk_cross, 16 * LE, 128, 512, 512,
        512, 512, 128, 0, 0, 0, 0, 1.0f, 0, 128);

    // ---- decoder (96 batched) ----
    gemm_kernel<1, 2><<<dim3(4, (LDQ + 127) / 128, 96), 256>>>(
        dpq, dpq, nullptr, probs, nullptr, LDQ, LDQ, 128, 128,
        128, 128, 496, (size_t)LDQ * 128, (size_t)LDQ * 128, (size_t)LDQ * 496,
        0, 30.0f, 0, LDQ);
    rowsum_kernel<<<dim3(LDQ, 96), 128>>>(probs, nullptr, rsum, nullptr, LDQ, 496, 496, 0);
    tf32_value_kernel<<<dim3(4, 4, 96), 256>>>(
        probs, dx0, dx0, dx1, rsum, nullptr, LDQ, 496, LDQ, 496,
        (size_t)LDQ * 496, (size_t)LDQ * 512, (size_t)LDQ * 512, 0);
    inorm_part<<<dim3(96, 4), 256>>>(dx1, ipart);
    inorm_apply<<<dim3(96, 4), 256>>>(dx1, dx, ipart);
    gemm_kernel<1, 1><<<dim3(1, (96 * LDQ + 127) / 128, 1), 256>>>(
        dx, wk_cross, nullptr, dpq, bk_cross, 96 * LDQ, 128, 512, 512,
        512, 512, 128, 0, 0, 0, 0, 1.0f, 0, 128);
    gemm_kernel<1, 2><<<dim3(12, (LDQ + 127) / 128, 96), 256>>>(
        dpq, pkc, nullptr, probs, nullptr, LDQ, LE, 128, 128,
        128, 128, 1456, (size_t)LDQ * 128, (size_t)LE * 128, (size_t)LDQ * 1456,
        1, 30.0f, 0, LE);
    rowsum_kernel<<<dim3(LDQ, 96), 128>>>(probs, label, rsum, dmask, LDQ, LE, 1456, 1);
    // t3 value: P~ @ (mem * label) via fused label-weighted B staging
    tf32_value_kernel<<<dim3(4, 4, 96), 256>>>(
        probs, mem, dx, dxpt3, rsum, label, LDQ, 1456, LE, 1456,
        (size_t)LDQ * 1456, (size_t)LE * 512, (size_t)LDQ * 512, 1);
    dec_part_kernel<<<dim3(96, 4), 256>>>(dx, dxpt3, dmask, dpart);
    dec_scale_kernel<<<1, 96>>>(dpart, dsc);
    final_kernel<<<dim3(96, 16, 16), tb>>>(dx, dxpt3, dmask, dsc, out);
}

// round 12
// speedup vs baseline: 2.7733x; 1.1299x over previous
#include <cuda_runtime.h>
#include <math.h>
#include <stdint.h>

typedef unsigned long long u64;

#define BB 16
#define DD 512
#define HW 484
#define LE 1452
#define LDQ 484
#define NSCALE 0.011048543456039806f
#define DHWF 247808.0f
#define IEPS 1e-5f
#define GRP 247808
#define QF4 15488   // GRP/4/4 : float4s per quarter

// ---- scratch layout (floats) ----
#define SZ_PE     ((size_t)HW*DD)
#define SZ_LABEL  ((size_t)BB*LE)
#define SZ_XE     ((size_t)BB*LE*DD)
#define SZ_DX0    ((size_t)96*LDQ*DD)
#define SZ_PQ     ((size_t)BB*LE*128)
#define SZ_DPQ    ((size_t)96*LDQ*128)
#define SZ_DX     ((size_t)96*LDQ*DD)
#define SZ_DMASK  ((size_t)96*LDQ)
#define SZ_PROBS  ((size_t)96*LDQ*1456)
#define SZ_RSUM   ((size_t)96*LDQ)

#define OFF_PE    ((size_t)0)
#define OFF_LABEL (OFF_PE + SZ_PE)
#define OFF_XE    (OFF_LABEL + SZ_LABEL)
#define OFF_DX0   (OFF_XE + SZ_XE)          // contiguous with XE for merged proj
#define OFF_X1E   (OFF_DX0 + SZ_DX0)
#define OFF_MEM   (OFF_X1E + SZ_XE)
#define OFF_PQ    (OFF_MEM + SZ_XE)
#define OFF_DPQ   (OFF_PQ + SZ_PQ)          // contiguous with PQ for merged proj
#define OFF_PKC   (OFF_DPQ + SZ_DPQ)
#define OFF_DX1   (OFF_PKC + SZ_PQ)
#define OFF_DX    (OFF_DX1 + SZ_DX)
#define OFF_DXPT3 (OFF_DX + SZ_DX)
#define OFF_DMASK (OFF_DXPT3 + SZ_DX)
#define OFF_DSC   (OFF_DMASK + SZ_DMASK)
#define OFF_IPART (OFF_DSC + 96*4)
#define OFF_DPART (OFF_IPART + 96*4)
#define OFF_RSUM  (OFF_DPART + 96*4*3)
#define OFF_PROBS (OFF_RSUM + SZ_RSUM)
#define SCRATCH_TOTAL (OFF_PROBS + SZ_PROBS)

__device__ __align__(16) float g_scratch[SCRATCH_TOTAL];

// ---- f32x2 helpers ----
__device__ __forceinline__ u64 ffma2(u64 a, u64 b, u64 c) {
    u64 d;
    asm("fma.rn.f32x2 %0, %1, %2, %3;" : "=l"(d) : "l"(a), "l"(b), "l"(c));
    return d;
}
__device__ __forceinline__ u64 pack2(float lo, float hi) {
    u64 r;
    asm("mov.b64 %0, {%1, %2};" : "=l"(r) : "f"(lo), "f"(hi));
    return r;
}
__device__ __forceinline__ void unpack2(u64 v, float& lo, float& hi) {
    asm("mov.b64 {%0, %1}, %2;" : "=f"(lo), "=f"(hi) : "l"(v));
}
__device__ __forceinline__ uint32_t f2tf32(float f) {
    uint32_t u;
    asm("cvt.rna.tf32.f32 %0, %1;" : "=r"(u) : "f"(f));
    return u;
}
__device__ __forceinline__ void mma_tf32(float* c, uint32_t a0, uint32_t a1,
                                         uint32_t a2, uint32_t a3,
                                         uint32_t b0, uint32_t b1) {
    asm volatile("mma.sync.aligned.m16n8k8.row.col.f32.tf32.tf32.f32 "
                 "{%0,%1,%2,%3}, {%4,%5,%6,%7}, {%8,%9}, {%0,%1,%2,%3};"
                 : "+f"(c[0]), "+f"(c[1]), "+f"(c[2]), "+f"(c[3])
                 : "r"(a0), "r"(a1), "r"(a2), "r"(a3), "r"(b0), "r"(b1));
}

__device__ __forceinline__ void ld8(const float* p, bool valid, float* r) {
    if (valid) {
        float4 v0 = *(const float4*)p;
        float4 v1 = *(const float4*)(p + 4);
        r[0] = v0.x; r[1] = v0.y; r[2] = v0.z; r[3] = v0.w;
        r[4] = v1.x; r[5] = v1.y; r[6] = v1.z; r[7] = v1.w;
    } else {
#pragma unroll
        for (int j = 0; j < 8; j++) r[j] = 0.0f;
    }
}

// ============ tf32 tensor-core logits GEMM (NT) + exp epilogue ============
// C[g][m][n] = exp(30 * dot(PQ[g][m], PK[gk][n])) for n < NVALID, 0 for
// NVALID <= n < ldC.  PQ [M][128], PK [N][128] row-major, K = 128.
__global__ void __launch_bounds__(256, 2)
tf32_logits_kernel(const float* __restrict__ PQ, const float* __restrict__ PK,
                   float* __restrict__ C, int M, int N, int ldC, int NVALID,
                   size_t sA, size_t sB, size_t sC, int gkMod) {
    __shared__ __align__(16) uint32_t As[2][128][20];
    __shared__ __align__(16) uint32_t Bs[2][128][20];
    int g = blockIdx.z;
    int gk = gkMod ? (g & 15) : g;
    const float* Ag = PQ + (size_t)g * sA;
    const float* Bg = PK + (size_t)gk * sB;
    int mBase = blockIdx.y * 128, nBase = blockIdx.x * 128;
    int t = threadIdx.x, lane = t & 31, warp = t >> 5;
    int mW = (warp >> 2) * 64, nW = (warp & 3) * 32;

    int rr = t >> 1, kc = (t & 1) * 8;
    bool avalid = (mBase + rr) < M;
    bool bvalid = (nBase + rr) < N;
    const float* aPtr = Ag + (size_t)(mBase + rr) * 128 + kc;
    const float* bPtr = Bg + (size_t)(nBase + rr) * 128 + kc;

    float ra[8], rb[8];
    ld8(aPtr, avalid, ra);
    ld8(bPtr, bvalid, rb);
    {
        uint32_t ua[8], ub[8];
#pragma unroll
        for (int j = 0; j < 8; j++) { ua[j] = f2tf32(ra[j]); ub[j] = f2tf32(rb[j]); }
        *(uint4*)&As[0][rr][kc]     = make_uint4(ua[0], ua[1], ua[2], ua[3]);
        *(uint4*)&As[0][rr][kc + 4] = make_uint4(ua[4], ua[5], ua[6], ua[7]);
        *(uint4*)&Bs[0][rr][kc]     = make_uint4(ub[0], ub[1], ub[2], ub[3]);
        *(uint4*)&Bs[0][rr][kc + 4] = make_uint4(ub[4], ub[5], ub[6], ub[7]);
    }
    __syncthreads();

    float acc[4][4][4];
#pragma unroll
    for (int i = 0; i < 4; i++)
#pragma unroll
        for (int j = 0; j < 4; j++)
#pragma unroll
            for (int q = 0; q < 4; q++) acc[i][j][q] = 0.0f;

    int buf = 0;
    int lr = lane >> 2, lc = lane & 3;

    for (int k0 = 0; k0 < 128; k0 += 16) {
        int kn = k0 + 16;
        bool more = kn < 128;
        if (more) {
            ld8(aPtr + kn, avalid, ra);
            ld8(bPtr + kn, bvalid, rb);
        }
#pragma unroll
        for (int ks = 0; ks < 16; ks += 8) {
            uint32_t bf[4][2];
#pragma unroll
            for (int nt = 0; nt < 4; nt++) {
                int nn = nW + nt * 8 + lr;
                bf[nt][0] = Bs[buf][nn][ks + lc];
                bf[nt][1] = Bs[buf][nn][ks + lc + 4];
            }
#pragma unroll
            for (int mt = 0; mt < 4; mt++) {
                int r = mW + mt * 16 + lr;
                uint32_t a0 = As[buf][r][ks + lc];
                uint32_t a1 = As[buf][r + 8][ks + lc];
                uint32_t a2 = As[buf][r][ks + lc + 4];
                uint32_t a3 = As[buf][r + 8][ks + lc + 4];
#pragma unroll
                for (int nt = 0; nt < 4; nt++)
                    mma_tf32(acc[mt][nt], a0, a1, a2, a3, bf[nt][0], bf[nt][1]);
            }
        }
        if (more) {
            int nb = buf ^ 1;
            uint32_t ua[8], ub[8];
#pragma unroll
            for (int j = 0; j < 8; j++) { ua[j] = f2tf32(ra[j]); ub[j] = f2tf32(rb[j]); }
            *(uint4*)&As[nb][rr][kc]     = make_uint4(ua[0], ua[1], ua[2], ua[3]);
            *(uint4*)&As[nb][rr][kc + 4] = make_uint4(ua[4], ua[5], ua[6], ua[7]);
            *(uint4*)&Bs[nb][rr][kc]     = make_uint4(ub[0], ub[1], ub[2], ub[3]);
            *(uint4*)&Bs[nb][rr][kc + 4] = make_uint4(ub[4], ub[5], ub[6], ub[7]);
            __syncthreads();
            buf = nb;
        }
    }

    bool interior = (nBase + 128) <= NVALID;
#pragma unroll
    for (int mt = 0; mt < 4; mt++) {
        int r1 = mBase + mW + mt * 16 + lr;
        int r2 = r1 + 8;
#pragma unroll
        for (int nt = 0; nt < 4; nt++) {
            int cb = nBase + nW + nt * 8 + lc * 2;
            if (interior) {
                if (r1 < M) {
                    size_t off = (size_t)g * sC + (size_t)r1 * ldC + cb;
                    *(float2*)(C + off) = make_float2(__expf(30.0f * acc[mt][nt][0]),
                                                      __expf(30.0f * acc[mt][nt][1]));
                }
                if (r2 < M) {
                    size_t off = (size_t)g * sC + (size_t)r2 * ldC + cb;
                    *(float2*)(C + off) = make_float2(__expf(30.0f * acc[mt][nt][2]),
                                                      __expf(30.0f * acc[mt][nt][3]));
                }
            } else {
#pragma unroll
                for (int e = 0; e < 2; e++) {
                    int n = cb + e;
                    if (n >= ldC) continue;
                    if (r1 < M)
                        C[(size_t)g * sC + (size_t)r1 * ldC + n] =
                            (n < NVALID) ? __expf(30.0f * acc[mt][nt][e]) : 0.0f;
                    if (r2 < M)
                        C[(size_t)g * sC + (size_t)r2 * ldC + n] =
                            (n < NVALID) ? __expf(30.0f * acc[mt][nt][2 + e]) : 0.0f;
                }
            }
        }
    }
}

// ============ tf32 tensor-core value GEMM ============
// C[g] = RS[g][m] * (P[g] @ V[gk]) + Cin[g];  P row-major [M][Kpad] (zero-padded
// cols >= KB), V row-major [KB][512] (LABB row-scale optional). N fixed 512.
__global__ void __launch_bounds__(256, 2)
tf32_value_kernel(const float* __restrict__ P, const float* __restrict__ V,
                  const float* __restrict__ Cin, float* __restrict__ C,
                  const float* __restrict__ RS, const float* __restrict__ LABB,
                  int M, int Kpad, int KB, int ldA,
                  size_t sA, size_t sB, size_t sC, int gkMod) {
    __shared__ __align__(16) uint32_t As[2][128][20];
    __shared__ __align__(16) uint32_t Bs[2][16][136];
    int g = blockIdx.z;
    int gk = gkMod ? (g & 15) : g;
    const float* Pg = P + (size_t)g * sA;
    const float* Vg = V + (size_t)gk * sB;
    int mBase = blockIdx.y * 128, nBase = blockIdx.x * 128;
    int t = threadIdx.x, lane = t & 31, warp = t >> 5;
    int mW = (warp >> 2) * 64, nW = (warp & 3) * 32;

    int am = t >> 1, ak = (t & 1) * 8;
    bool avalid = (mBase + am) < M;
    const float* aPtr = Pg + (size_t)(mBase + am) * ldA + ak;
    int bk2 = t >> 4, bnq = (t & 15) * 8;
    const float* bPtr = Vg + (size_t)bk2 * 512 + nBase + bnq;
    const float* labRow = LABB ? (LABB + (size_t)gk * KB) : nullptr;

    float ra[8], rb[8];
    ld8(aPtr, avalid, ra);
    {
        bool bv = bk2 < KB;
        ld8(bPtr, bv, rb);
        if (labRow && bv) {
            float lb = labRow[bk2];
#pragma unroll
            for (int j = 0; j < 8; j++) rb[j] *= lb;
        }
    }
    {
        uint32_t ua[8], ub[8];
#pragma unroll
        for (int j = 0; j < 8; j++) { ua[j] = f2tf32(ra[j]); ub[j] = f2tf32(rb[j]); }
        *(uint4*)&As[0][am][ak]     = make_uint4(ua[0], ua[1], ua[2], ua[3]);
        *(uint4*)&As[0][am][ak + 4] = make_uint4(ua[4], ua[5], ua[6], ua[7]);
        *(uint4*)&Bs[0][bk2][bnq]     = make_uint4(ub[0], ub[1], ub[2], ub[3]);
        *(uint4*)&Bs[0][bk2][bnq + 4] = make_uint4(ub[4], ub[5], ub[6], ub[7]);
    }
    __syncthreads();

    float acc[4][4][4];
#pragma unroll
    for (int i = 0; i < 4; i++)
#pragma unroll
        for (int j = 0; j < 4; j++)
#pragma unroll
            for (int q = 0; q < 4; q++) acc[i][j][q] = 0.0f;

    int buf = 0;
    int lr = lane >> 2, lc = lane & 3;

    for (int k0 = 0; k0 < Kpad; k0 += 16) {
        int kn = k0 + 16;
        bool more = kn < Kpad;
        if (more) {
            ld8(aPtr + kn, avalid, ra);
            bool bv = (kn + bk2) < KB;
            ld8(bPtr + (size_t)kn * 512, bv, rb);
            if (labRow && bv) {
                float lb = labRow[kn + bk2];
#pragma unroll
                for (int j = 0; j < 8; j++) rb[j] *= lb;
            }
        }
#pragma unroll
        for (int ks = 0; ks < 16; ks += 8) {
            uint32_t bf[4][2];
#pragma unroll
            for (int nt = 0; nt < 4; nt++) {
                int cc = nW + nt * 8 + lr;
                bf[nt][0] = Bs[buf][ks + lc][cc];
                bf[nt][1] = Bs[buf][ks + lc + 4][cc];
            }
#pragma unroll
            for (int mt = 0; mt < 4; mt++) {
                int r = mW + mt * 16 + lr;
                uint32_t a0 = As[buf][r][ks + lc];
                uint32_t a1 = As[buf][r + 8][ks + lc];
                uint32_t a2 = As[buf][r][ks + lc + 4];
                uint32_t a3 = As[buf][r + 8][ks + lc + 4];
#pragma unroll
                for (int nt = 0; nt < 4; nt++)
                    mma_tf32(acc[mt][nt], a0, a1, a2, a3, bf[nt][0], bf[nt][1]);
            }
        }
        if (more) {
            int nb = buf ^ 1;
            uint32_t ua[8], ub[8];
#pragma unroll
            for (int j = 0; j < 8; j++) { ua[j] = f2tf32(ra[j]); ub[j] = f2tf32(rb[j]); }
            *(uint4*)&As[nb][am][ak]     = make_uint4(ua[0], ua[1], ua[2], ua[3]);
            *(uint4*)&As[nb][am][ak + 4] = make_uint4(ua[4], ua[5], ua[6], ua[7]);
            *(uint4*)&Bs[nb][bk2][bnq]     = make_uint4(ub[0], ub[1], ub[2], ub[3]);
            *(uint4*)&Bs[nb][bk2][bnq + 4] = make_uint4(ub[4], ub[5], ub[6], ub[7]);
            __syncthreads();
            buf = nb;
        }
    }

    // epilogue: rs * acc + Cin
#pragma unroll
    for (int mt = 0; mt < 4; mt++) {
        int r1 = mBase + mW + mt * 16 + lr;
        int r2 = r1 + 8;
        float rs1 = (r1 < M) ? RS[(size_t)g * M + r1] : 0.0f;
        float rs2 = (r2 < M) ? RS[(size_t)g * M + r2] : 0.0f;
#pragma unroll
        for (int nt = 0; nt < 4; nt++) {
            int cb = nBase + nW + nt * 8 + lc * 2;
            if (r1 < M) {
                size_t off = (size_t)g * sC + (size_t)r1 * 512 + cb;
                float2 ci = *(const float2*)(Cin + off);
                float2 o;
                o.x = rs1 * acc[mt][nt][0] + ci.x;
                o.y = rs1 * acc[mt][nt][1] + ci.y;
                *(float2*)(C + off) = o;
            }
            if (r2 < M) {
                size_t off = (size_t)g * sC + (size_t)r2 * 512 + cb;
                float2 ci = *(const float2*)(Cin + off);
                float2 o;
                o.x = rs2 * acc[mt][nt][2] + ci.x;
                o.y = rs2 * acc[mt][nt][3] + ci.y;
                *(float2*)(C + off) = o;
            }
        }
    }
}

// ============ f32x2 projection GEMM (exact; bias + L2-normalize epilogue) ====
__global__ void __launch_bounds__(256, 2)
proj_kernel(const float* __restrict__ A, const float* __restrict__ B,
            float* __restrict__ C, const float* __restrict__ AUX, int M) {
    __shared__ float As[2][16][132];
    __shared__ float Bs[2][16][132];
    const float* Ag = A;
    const float* Bg = B;
    int mBase = blockIdx.y * 128;
    int t = threadIdx.x;

    int am = t >> 1, ak = (t & 1) * 8;
    bool avalid = (mBase + am) < M;
    const float* aPtr = Ag + (size_t)(mBase + am) * 512 + ak;
    int bn = t >> 1, bk = (t & 1) * 8;
    const float* bPtrT = Bg + (size_t)bn * 512 + bk;

    float ra[8], rb[8];
    ld8(aPtr, avalid, ra);
    ld8(bPtrT, true, rb);

#pragma unroll
    for (int j = 0; j < 8; j++) As[0][ak + j][am] = ra[j];
#pragma unroll
    for (int j = 0; j < 8; j++) Bs[0][bk + j][bn] = rb[j];
    __syncthreads();

    u64 acc[8][4];
#pragma unroll
    for (int i = 0; i < 8; i++)
#pragma unroll
        for (int j = 0; j < 4; j++) acc[i][j] = 0ull;

    int m0 = (t >> 4) * 8;
    int nA = (t & 15) * 4;
    int buf = 0;

    for (int k0 = 0; k0 < 512; k0 += 16) {
        int kn = k0 + 16;
        bool more = kn < 512;
        if (more) {
            ld8(aPtr + kn, avalid, ra);
            ld8(bPtrT + kn, true, rb);
        }
        ulonglong2 pbA[2], pbB[2];
        float4 pa0[2], pa1[2];
        pbA[0] = *(const ulonglong2*)&Bs[buf][0][nA];
        pbB[0] = *(const ulonglong2*)&Bs[buf][0][nA + 64];
        pa0[0] = *(const float4*)&As[buf][0][m0];
        pa1[0] = *(const float4*)&As[buf][0][m0 + 4];
#pragma unroll
        for (int kk = 0; kk < 16; kk++) {
            int cur = kk & 1, nxt = cur ^ 1;
            if (kk < 15) {
                pbA[nxt] = *(const ulonglong2*)&Bs[buf][kk + 1][nA];
                pbB[nxt] = *(const ulonglong2*)&Bs[buf][kk + 1][nA + 64];
                pa0[nxt] = *(const float4*)&As[buf][kk + 1][m0];
                pa1[nxt] = *(const float4*)&As[buf][kk + 1][m0 + 4];
            }
            float av[8] = {pa0[cur].x, pa0[cur].y, pa0[cur].z, pa0[cur].w,
                           pa1[cur].x, pa1[cur].y, pa1[cur].z, pa1[cur].w};
#pragma unroll
            for (int i = 0; i < 8; i++) {
                u64 ad = pack2(av[i], av[i]);
                acc[i][0] = ffma2(ad, pbA[cur].x, acc[i][0]);
                acc[i][1] = ffma2(ad, pbA[cur].y, acc[i][1]);
                acc[i][2] = ffma2(ad, pbB[cur].x, acc[i][2]);
                acc[i][3] = ffma2(ad, pbB[cur].y, acc[i][3]);
            }
        }
        if (more) {
            int nb = buf ^ 1;
#pragma unroll
            for (int j = 0; j < 8; j++) As[nb][ak + j][am] = ra[j];
#pragma unroll
            for (int j = 0; j < 8; j++) Bs[nb][bk + j][bn] = rb[j];
            __syncthreads();
            buf = nb;
        }
    }

    float bkv[8];
#pragma unroll
    for (int s = 0; s < 2; s++)
#pragma unroll
        for (int j = 0; j < 4; j++) bkv[s * 4 + j] = AUX[nA + s * 64 + j];
#pragma unroll
    for (int i = 0; i < 8; i++) {
        int m = mBase + m0 + i;
        float o[8];
#pragma unroll
        for (int j = 0; j < 4; j++) unpack2(acc[i][j], o[2 * j], o[2 * j + 1]);
        float ss = 0.0f;
#pragma unroll
        for (int j = 0; j < 8; j++) {
            o[j] += bkv[j];
            ss += o[j] * o[j];
        }
#pragma unroll
        for (int d = 8; d; d >>= 1) ss += __shfl_xor_sync(0xffffffffu, ss, d, 16);
        float rn = 1.0f / fmaxf(sqrtf(ss), 1e-12f);
        if (m < M) {
            size_t off = (size_t)m * 128;
            *(float4*)(C + off + nA)      = make_float4(o[0] * rn, o[1] * rn, o[2] * rn, o[3] * rn);
            *(float4*)(C + off + nA + 64) = make_float4(o[4] * rn, o[5] * rn, o[6] * rn, o[7] * rn);
        }
    }
}

// ================= small kernels =================
__global__ void pe_kernel(float* __restrict__ pe) {
    int idx = blockIdx.x * 256 + threadIdx.x;
    if (idx >= HW * DD) return;
    int p = idx >> 9, c = idx & 511;
    float pos = (float)(p + 1);
    int j = c & 255;
    float f = powf(10000.0f, -(float)j * (1.0f / 256.0f));
    float a = pos * f;
    pe[idx] = (c < 256) ? sinf(a) : cosf(a);
}

__global__ void label_kernel(const float* __restrict__ lab, float* __restrict__ out) {
    int idx = blockIdx.x * 256 + threadIdx.x;
    if (idx >= 3 * BB * HW) return;
    int p = idx % HW;
    int t = idx / HW;
    int b = t % BB;
    int ni = t / BB;
    out[(size_t)b * LE + ni * HW + p] = lab[idx];
}

__global__ void build_kernel(const float* __restrict__ fa, const float* __restrict__ fb,
                             int split, const float* __restrict__ pe,
                             float* __restrict__ xout, int mode) {
    int g = blockIdx.x;
    int img = g >> 4, b = g & 15;
    const float* f = (img < split) ? (fa + (size_t)img * BB * DD * HW)
                                   : (fb + (size_t)(img - split) * BB * DD * HW);
    int p0 = blockIdx.y * 32, c0 = blockIdx.z * 32;
    __shared__ float tl[32][33];
    int tx = threadIdx.x, ty = threadIdx.y;
#pragma unroll
    for (int r = 0; r < 4; r++) {
        int c = c0 + ty + r * 8, p = p0 + tx;
        if (p < HW) tl[ty + r * 8][tx] = f[((size_t)b * DD + c) * HW + p];
    }
    __syncthreads();
#pragma unroll
    for (int r = 0; r < 4; r++) {
        int p = p0 + ty + r * 8, c = c0 + tx;
        if (p < HW) {
            size_t row = (mode == 0) ? ((size_t)b * LE + (size_t)img * HW + p)
                                     : ((size_t)g * LDQ + p);
            xout[row * DD + c] = tl[tx][ty + r * 8] + pe[(size_t)p * DD + c] * 1e-3f;
        }
    }
}

// row sums of exp'd probs -> 1/sum (and mask = sum(p*label)/sum when LABEL)
__global__ void rowsum_kernel(const float* __restrict__ P, const float* __restrict__ LABEL,
                              float* __restrict__ RS, float* __restrict__ MASKOUT,
                              int Mrows, int Lk, int ld, int gkMod) {
    int q = blockIdx.x, g = blockIdx.y, t = threadIdx.x;   // 128 threads
    int gk = gkMod ? (g & 15) : g;
    const float4* p4 = (const float4*)(P + ((size_t)g * Mrows + q) * ld);
    int n4 = Lk >> 2;
    float s = 0.0f, ms = 0.0f;
    if (LABEL) {
        const float4* l4 = (const float4*)(LABEL + (size_t)gk * Lk);
        for (int i = t; i < n4; i += 128) {
            float4 v = p4[i];
            float4 lv = l4[i];
            s += v.x + v.y + v.z + v.w;
            ms += v.x * lv.x + v.y * lv.y + v.z * lv.z + v.w * lv.w;
        }
    } else {
        for (int i = t; i < n4; i += 128) {
            float4 v = p4[i];
            s += v.x + v.y + v.z + v.w;
        }
    }
    __shared__ float rs_[4], rm_[4];
#pragma unroll
    for (int m = 16; m; m >>= 1) {
        s += __shfl_xor_sync(0xffffffffu, s, m);
        ms += __shfl_xor_sync(0xffffffffu, ms, m);
    }
    if ((t & 31) == 0) { rs_[t >> 5] = s; rm_[t >> 5] = ms; }
    __syncthreads();
    if (t == 0) {
        float st = rs_[0] + rs_[1] + rs_[2] + rs_[3];
        float inv = 1.0f / st;
        RS[(size_t)g * Mrows + q] = inv;
        if (MASKOUT) {
            float mt = rm_[0] + rm_[1] + rm_[2] + rm_[3];
            MASKOUT[(size_t)g * Mrows + q] = mt * inv;
        }
    }
}

// InstanceL2Norm: partial sums then apply (deterministic 2-stage)
__global__ void inorm_part(const float* __restrict__ in, float* __restrict__ part) {
    int g = blockIdx.x, q = blockIdx.y, t = threadIdx.x;
    const float4* ip = (const float4*)(in + (size_t)g * GRP) + (size_t)q * QF4;
    float ss = 0.0f;
    for (int i = t; i < QF4; i += 256) {
        float4 v = ip[i];
        ss += v.x * v.x + v.y * v.y + v.z * v.z + v.w * v.w;
    }
    __shared__ float red[8];
#pragma unroll
    for (int m = 16; m; m >>= 1) ss += __shfl_xor_sync(0xffffffffu, ss, m);
    if ((t & 31) == 0) red[t >> 5] = ss;
    __syncthreads();
    if (t == 0) {
        float s = 0.0f;
#pragma unroll
        for (int i = 0; i < 8; i++) s += red[i];
        part[g * 4 + q] = s;
    }
}

__global__ void inorm_apply(const float* __restrict__ in, float* __restrict__ out,
                            const float* __restrict__ part) {
    int g = blockIdx.x, q = blockIdx.y, t = threadIdx.x;
    float ss = part[g * 4 + 0] + part[g * 4 + 1] + part[g * 4 + 2] + part[g * 4 + 3];
    float sc = NSCALE * sqrtf(DHWF / (ss + IEPS));
    const float4* ip = (const float4*)(in + (size_t)g * GRP) + (size_t)q * QF4;
    float4* op = (float4*)(out + (size_t)g * GRP) + (size_t)q * QF4;
    for (int i = t; i < QF4; i += 256) {
        float4 v = ip[i];
        v.x *= sc; v.y *= sc; v.z *= sc; v.w *= sc;
        op[i] = v;
    }
}

// decoder 3-sum partials: u = x*mask, v = x + t3
__global__ void dec_part_kernel(const float* __restrict__ X, const float* __restrict__ XP,
                                const float* __restrict__ MASK, float* __restrict__ part) {
    int g = blockIdx.x, q = blockIdx.y, t = threadIdx.x;
    const float4* x4 = (const float4*)(X + (size_t)g * GRP);
    const float4* p4 = (const float4*)(XP + (size_t)g * GRP);
    const float* mk = MASK + (size_t)g * LDQ;
    float s2 = 0.0f, s4 = 0.0f, cr = 0.0f;
    for (int i = t; i < QF4; i += 256) {
        int gi = q * QF4 + i;
        float m = mk[gi >> 7];
        float4 x = x4[gi];
        float4 v = p4[gi];
        float ux = x.x * m, uy = x.y * m, uz = x.z * m, uw = x.w * m;
        s2 += ux * ux + uy * uy + uz * uz + uw * uw;
        s4 += v.x * v.x + v.y * v.y + v.z * v.z + v.w * v.w;
        cr += ux * v.x + uy * v.y + uz * v.z + uw * v.w;
    }
    __shared__ float r2[8], r4[8], rc[8];
#pragma unroll
    for (int m = 16; m; m >>= 1) {
        s2 += __shfl_xor_sync(0xffffffffu, s2, m);
        s4 += __shfl_xor_sync(0xffffffffu, s4, m);
        cr += __shfl_xor_sync(0xffffffffu, cr, m);
    }
    if ((t & 31) == 0) { r2[t >> 5] = s2; r4[t >> 5] = s4; rc[t >> 5] = cr; }
    __syncthreads();
    if (t == 0) {
        float a = 0, b = 0, c = 0;
#pragma unroll
        for (int i = 0; i < 8; i++) { a += r2[i]; b += r4[i]; c += rc[i]; }
        part[(g * 4 + q) * 3 + 0] = a;
        part[(g * 4 + q) * 3 + 1] = b;
        part[(g * 4 + q) * 3 + 2] = c;
    }
}

__global__ void dec_scale_kernel(const float* __restrict__ part, float* __restrict__ SC) {
    int g = threadIdx.x;
    if (g >= 96) return;
    float a = 0, b = 0, c = 0;
#pragma unroll
    for (int q = 0; q < 4; q++) {
        a += part[(g * 4 + q) * 3 + 0];
        b += part[(g * 4 + q) * 3 + 1];
        c += part[(g * 4 + q) * 3 + 2];
    }
    float S2 = NSCALE * sqrtf(DHWF / (a + IEPS));
    float S4 = NSCALE * sqrtf(DHWF / (b + IEPS));
    float sso = S2 * S2 * a + 2.0f * S2 * S4 * c + S4 * S4 * b;
    float SO = NSCALE * sqrtf(DHWF / (sso + IEPS));
    SC[g * 4 + 0] = S2;
    SC[g * 4 + 1] = S4;
    SC[g * 4 + 2] = SO;
}

__global__ void final_kernel(const float* __restrict__ X, const float* __restrict__ XP,
                             const float* __restrict__ MASK, const float* __restrict__ SC,
                             float* __restrict__ out) {
    int g = blockIdx.x;
    float S2 = SC[g * 4 + 0], S4 = SC[g * 4 + 1], SO = SC[g * 4 + 2];
    int p0 = blockIdx.y * 32, c0 = blockIdx.z * 32;
    __shared__ float tile[32][33];
    int tx = threadIdx.x, ty = threadIdx.y;
    size_t base = (size_t)g * GRP;
#pragma unroll
    for (int r = 0; r < 4; r++) {
        int p = p0 + ty + r * 8, c = c0 + tx;
        if (p < LDQ) {
            size_t idx = base + (size_t)p * 512 + c;
            float u = X[idx] * MASK[(size_t)g * LDQ + p];
            tile[ty + r * 8][tx] = SO * (S2 * u + S4 * XP[idx]);
        }
    }
    __syncthreads();
#pragma unroll
    for (int r = 0; r < 4; r++) {
        int p = p0 + tx, c = c0 + ty + r * 8;
        if (p < LDQ) out[((size_t)g * 512 + c) * LDQ + p] = tile[tx][ty + r * 8];
    }
}

// ================= launcher =================
extern "C" void kernel_launch(void* const* d_in, const int* in_sizes, int n_in,
                              void* d_out, int out_size) {
    const float* train_feat  = (const float*)d_in[0];
    const float* test_feat   = (const float*)d_in[1];
    const float* train_label = (const float*)d_in[2];
    const float* wk_self     = (const float*)d_in[3];
    const float* bk_self     = (const float*)d_in[4];
    const float* wk_cross    = (const float*)d_in[5];
    const float* bk_cross    = (const float*)d_in[6];
    float* out = (float*)d_out;

    float* base = nullptr;
    cudaGetSymbolAddress((void**)&base, g_scratch);
    float* pe     = base + OFF_PE;
    float* label  = base + OFF_LABEL;
    float* xe     = base + OFF_XE;
    float* dx0    = base + OFF_DX0;
    float* x1e    = base + OFF_X1E;
    float* mem    = base + OFF_MEM;
    float* pq     = base + OFF_PQ;
    float* dpq    = base + OFF_DPQ;
    float* pkc    = base + OFF_PKC;
    float* dx1    = base + OFF_DX1;
    float* dx     = base + OFF_DX;
    float* dxpt3  = base + OFF_DXPT3;
    float* dmask  = base + OFF_DMASK;
    float* dsc    = base + OFF_DSC;
    float* ipart  = base + OFF_IPART;
    float* dpart  = base + OFF_DPART;
    float* rsum   = base + OFF_RSUM;
    float* probs  = base + OFF_PROBS;

    dim3 tb(32, 8);

    pe_kernel<<<(HW * DD + 255) / 256, 256>>>(pe);
    label_kernel<<<(3 * BB * HW + 255) / 256, 256>>>(train_label, label);

    // ---- build both token buffers up front ----
    build_kernel<<<dim3(48, 16, 16), tb>>>(train_feat, train_feat, 3, pe, xe, 0);
    build_kernel<<<dim3(96, 16, 16), tb>>>(train_feat, test_feat, 3, pe, dx0, 1);

    // ---- merged self projection over [xe | dx0] -> [pq | dpq] ----
    const int MALL = 16 * LE + 96 * LDQ;   // 69696
    proj_kernel<<<dim3(1, (MALL + 127) / 128, 1), 256>>>(xe, wk_self, pq, bk_self, MALL);

    // ---- encoder ----
    tf32_logits_kernel<<<dim3(12, 12, 16), 256>>>(
        pq, pq, probs, LE, LE, 1456, LE,
        (size_t)LE * 128, (size_t)LE * 128, (size_t)LE * 1456, 0);
    rowsum_kernel<<<dim3(LE, 16), 128>>>(probs, nullptr, rsum, nullptr, LE, 1456, 1456, 0);
    tf32_value_kernel<<<dim3(4, 12, 16), 256>>>(
        probs, xe, xe, x1e, rsum, nullptr, LE, 1456, LE, 1456,
        (size_t)LE * 1456, (size_t)LE * 512, (size_t)LE * 512, 0);
    inorm_part<<<dim3(48, 4), 256>>>(x1e, ipart);
    inorm_apply<<<dim3(48, 4), 256>>>(x1e, mem, ipart);
    proj_kernel<<<dim3(1, (16 * LE + 127) / 128, 1), 256>>>(mem, wk_cross, pkc, bk_cross, 16 * LE);

    // ---- decoder (96 batched) ----
    tf32_logits_kernel<<<dim3(4, 4, 96), 256>>>(
        dpq, dpq, probs, LDQ, LDQ, 496, LDQ,
        (size_t)LDQ * 128, (size_t)LDQ * 128, (size_t)LDQ * 496, 0);
    rowsum_kernel<<<dim3(LDQ, 96), 128>>>(probs, nullptr, rsum, nullptr, LDQ, 496, 496, 0);
    tf32_value_kernel<<<dim3(4, 4, 96), 256>>>(
        probs, dx0, dx0, dx1, rsum, nullptr, LDQ, 496, LDQ, 496,
        (size_t)LDQ * 496, (size_t)LDQ * 512, (size_t)LDQ * 512, 0);
    inorm_part<<<dim3(96, 4), 256>>>(dx1, ipart);
    inorm_apply<<<dim3(96, 4), 256>>>(dx1, dx, ipart);
    proj_kernel<<<dim3(1, (96 * LDQ + 127) / 128, 1), 256>>>(dx, wk_cross, dpq, bk_cross, 96 * LDQ);
    tf32_logits_kernel<<<dim3(12, 4, 96), 256>>>(
        dpq, pkc, probs, LDQ, LE, 1456, LE,
        (size_t)LDQ * 128, (size_t)LE * 128, (size_t)LDQ * 1456, 1);
    rowsum_kernel<<<dim3(LDQ, 96), 128>>>(probs, label, rsum, dmask, LDQ, LE, 1456, 1);
    // t3 value: P~ @ (mem * label) via fused label-weighted B staging
    tf32_value_kernel<<<dim3(4, 4, 96), 256>>>(
        probs, mem, dx, dxpt3, rsum, label, LDQ, 1456, LE, 1456,
        (size_t)LDQ * 1456, (size_t)LE * 512, (size_t)LDQ * 512, 1);
    dec_part_kernel<<<dim3(96, 4), 256>>>(dx, dxpt3, dmask, dpart);
    dec_scale_kernel<<<1, 96>>>(dpart, dsc);
    final_kernel<<<dim3(96, 16, 16), tb>>>(dx, dxpt3, dmask, dsc, out);
}

// round 13
// speedup vs baseline: 3.1529x; 1.1369x over previous
#include <cuda_runtime.h>
#include <math.h>
#include <stdint.h>

#define BB 16
#define DD 512
#define HW 484
#define LE 1452
#define LDQ 484
#define NSCALE 0.011048543456039806f
#define DHWF 247808.0f
#define IEPS 1e-5f
#define GRP 247808
#define QF4 15488   // GRP/4/4 : float4s per quarter

// ---- scratch layout (floats) ----
#define SZ_PE     ((size_t)HW*DD)
#define SZ_LABEL  ((size_t)BB*LE)
#define SZ_XE     ((size_t)BB*LE*DD)
#define SZ_DX0    ((size_t)96*LDQ*DD)
#define SZ_PQ     ((size_t)BB*LE*128)
#define SZ_DPQ    ((size_t)96*LDQ*128)
#define SZ_DMASK  ((size_t)96*LDQ)
#define SZ_PROBS  ((size_t)96*LDQ*1456)

#define OFF_PE    ((size_t)0)
#define OFF_LABEL (OFF_PE + SZ_PE)
#define OFF_XE    (OFF_LABEL + SZ_LABEL)
#define OFF_DX0   (OFF_XE + SZ_XE)          // [xe|dx0] contiguous (self proj in)
#define OFF_PQ    (OFF_DX0 + SZ_DX0)
#define OFF_DPQ   (OFF_PQ + SZ_PQ)          // [pq|dpq] contiguous (self proj out)
#define OFF_MEM   (OFF_DPQ + SZ_DPQ)
#define OFF_DX    (OFF_MEM + SZ_XE)         // [mem|dx] contiguous (cross proj in)
#define OFF_PKC   (OFF_DX + SZ_DX0)
#define OFF_DPQ2  (OFF_PKC + SZ_PQ)         // [pkc|dpq2] contiguous (cross proj out)
#define OFF_X1E   (OFF_DPQ2 + SZ_DPQ)
#define OFF_DX1   (OFF_X1E + SZ_XE)
#define OFF_DXPT3 (OFF_DX1 + SZ_DX0)
#define OFF_DMASK (OFF_DXPT3 + SZ_DX0)
#define OFF_DSC   (OFF_DMASK + SZ_DMASK)
#define OFF_IPART (OFF_DSC + 96*4)
#define OFF_DPART (OFF_IPART + 96*4)
#define OFF_PROBS (OFF_DPART + 96*4*3)
#define SCRATCH_TOTAL (OFF_PROBS + SZ_PROBS)

__device__ __align__(16) float g_scratch[SCRATCH_TOTAL];

// ---- tf32 helpers ----
__device__ __forceinline__ uint32_t f2tf32(float f) {
    uint32_t u;
    asm("cvt.rna.tf32.f32 %0, %1;" : "=r"(u) : "f"(f));
    return u;
}
__device__ __forceinline__ void mma_tf32(float* c, uint32_t a0, uint32_t a1,
                                         uint32_t a2, uint32_t a3,
                                         uint32_t b0, uint32_t b1) {
    asm volatile("mma.sync.aligned.m16n8k8.row.col.f32.tf32.tf32.f32 "
                 "{%0,%1,%2,%3}, {%4,%5,%6,%7}, {%8,%9}, {%0,%1,%2,%3};"
                 : "+f"(c[0]), "+f"(c[1]), "+f"(c[2]), "+f"(c[3])
                 : "r"(a0), "r"(a1), "r"(a2), "r"(a3), "r"(b0), "r"(b1));
}

__device__ __forceinline__ void ld8(const float* p, bool valid, float* r) {
    if (valid) {
        float4 v0 = *(const float4*)p;
        float4 v1 = *(const float4*)(p + 4);
        r[0] = v0.x; r[1] = v0.y; r[2] = v0.z; r[3] = v0.w;
        r[4] = v1.x; r[5] = v1.y; r[6] = v1.z; r[7] = v1.w;
    } else {
#pragma unroll
        for (int j = 0; j < 8; j++) r[j] = 0.0f;
    }
}

// ============ tf32 projection GEMM (NT, K=512, N=128) + bias + L2norm ======
// C[m] = normalize(A[m] @ W^T + BIAS);  A [M][512], W [128][512] row-major.
__global__ void __launch_bounds__(256, 2)
tf32_proj_kernel(const float* __restrict__ A, const float* __restrict__ W,
                 float* __restrict__ C, const float* __restrict__ BIAS, int M) {
    __shared__ __align__(16) uint32_t As[2][128][20];
    __shared__ __align__(16) uint32_t Bs[2][128][20];
    __shared__ float ssq[128][4];
    int mBase = blockIdx.y * 128;
    int t = threadIdx.x, lane = t & 31, warp = t >> 5;
    int mW = (warp >> 2) * 64, nW = (warp & 3) * 32;

    int rr = t >> 1, kc = (t & 1) * 8;
    bool avalid = (mBase + rr) < M;
    const float* aPtr = A + (size_t)(mBase + rr) * 512 + kc;
    const float* bPtr = W + (size_t)rr * 512 + kc;

    float ra[8], rb[8];
    ld8(aPtr, avalid, ra);
    ld8(bPtr, true, rb);
    {
        uint32_t ua[8], ub[8];
#pragma unroll
        for (int j = 0; j < 8; j++) { ua[j] = f2tf32(ra[j]); ub[j] = f2tf32(rb[j]); }
        *(uint4*)&As[0][rr][kc]     = make_uint4(ua[0], ua[1], ua[2], ua[3]);
        *(uint4*)&As[0][rr][kc + 4] = make_uint4(ua[4], ua[5], ua[6], ua[7]);
        *(uint4*)&Bs[0][rr][kc]     = make_uint4(ub[0], ub[1], ub[2], ub[3]);
        *(uint4*)&Bs[0][rr][kc + 4] = make_uint4(ub[4], ub[5], ub[6], ub[7]);
    }
    __syncthreads();

    float acc[4][4][4];
#pragma unroll
    for (int i = 0; i < 4; i++)
#pragma unroll
        for (int j = 0; j < 4; j++)
#pragma unroll
            for (int q = 0; q < 4; q++) acc[i][j][q] = 0.0f;

    int buf = 0;
    int lr = lane >> 2, lc = lane & 3;

    for (int k0 = 0; k0 < 512; k0 += 16) {
        int kn = k0 + 16;
        bool more = kn < 512;
        if (more) {
            ld8(aPtr + kn, avalid, ra);
            ld8(bPtr + kn, true, rb);
        }
#pragma unroll
        for (int ks = 0; ks < 16; ks += 8) {
            uint32_t bf[4][2];
#pragma unroll
            for (int nt = 0; nt < 4; nt++) {
                int nn = nW + nt * 8 + lr;
                bf[nt][0] = Bs[buf][nn][ks + lc];
                bf[nt][1] = Bs[buf][nn][ks + lc + 4];
            }
#pragma unroll
            for (int mt = 0; mt < 4; mt++) {
                int r = mW + mt * 16 + lr;
                uint32_t a0 = As[buf][r][ks + lc];
                uint32_t a1 = As[buf][r + 8][ks + lc];
                uint32_t a2 = As[buf][r][ks + lc + 4];
                uint32_t a3 = As[buf][r + 8][ks + lc + 4];
#pragma unroll
                for (int nt = 0; nt < 4; nt++)
                    mma_tf32(acc[mt][nt], a0, a1, a2, a3, bf[nt][0], bf[nt][1]);
            }
        }
        if (more) {
            int nb = buf ^ 1;
            uint32_t ua[8], ub[8];
#pragma unroll
            for (int j = 0; j < 8; j++) { ua[j] = f2tf32(ra[j]); ub[j] = f2tf32(rb[j]); }
            *(uint4*)&As[nb][rr][kc]     = make_uint4(ua[0], ua[1], ua[2], ua[3]);
            *(uint4*)&As[nb][rr][kc + 4] = make_uint4(ua[4], ua[5], ua[6], ua[7]);
            *(uint4*)&Bs[nb][rr][kc]     = make_uint4(ub[0], ub[1], ub[2], ub[3]);
            *(uint4*)&Bs[nb][rr][kc + 4] = make_uint4(ub[4], ub[5], ub[6], ub[7]);
            __syncthreads();
            buf = nb;
        }
    }

    // bias + per-row sum of squares (cross-warp via smem)
    float bv[4][2];
#pragma unroll
    for (int nt = 0; nt < 4; nt++) {
        bv[nt][0] = BIAS[nW + nt * 8 + lc * 2];
        bv[nt][1] = BIAS[nW + nt * 8 + lc * 2 + 1];
    }
#pragma unroll
    for (int mt = 0; mt < 4; mt++) {
        float p1 = 0.0f, p2 = 0.0f;
#pragma unroll
        for (int nt = 0; nt < 4; nt++) {
            acc[mt][nt][0] += bv[nt][0];
            acc[mt][nt][1] += bv[nt][1];
            acc[mt][nt][2] += bv[nt][0];
            acc[mt][nt][3] += bv[nt][1];
            p1 += acc[mt][nt][0] * acc[mt][nt][0] + acc[mt][nt][1] * acc[mt][nt][1];
            p2 += acc[mt][nt][2] * acc[mt][nt][2] + acc[mt][nt][3] * acc[mt][nt][3];
        }
        p1 += __shfl_xor_sync(0xffffffffu, p1, 1);
        p1 += __shfl_xor_sync(0xffffffffu, p1, 2);
        p2 += __shfl_xor_sync(0xffffffffu, p2, 1);
        p2 += __shfl_xor_sync(0xffffffffu, p2, 2);
        if (lc == 0) {
            ssq[mW + mt * 16 + lr][warp & 3] = p1;
            ssq[mW + mt * 16 + lr + 8][warp & 3] = p2;
        }
    }
    __syncthreads();
#pragma unroll
    for (int mt = 0; mt < 4; mt++) {
        int l1 = mW + mt * 16 + lr, l2 = l1 + 8;
        float s1 = ssq[l1][0] + ssq[l1][1] + ssq[l1][2] + ssq[l1][3];
        float s2 = ssq[l2][0] + ssq[l2][1] + ssq[l2][2] + ssq[l2][3];
        float rn1 = 1.0f / fmaxf(sqrtf(s1), 1e-12f);
        float rn2 = 1.0f / fmaxf(sqrtf(s2), 1e-12f);
        int r1 = mBase + l1, r2 = mBase + l2;
#pragma unroll
        for (int nt = 0; nt < 4; nt++) {
            int cb = nW + nt * 8 + lc * 2;
            if (r1 < M)
                *(float2*)(C + (size_t)r1 * 128 + cb) =
                    make_float2(acc[mt][nt][0] * rn1, acc[mt][nt][1] * rn1);
            if (r2 < M)
                *(float2*)(C + (size_t)r2 * 128 + cb) =
                    make_float2(acc[mt][nt][2] * rn2, acc[mt][nt][3] * rn2);
        }
    }
}

// ============ tf32 logits GEMM (NT) + exp epilogue ============
__global__ void __launch_bounds__(256, 2)
tf32_logits_kernel(const float* __restrict__ PQ, const float* __restrict__ PK,
                   float* __restrict__ C, int M, int N, int ldC, int NVALID,
                   size_t sA, size_t sB, size_t sC, int gkMod) {
    __shared__ __align__(16) uint32_t As[2][128][20];
    __shared__ __align__(16) uint32_t Bs[2][128][20];
    int g = blockIdx.z;
    int gk = gkMod ? (g & 15) : g;
    const float* Ag = PQ + (size_t)g * sA;
    const float* Bg = PK + (size_t)gk * sB;
    int mBase = blockIdx.y * 128, nBase = blockIdx.x * 128;
    int t = threadIdx.x, lane = t & 31, warp = t >> 5;
    int mW = (warp >> 2) * 64, nW = (warp & 3) * 32;

    int rr = t >> 1, kc = (t & 1) * 8;
    bool avalid = (mBase + rr) < M;
    bool bvalid = (nBase + rr) < N;
    const float* aPtr = Ag + (size_t)(mBase + rr) * 128 + kc;
    const float* bPtr = Bg + (size_t)(nBase + rr) * 128 + kc;

    float ra[8], rb[8];
    ld8(aPtr, avalid, ra);
    ld8(bPtr, bvalid, rb);
    {
        uint32_t ua[8], ub[8];
#pragma unroll
        for (int j = 0; j < 8; j++) { ua[j] = f2tf32(ra[j]); ub[j] = f2tf32(rb[j]); }
        *(uint4*)&As[0][rr][kc]     = make_uint4(ua[0], ua[1], ua[2], ua[3]);
        *(uint4*)&As[0][rr][kc + 4] = make_uint4(ua[4], ua[5], ua[6], ua[7]);
        *(uint4*)&Bs[0][rr][kc]     = make_uint4(ub[0], ub[1], ub[2], ub[3]);
        *(uint4*)&Bs[0][rr][kc + 4] = make_uint4(ub[4], ub[5], ub[6], ub[7]);
    }
    __syncthreads();

    float acc[4][4][4];
#pragma unroll
    for (int i = 0; i < 4; i++)
#pragma unroll
        for (int j = 0; j < 4; j++)
#pragma unroll
            for (int q = 0; q < 4; q++) acc[i][j][q] = 0.0f;

    int buf = 0;
    int lr = lane >> 2, lc = lane & 3;

    for (int k0 = 0; k0 < 128; k0 += 16) {
        int kn = k0 + 16;
        bool more = kn < 128;
        if (more) {
            ld8(aPtr + kn, avalid, ra);
            ld8(bPtr + kn, bvalid, rb);
        }
#pragma unroll
        for (int ks = 0; ks < 16; ks += 8) {
            uint32_t bf[4][2];
#pragma unroll
            for (int nt = 0; nt < 4; nt++) {
                int nn = nW + nt * 8 + lr;
                bf[nt][0] = Bs[buf][nn][ks + lc];
                bf[nt][1] = Bs[buf][nn][ks + lc + 4];
            }
#pragma unroll
            for (int mt = 0; mt < 4; mt++) {
                int r = mW + mt * 16 + lr;
                uint32_t a0 = As[buf][r][ks + lc];
                uint32_t a1 = As[buf][r + 8][ks + lc];
                uint32_t a2 = As[buf][r][ks + lc + 4];
                uint32_t a3 = As[buf][r + 8][ks + lc + 4];
#pragma unroll
                for (int nt = 0; nt < 4; nt++)
                    mma_tf32(acc[mt][nt], a0, a1, a2, a3, bf[nt][0], bf[nt][1]);
            }
        }
        if (more) {
            int nb = buf ^ 1;
            uint32_t ua[8], ub[8];
#pragma unroll
            for (int j = 0; j < 8; j++) { ua[j] = f2tf32(ra[j]); ub[j] = f2tf32(rb[j]); }
            *(uint4*)&As[nb][rr][kc]     = make_uint4(ua[0], ua[1], ua[2], ua[3]);
            *(uint4*)&As[nb][rr][kc + 4] = make_uint4(ua[4], ua[5], ua[6], ua[7]);
            *(uint4*)&Bs[nb][rr][kc]     = make_uint4(ub[0], ub[1], ub[2], ub[3]);
            *(uint4*)&Bs[nb][rr][kc + 4] = make_uint4(ub[4], ub[5], ub[6], ub[7]);
            __syncthreads();
            buf = nb;
        }
    }

    bool interior = (nBase + 128) <= NVALID;
#pragma unroll
    for (int mt = 0; mt < 4; mt++) {
        int r1 = mBase + mW + mt * 16 + lr;
        int r2 = r1 + 8;
#pragma unroll
        for (int nt = 0; nt < 4; nt++) {
            int cb = nBase + nW + nt * 8 + lc * 2;
            if (interior) {
                if (r1 < M) {
                    size_t off = (size_t)g * sC + (size_t)r1 * ldC + cb;
                    *(float2*)(C + off) = make_float2(__expf(30.0f * acc[mt][nt][0]),
                                                      __expf(30.0f * acc[mt][nt][1]));
                }
                if (r2 < M) {
                    size_t off = (size_t)g * sC + (size_t)r2 * ldC + cb;
                    *(float2*)(C + off) = make_float2(__expf(30.0f * acc[mt][nt][2]),
                                                      __expf(30.0f * acc[mt][nt][3]));
                }
            } else {
#pragma unroll
                for (int e = 0; e < 2; e++) {
                    int n = cb + e;
                    if (n >= ldC) continue;
                    if (r1 < M)
                        C[(size_t)g * sC + (size_t)r1 * ldC + n] =
                            (n < NVALID) ? __expf(30.0f * acc[mt][nt][e]) : 0.0f;
                    if (r2 < M)
                        C[(size_t)g * sC + (size_t)r2 * ldC + n] =
                            (n < NVALID) ? __expf(30.0f * acc[mt][nt][2 + e]) : 0.0f;
                }
            }
        }
    }
}

// ============ tf32 value GEMM with fused rowsum (and mask) ============
// C[g][m] = (1/Σ_k P[g][m][k]) * (P[g] @ Vs[gk])[m] + Cin[g][m]
// If LAB != null: V rows scaled by LAB[gk][k] during staging, and
// MASKOUT[g][m] = Σ P·LAB / Σ P is written by blockIdx.x==0.
__global__ void __launch_bounds__(256, 2)
tf32_value_kernel(const float* __restrict__ P, const float* __restrict__ V,
                  const float* __restrict__ Cin, float* __restrict__ C,
                  const float* __restrict__ LAB, float* __restrict__ MASKOUT,
                  int M, int Kpad, int KB, int ldA,
                  size_t sA, size_t sB, size_t sC, int gkMod) {
    __shared__ __align__(16) uint32_t As[2][128][20];
    __shared__ __align__(16) uint32_t Bs[2][16][136];
    __shared__ float rs_s[128][2];
    __shared__ float rm_s[128][2];
    int g = blockIdx.z;
    int gk = gkMod ? (g & 15) : g;
    const float* Pg = P + (size_t)g * sA;
    const float* Vg = V + (size_t)gk * sB;
    const float* labRow = LAB ? (LAB + (size_t)gk * KB) : nullptr;
    int mBase = blockIdx.y * 128, nBase = blockIdx.x * 128;
    int t = threadIdx.x, lane = t & 31, warp = t >> 5;
    int mW = (warp >> 2) * 64, nW = (warp & 3) * 32;

    int am = t >> 1, ak = (t & 1) * 8;
    bool avalid = (mBase + am) < M;
    const float* aPtr = Pg + (size_t)(mBase + am) * ldA + ak;
    int bk2 = t >> 4, bnq = (t & 15) * 8;
    const float* bPtr = Vg + (size_t)bk2 * 512 + nBase + bnq;

    float psum = 0.0f, pmask = 0.0f;
    float ra[8], rb[8];
    ld8(aPtr, avalid, ra);
#pragma unroll
    for (int j = 0; j < 8; j++) psum += ra[j];
    if (labRow) {
#pragma unroll
        for (int j = 0; j < 8; j++) {
            int k = ak + j;
            if (k < KB) pmask += ra[j] * labRow[k];
        }
    }
    {
        bool bv = bk2 < KB;
        ld8(bPtr, bv, rb);
        if (labRow && bv) {
            float lb = labRow[bk2];
#pragma unroll
            for (int j = 0; j < 8; j++) rb[j] *= lb;
        }
    }
    {
        uint32_t ua[8], ub[8];
#pragma unroll
        for (int j = 0; j < 8; j++) { ua[j] = f2tf32(ra[j]); ub[j] = f2tf32(rb[j]); }
        *(uint4*)&As[0][am][ak]     = make_uint4(ua[0], ua[1], ua[2], ua[3]);
        *(uint4*)&As[0][am][ak + 4] = make_uint4(ua[4], ua[5], ua[6], ua[7]);
        *(uint4*)&Bs[0][bk2][bnq]     = make_uint4(ub[0], ub[1], ub[2], ub[3]);
        *(uint4*)&Bs[0][bk2][bnq + 4] = make_uint4(ub[4], ub[5], ub[6], ub[7]);
    }
    __syncthreads();

    float acc[4][4][4];
#pragma unroll
    for (int i = 0; i < 4; i++)
#pragma unroll
        for (int j = 0; j < 4; j++)
#pragma unroll
            for (int q = 0; q < 4; q++) acc[i][j][q] = 0.0f;

    int buf = 0;
    int lr = lane >> 2, lc = lane & 3;

    for (int k0 = 0; k0 < Kpad; k0 += 16) {
        int kn = k0 + 16;
        bool more = kn < Kpad;
        if (more) {
            ld8(aPtr + kn, avalid, ra);
#pragma unroll
            for (int j = 0; j < 8; j++) psum += ra[j];
            if (labRow) {
#pragma unroll
                for (int j = 0; j < 8; j++) {
                    int k = kn + ak + j;
                    if (k < KB) pmask += ra[j] * labRow[k];
                }
            }
            bool bv = (kn + bk2) < KB;
            ld8(bPtr + (size_t)kn * 512, bv, rb);
            if (labRow && bv) {
                float lb = labRow[kn + bk2];
#pragma unroll
                for (int j = 0; j < 8; j++) rb[j] *= lb;
            }
        }
#pragma unroll
        for (int ks = 0; ks < 16; ks += 8) {
            uint32_t bf[4][2];
#pragma unroll
            for (int nt = 0; nt < 4; nt++) {
                int cc = nW + nt * 8 + lr;
                bf[nt][0] = Bs[buf][ks + lc][cc];
                bf[nt][1] = Bs[buf][ks + lc + 4][cc];
            }
#pragma unroll
            for (int mt = 0; mt < 4; mt++) {
                int r = mW + mt * 16 + lr;
                uint32_t a0 = As[buf][r][ks + lc];
                uint32_t a1 = As[buf][r + 8][ks + lc];
                uint32_t a2 = As[buf][r][ks + lc + 4];
                uint32_t a3 = As[buf][r + 8][ks + lc + 4];
#pragma unroll
                for (int nt = 0; nt < 4; nt++)
                    mma_tf32(acc[mt][nt], a0, a1, a2, a3, bf[nt][0], bf[nt][1]);
            }
        }
        if (more) {
            int nb = buf ^ 1;
            uint32_t ua[8], ub[8];
#pragma unroll
            for (int j = 0; j < 8; j++) { ua[j] = f2tf32(ra[j]); ub[j] = f2tf32(rb[j]); }
            *(uint4*)&As[nb][am][ak]     = make_uint4(ua[0], ua[1], ua[2], ua[3]);
            *(uint4*)&As[nb][am][ak + 4] = make_uint4(ua[4], ua[5], ua[6], ua[7]);
            *(uint4*)&Bs[nb][bk2][bnq]     = make_uint4(ub[0], ub[1], ub[2], ub[3]);
            *(uint4*)&Bs[nb][bk2][bnq + 4] = make_uint4(ub[4], ub[5], ub[6], ub[7]);
            __syncthreads();
            buf = nb;
        }
    }

    // combine row-sum partials
    rs_s[am][t & 1] = psum;
    rm_s[am][t & 1] = pmask;
    __syncthreads();

    if (labRow && MASKOUT && blockIdx.x == 0 && t < 128) {
        int row = mBase + t;
        if (row < M) {
            float s = rs_s[t][0] + rs_s[t][1];
            MASKOUT[(size_t)g * M + row] = (rm_s[t][0] + rm_s[t][1]) / s;
        }
    }

    // epilogue: (1/rowsum) * acc + Cin
#pragma unroll
    for (int mt = 0; mt < 4; mt++) {
        int l1 = mW + mt * 16 + lr, l2 = l1 + 8;
        int r1 = mBase + l1, r2 = mBase + l2;
        float rs1 = (r1 < M) ? 1.0f / (rs_s[l1][0] + rs_s[l1][1]) : 0.0f;
        float rs2 = (r2 < M) ? 1.0f / (rs_s[l2][0] + rs_s[l2][1]) : 0.0f;
#pragma unroll
        for (int nt = 0; nt < 4; nt++) {
            int cb = nBase + nW + nt * 8 + lc * 2;
            if (r1 < M) {
                size_t off = (size_t)g * sC + (size_t)r1 * 512 + cb;
                float2 ci = *(const float2*)(Cin + off);
                *(float2*)(C + off) = make_float2(rs1 * acc[mt][nt][0] + ci.x,
                                                  rs1 * acc[mt][nt][1] + ci.y);
            }
            if (r2 < M) {
                size_t off = (size_t)g * sC + (size_t)r2 * 512 + cb;
                float2 ci = *(const float2*)(Cin + off);
                *(float2*)(C + off) = make_float2(rs2 * acc[mt][nt][2] + ci.x,
                                                  rs2 * acc[mt][nt][3] + ci.y);
            }
        }
    }
}

// ================= small kernels =================
__global__ void pe_kernel(float* __restrict__ pe) {
    int idx = blockIdx.x * 256 + threadIdx.x;
    if (idx >= HW * DD) return;
    int p = idx >> 9, c = idx & 511;
    float pos = (float)(p + 1);
    int j = c & 255;
    float f = powf(10000.0f, -(float)j * (1.0f / 256.0f));
    float a = pos * f;
    pe[idx] = (c < 256) ? sinf(a) : cosf(a);
}

__global__ void label_kernel(const float* __restrict__ lab, float* __restrict__ out) {
    int idx = blockIdx.x * 256 + threadIdx.x;
    if (idx >= 3 * BB * HW) return;
    int p = idx % HW;
    int t = idx / HW;
    int b = t % BB;
    int ni = t / BB;
    out[(size_t)b * LE + ni * HW + p] = lab[idx];
}

__global__ void build_kernel(const float* __restrict__ fa, const float* __restrict__ fb,
                             int split, const float* __restrict__ pe,
                             float* __restrict__ xout, int mode) {
    int g = blockIdx.x;
    int img = g >> 4, b = g & 15;
    const float* f = (img < split) ? (fa + (size_t)img * BB * DD * HW)
                                   : (fb + (size_t)(img - split) * BB * DD * HW);
    int p0 = blockIdx.y * 32, c0 = blockIdx.z * 32;
    __shared__ float tl[32][33];
    int tx = threadIdx.x, ty = threadIdx.y;
#pragma unroll
    for (int r = 0; r < 4; r++) {
        int c = c0 + ty + r * 8, p = p0 + tx;
        if (p < HW) tl[ty + r * 8][tx] = f[((size_t)b * DD + c) * HW + p];
    }
    __syncthreads();
#pragma unroll
    for (int r = 0; r < 4; r++) {
        int p = p0 + ty + r * 8, c = c0 + tx;
        if (p < HW) {
            size_t row = (mode == 0) ? ((size_t)b * LE + (size_t)img * HW + p)
                                     : ((size_t)g * LDQ + p);
            xout[row * DD + c] = tl[tx][ty + r * 8] + pe[(size_t)p * DD + c] * 1e-3f;
        }
    }
}

// InstanceL2Norm: partial sums then apply (deterministic 2-stage)
__global__ void inorm_part(const float* __restrict__ in, float* __restrict__ part) {
    int g = blockIdx.x, q = blockIdx.y, t = threadIdx.x;
    const float4* ip = (const float4*)(in + (size_t)g * GRP) + (size_t)q * QF4;
    float ss = 0.0f;
    for (int i = t; i < QF4; i += 256) {
        float4 v = ip[i];
        ss += v.x * v.x + v.y * v.y + v.z * v.z + v.w * v.w;
    }
    __shared__ float red[8];
#pragma unroll
    for (int m = 16; m; m >>= 1) ss += __shfl_xor_sync(0xffffffffu, ss, m);
    if ((t & 31) == 0) red[t >> 5] = ss;
    __syncthreads();
    if (t == 0) {
        float s = 0.0f;
#pragma unroll
        for (int i = 0; i < 8; i++) s += red[i];
        part[g * 4 + q] = s;
    }
}

__global__ void inorm_apply(const float* __restrict__ in, float* __restrict__ out,
                            const float* __restrict__ part) {
    int g = blockIdx.x, q = blockIdx.y, t = threadIdx.x;
    float ss = part[g * 4 + 0] + part[g * 4 + 1] + part[g * 4 + 2] + part[g * 4 + 3];
    float sc = NSCALE * sqrtf(DHWF / (ss + IEPS));
    const float4* ip = (const float4*)(in + (size_t)g * GRP) + (size_t)q * QF4;
    float4* op = (float4*)(out + (size_t)g * GRP) + (size_t)q * QF4;
    for (int i = t; i < QF4; i += 256) {
        float4 v = ip[i];
        v.x *= sc; v.y *= sc; v.z *= sc; v.w *= sc;
        op[i] = v;
    }
}

// decoder 3-sum partials: u = x*mask, v = x + t3
__global__ void dec_part_kernel(const float* __restrict__ X, const float* __restrict__ XP,
                                const float* __restrict__ MASK, float* __restrict__ part) {
    int g = blockIdx.x, q = blockIdx.y, t = threadIdx.x;
    const float4* x4 = (const float4*)(X + (size_t)g * GRP);
    const float4* p4 = (const float4*)(XP + (size_t)g * GRP);
    const float* mk = MASK + (size_t)g * LDQ;
    float s2 = 0.0f, s4 = 0.0f, cr = 0.0f;
    for (int i = t; i < QF4; i += 256) {
        int gi = q * QF4 + i;
        float m = mk[gi >> 7];
        float4 x = x4[gi];
        float4 v = p4[gi];
        float ux = x.x * m, uy = x.y * m, uz = x.z * m, uw = x.w * m;
        s2 += ux * ux + uy * uy + uz * uz + uw * uw;
        s4 += v.x * v.x + v.y * v.y + v.z * v.z + v.w * v.w;
        cr += ux * v.x + uy * v.y + uz * v.z + uw * v.w;
    }
    __shared__ float r2[8], r4[8], rc[8];
#pragma unroll
    for (int m = 16; m; m >>= 1) {
        s2 += __shfl_xor_sync(0xffffffffu, s2, m);
        s4 += __shfl_xor_sync(0xffffffffu, s4, m);
        cr += __shfl_xor_sync(0xffffffffu, cr, m);
    }
    if ((t & 31) == 0) { r2[t >> 5] = s2; r4[t >> 5] = s4; rc[t >> 5] = cr; }
    __syncthreads();
    if (t == 0) {
        float a = 0, b = 0, c = 0;
#pragma unroll
        for (int i = 0; i < 8; i++) { a += r2[i]; b += r4[i]; c += rc[i]; }
        part[(g * 4 + q) * 3 + 0] = a;
        part[(g * 4 + q) * 3 + 1] = b;
        part[(g * 4 + q) * 3 + 2] = c;
    }
}

__global__ void dec_scale_kernel(const float* __restrict__ part, float* __restrict__ SC) {
    int g = threadIdx.x;
    if (g >= 96) return;
    float a = 0, b = 0, c = 0;
#pragma unroll
    for (int q = 0; q < 4; q++) {
        a += part[(g * 4 + q) * 3 + 0];
        b += part[(g * 4 + q) * 3 + 1];
        c += part[(g * 4 + q) * 3 + 2];
    }
    float S2 = NSCALE * sqrtf(DHWF / (a + IEPS));
    float S4 = NSCALE * sqrtf(DHWF / (b + IEPS));
    float sso = S2 * S2 * a + 2.0f * S2 * S4 * c + S4 * S4 * b;
    float SO = NSCALE * sqrtf(DHWF / (sso + IEPS));
    SC[g * 4 + 0] = S2;
    SC[g * 4 + 1] = S4;
    SC[g * 4 + 2] = SO;
}

__global__ void final_kernel(const float* __restrict__ X, const float* __restrict__ XP,
                             const float* __restrict__ MASK, const float* __restrict__ SC,
                             float* __restrict__ out) {
    int g = blockIdx.x;
    float S2 = SC[g * 4 + 0], S4 = SC[g * 4 + 1], SO = SC[g * 4 + 2];
    int p0 = blockIdx.y * 32, c0 = blockIdx.z * 32;
    __shared__ float tile[32][33];
    int tx = threadIdx.x, ty = threadIdx.y;
    size_t base = (size_t)g * GRP;
#pragma unroll
    for (int r = 0; r < 4; r++) {
        int p = p0 + ty + r * 8, c = c0 + tx;
        if (p < LDQ) {
            size_t idx = base + (size_t)p * 512 + c;
            float u = X[idx] * MASK[(size_t)g * LDQ + p];
            tile[ty + r * 8][tx] = SO * (S2 * u + S4 * XP[idx]);
        }
    }
    __syncthreads();
#pragma unroll
    for (int r = 0; r < 4; r++) {
        int p = p0 + tx, c = c0 + ty + r * 8;
        if (p < LDQ) out[((size_t)g * 512 + c) * LDQ + p] = tile[tx][ty + r * 8];
    }
}

// ================= launcher =================
extern "C" void kernel_launch(void* const* d_in, const int* in_sizes, int n_in,
                              void* d_out, int out_size) {
    const float* train_feat  = (const float*)d_in[0];
    const float* test_feat   = (const float*)d_in[1];
    const float* train_label = (const float*)d_in[2];
    const float* wk_self     = (const float*)d_in[3];
    const float* bk_self     = (const float*)d_in[4];
    const float* wk_cross    = (const float*)d_in[5];
    const float* bk_cross    = (const float*)d_in[6];
    float* out = (float*)d_out;

    float* base = nullptr;
    cudaGetSymbolAddress((void**)&base, g_scratch);
    float* pe     = base + OFF_PE;
    float* label  = base + OFF_LABEL;
    float* xe     = base + OFF_XE;
    float* dx0    = base + OFF_DX0;
    float* pq     = base + OFF_PQ;
    float* dpq    = base + OFF_DPQ;
    float* mem    = base + OFF_MEM;
    float* dx     = base + OFF_DX;
    float* pkc    = base + OFF_PKC;
    float* dpq2   = base + OFF_DPQ2;
    float* x1e    = base + OFF_X1E;
    float* dx1    = base + OFF_DX1;
    float* dxpt3  = base + OFF_DXPT3;
    float* dmask  = base + OFF_DMASK;
    float* dsc    = base + OFF_DSC;
    float* ipart  = base + OFF_IPART;
    float* dpart  = base + OFF_DPART;
    float* probs  = base + OFF_PROBS;

    dim3 tb(32, 8);
    const int MALL = 16 * LE + 96 * LDQ;   // 69696

    pe_kernel<<<(HW * DD + 255) / 256, 256>>>(pe);
    label_kernel<<<(3 * BB * HW + 255) / 256, 256>>>(train_label, label);

    // build both token buffers
    build_kernel<<<dim3(48, 16, 16), tb>>>(train_feat, train_feat, 3, pe, xe, 0);
    build_kernel<<<dim3(96, 16, 16), tb>>>(train_feat, test_feat, 3, pe, dx0, 1);

    // merged self projection [xe|dx0] -> [pq|dpq]
    tf32_proj_kernel<<<dim3(1, (MALL + 127) / 128, 1), 256>>>(xe, wk_self, pq, bk_self, MALL);

    // encoder
    tf32_logits_kernel<<<dim3(12, 12, 16), 256>>>(
        pq, pq, probs, LE, LE, 1456, LE,
        (size_t)LE * 128, (size_t)LE * 128, (size_t)LE * 1456, 0);
    tf32_value_kernel<<<dim3(4, 12, 16), 256>>>(
        probs, xe, xe, x1e, nullptr, nullptr, LE, 1456, LE, 1456,
        (size_t)LE * 1456, (size_t)LE * 512, (size_t)LE * 512, 0);
    inorm_part<<<dim3(48, 4), 256>>>(x1e, ipart);
    inorm_apply<<<dim3(48, 4), 256>>>(x1e, mem, ipart);

    // decoder self
    tf32_logits_kernel<<<dim3(4, 4, 96), 256>>>(
        dpq, dpq, probs, LDQ, LDQ, 496, LDQ,
        (size_t)LDQ * 128, (size_t)LDQ * 128, (size_t)LDQ * 496, 0);
    tf32_value_kernel<<<dim3(4, 4, 96), 256>>>(
        probs, dx0, dx0, dx1, nullptr, nullptr, LDQ, 496, LDQ, 496,
        (size_t)LDQ * 496, (size_t)LDQ * 512, (size_t)LDQ * 512, 0);
    inorm_part<<<dim3(96, 4), 256>>>(dx1, ipart);
    inorm_apply<<<dim3(96, 4), 256>>>(dx1, dx, ipart);

    // merged cross projection [mem|dx] -> [pkc|dpq2]
    tf32_proj_kernel<<<dim3(1, (MALL + 127) / 128, 1), 256>>>(mem, wk_cross, pkc, bk_cross, MALL);

    // cross attention (fused mask + label-weighted memory)
    tf32_logits_kernel<<<dim3(12, 4, 96), 256>>>(
        dpq2, pkc, probs, LDQ, LE, 1456, LE,
        (size_t)LDQ * 128, (size_t)LE * 128, (size_t)LDQ * 1456, 1);
    tf32_value_kernel<<<dim3(4, 4, 96), 256>>>(
        probs, mem, dx, dxpt3, label, dmask, LDQ, 1456, LE, 1456,
        (size_t)LDQ * 1456, (size_t)LE * 512, (size_t)LDQ * 512, 1);

    dec_part_kernel<<<dim3(96, 4), 256>>>(dx, dxpt3, dmask, dpart);
    dec_scale_kernel<<<1, 96>>>(dpart, dsc);
    final_kernel<<<dim3(96, 16, 16), tb>>>(dx, dxpt3, dmask, dsc, out);
}